// round 6
// baseline (speedup 1.0000x reference)
#include <cuda_runtime.h>
#include <cuda_bf16.h>
#include <cstdint>

// ---------------------------------------------------------------------------
// TUPE multihead attention.
//  Projections / out-proj: bf16 split-precision 3-term HMMA (as round 5).
//  Flash attention middle: S = QK^T in INT8 2-digit (per-row scales, s32 accum,
//  2x tensor rate), softmax fp32, PV in bf16 3-term (P needs relative precision).
// ---------------------------------------------------------------------------

static constexpr int BB  = 4;
static constexpr int HH  = 8;
static constexpr int SQ  = 2048;
static constexpr int EMB = 512;
static constexpr int HD  = 64;
static constexpr float QK_SCALE = 0.0883883476483184f; // 1/sqrt(2*64)

// ------------------------------ scratch ------------------------------------
__device__ __align__(16) unsigned g_x2  [(size_t)BB * SQ * EMB];
__device__ __align__(16) unsigned g_PE2 [(size_t)BB * SQ * EMB];
__device__ __align__(16) unsigned g_W2  [(size_t)3 * EMB * EMB];
__device__ __align__(16) unsigned g_U2  [(size_t)2 * EMB * EMB];
__device__ __align__(16) unsigned g_Wo2 [(size_t)EMB * EMB];
__device__ __align__(16) float    g_Qcat[(size_t)BB * HH * SQ * 128];   // f32 (scaled q)
__device__ __align__(16) float    g_Kcat[(size_t)BB * HH * SQ * 128];   // f32
__device__ __align__(16) unsigned char g_Qh[(size_t)BB * HH * SQ * 128];
__device__ __align__(16) unsigned char g_Ql[(size_t)BB * HH * SQ * 128];
__device__ __align__(16) unsigned char g_Kh[(size_t)BB * HH * SQ * 128];
__device__ __align__(16) unsigned char g_Kl[(size_t)BB * HH * SQ * 128];
__device__ float g_sq[(size_t)BB * HH * SQ];
__device__ float g_sk[(size_t)BB * HH * SQ];
__device__ __align__(16) unsigned g_Vt  [(size_t)BB * HH * HD * SQ];    // packed bf16 pair
__device__ __align__(16) unsigned g_vals[(size_t)BB * SQ * EMB];        // packed bf16 pair

// ------------------------------ helpers ------------------------------------
__device__ __forceinline__ unsigned smem_u32(const void* p) {
    unsigned a;
    asm("{ .reg .u64 t; cvta.to.shared.u64 t, %1; cvt.u32.u64 %0, t; }" : "=r"(a) : "l"(p));
    return a;
}
__device__ __forceinline__ unsigned packf(float v) {
    __nv_bfloat16 hi = __float2bfloat16(v);
    float r = v - __bfloat162float(hi);
    __nv_bfloat16 lo = __float2bfloat16(r);
    return ((unsigned)__bfloat16_as_ushort(hi) << 16) | (unsigned)__bfloat16_as_ushort(lo);
}
__device__ __forceinline__ uint4 pack4(float4 v, float sc) {
    return make_uint4(packf(v.x * sc), packf(v.y * sc), packf(v.z * sc), packf(v.w * sc));
}
__device__ __forceinline__ void split2(float a, float b, unsigned& h, unsigned& lo) {
    __nv_bfloat16 ah = __float2bfloat16(a), bh = __float2bfloat16(b);
    float ar = a - __bfloat162float(ah), br = b - __bfloat162float(bh);
    __nv_bfloat16 al = __float2bfloat16(ar), bl = __float2bfloat16(br);
    h  = ((unsigned)__bfloat16_as_ushort(bh) << 16) | (unsigned)__bfloat16_as_ushort(ah);
    lo = ((unsigned)__bfloat16_as_ushort(bl) << 16) | (unsigned)__bfloat16_as_ushort(al);
}

__global__ void __launch_bounds__(256)
pack_kernel(const float4* __restrict__ in, uint4* __restrict__ out, int n4)
{
    int i = blockIdx.x * 256 + threadIdx.x;
    if (i < n4) out[i] = pack4(in[i], 1.0f);
}

#define LDSM4(r0, r1, r2, r3, a)                                              \
    asm volatile("ldmatrix.sync.aligned.m8n8.x4.shared.b16 {%0,%1,%2,%3}, [%4];" \
                 : "=r"(r0), "=r"(r1), "=r"(r2), "=r"(r3) : "r"(a))

#define MMA16816(c, a, b0, b1)                                                \
    asm volatile("mma.sync.aligned.m16n8k16.row.col.f32.bf16.bf16.f32 "       \
                 "{%0,%1,%2,%3}, {%4,%5,%6,%7}, {%8,%9}, {%0,%1,%2,%3};"      \
                 : "+f"((c)[0]), "+f"((c)[1]), "+f"((c)[2]), "+f"((c)[3])     \
                 : "r"((a)[0]), "r"((a)[1]), "r"((a)[2]), "r"((a)[3]),        \
                   "r"(b0), "r"(b1))

#define MMAS8(c, a, b0, b1)                                                   \
    asm volatile("mma.sync.aligned.m16n8k32.row.col.s32.s8.s8.s32 "           \
                 "{%0,%1,%2,%3}, {%4,%5,%6,%7}, {%8,%9}, {%0,%1,%2,%3};"      \
                 : "+r"((c)[0]), "+r"((c)[1]), "+r"((c)[2]), "+r"((c)[3])     \
                 : "r"((a)[0]), "r"((a)[1]), "r"((a)[2]), "r"((a)[3]),        \
                   "r"(b0), "r"(b1))

#define CP_ASYNC16(dst, src) \
    asm volatile("cp.async.cg.shared.global [%0], [%1], 16;" :: "r"(dst), "l"(src))
#define CP_COMMIT() asm volatile("cp.async.commit_group;" ::: "memory")
#define CP_WAIT1()  asm volatile("cp.async.wait_group 1;" ::: "memory")

__device__ __forceinline__ unsigned sw64(unsigned off)  { return off ^ ((off >> 3) & 0x30); }
__device__ __forceinline__ unsigned sw128(unsigned off) { return off ^ ((off >> 3) & 0x70); }

// ------------------------------ GEMM (projections / out) -------------------
template <typename Epi>
__global__ void __launch_bounds__(256, 2)
gemm_hmma(const unsigned* __restrict__ A, const unsigned* __restrict__ B,
          int K, int lda, int ldb, long sA, long sB, Epi epi)
{
    extern __shared__ __align__(1024) char smem[];
    constexpr int SA_LO = 8192, SB_HI = 16384, SB_LO = 20480, STAGE = 24576;

    const int tid = threadIdx.x;
    const int l   = tid & 31;
    const int w   = tid >> 5;
    const int wm  = w & 3;
    const int wn  = w >> 2;
    const int m0  = wm * 32;
    const int n0  = wn * 32;
    const int bz  = blockIdx.z;
    const unsigned sbase = smem_u32(smem);

    const unsigned* Ab = A + bz * sA + (long)blockIdx.y * 128 * lda;
    const unsigned* Bb = B + bz * sB + (long)blockIdx.x * 64 * ldb;

    float acc[2][4][4];
#pragma unroll
    for (int i = 0; i < 2; i++)
#pragma unroll
        for (int j = 0; j < 4; j++)
#pragma unroll
            for (int k = 0; k < 4; k++) acc[i][j][k] = 0.0f;

    const int arow = (l & 7) + ((l >> 3) & 1) * 8;
    const int akp  = ((l >> 4) & 1) * 16;
    const int brow = (l & 7) + ((l >> 4) & 1) * 8;
    const int bkp  = ((l >> 3) & 1) * 16;

    uint4 ra[4], rb[2];
    const int nChunks = K >> 5;

    auto load_global = [&](int c) {
#pragma unroll
        for (int it = 0; it < 4; it++) {
            int idx = tid + it * 256;
            int r = idx >> 3, q = idx & 7;
            ra[it] = *reinterpret_cast<const uint4*>(Ab + (long)r * lda + c * 32 + q * 4);
        }
#pragma unroll
        for (int it = 0; it < 2; it++) {
            int idx = tid + it * 256;
            int r = idx >> 3, q = idx & 7;
            rb[it] = *reinterpret_cast<const uint4*>(Bb + (long)r * ldb + c * 32 + q * 4);
        }
    };
    auto store_stage = [&](char* buf) {
#pragma unroll
        for (int it = 0; it < 4; it++) {
            int idx = tid + it * 256;
            int r = idx >> 3, q = idx & 7;
            unsigned sw = sw64(r * 64 + q * 8);
            uint4 wv = ra[it];
            *reinterpret_cast<uint2*>(buf + sw) =
                make_uint2(__byte_perm(wv.x, wv.y, 0x7632), __byte_perm(wv.z, wv.w, 0x7632));
            *reinterpret_cast<uint2*>(buf + SA_LO + sw) =
                make_uint2(__byte_perm(wv.x, wv.y, 0x5410), __byte_perm(wv.z, wv.w, 0x5410));
        }
#pragma unroll
        for (int it = 0; it < 2; it++) {
            int idx = tid + it * 256;
            int r = idx >> 3, q = idx & 7;
            unsigned sw = sw64(r * 64 + q * 8);
            uint4 wv = rb[it];
            *reinterpret_cast<uint2*>(buf + SB_HI + sw) =
                make_uint2(__byte_perm(wv.x, wv.y, 0x7632), __byte_perm(wv.z, wv.w, 0x7632));
            *reinterpret_cast<uint2*>(buf + SB_LO + sw) =
                make_uint2(__byte_perm(wv.x, wv.y, 0x5410), __byte_perm(wv.z, wv.w, 0x5410));
        }
    };

    load_global(0);
    store_stage(smem);
    __syncthreads();

    for (int c = 0; c < nChunks; c++) {
        const bool more = (c + 1) < nChunks;
        if (more) load_global(c + 1);

        const unsigned stage = sbase + (c & 1) * STAGE;
#pragma unroll
        for (int ks = 0; ks < 2; ks++) {
            unsigned aH[2][4], aL[2][4], bH[2][4], bL[2][4];
#pragma unroll
            for (int i = 0; i < 2; i++) {
                unsigned off = (m0 + i * 16 + arow) * 64 + ks * 32 + akp;
                unsigned sw = sw64(off);
                LDSM4(aH[i][0], aH[i][1], aH[i][2], aH[i][3], stage + sw);
                LDSM4(aL[i][0], aL[i][1], aL[i][2], aL[i][3], stage + SA_LO + sw);
            }
#pragma unroll
            for (int p = 0; p < 2; p++) {
                unsigned off = (n0 + p * 16 + brow) * 64 + ks * 32 + bkp;
                unsigned sw = sw64(off);
                LDSM4(bH[p][0], bH[p][1], bH[p][2], bH[p][3], stage + SB_HI + sw);
                LDSM4(bL[p][0], bL[p][1], bL[p][2], bL[p][3], stage + SB_LO + sw);
            }
#pragma unroll
            for (int i = 0; i < 2; i++)
#pragma unroll
                for (int j = 0; j < 4; j++) {
                    const int p = j >> 1, h = (j & 1) * 2;
                    MMA16816(acc[i][j], aH[i], bH[p][h], bH[p][h + 1]);
                    MMA16816(acc[i][j], aH[i], bL[p][h], bL[p][h + 1]);
                    MMA16816(acc[i][j], aL[i], bH[p][h], bH[p][h + 1]);
                }
        }

        if (more) store_stage(smem + ((c + 1) & 1) * STAGE);
        __syncthreads();
    }

    float* C = reinterpret_cast<float*>(smem);   // [128][68]
#pragma unroll
    for (int i = 0; i < 2; i++)
#pragma unroll
        for (int j = 0; j < 4; j++) {
            int r0  = m0 + i * 16 + (l >> 2);
            int col = n0 + j * 8 + (l & 3) * 2;
            *reinterpret_cast<float2*>(C + r0 * 68 + col)       = make_float2(acc[i][j][0], acc[i][j][1]);
            *reinterpret_cast<float2*>(C + (r0 + 8) * 68 + col) = make_float2(acc[i][j][2], acc[i][j][3]);
        }
    __syncthreads();

    {
        int r = tid >> 1, seg = (tid & 1) << 5;
        int m  = blockIdx.y * 128 + r;
        int nb = blockIdx.x * 64 + seg;
        const float* Crow = C + r * 68 + seg;
#pragma unroll
        for (int i = 0; i < 8; i++) {
            float4 v = *reinterpret_cast<const float4*>(Crow + i * 4);
            epi(bz, m, nb + i * 4, v);
        }
    }
}

struct EpiQKV {   // m in [0,8192), n in [0,1536)
    __device__ void operator()(int, int m, int n, float4 v) const {
        int b = m >> 11, s = m & (SQ - 1);
        int h = n / 192, r = n - h * 192;
        long row = ((long)(b * HH + h) * SQ + s);
        if (r < HD) {
            *reinterpret_cast<float4*>(&g_Qcat[row * 128 + r]) =
                make_float4(v.x * QK_SCALE, v.y * QK_SCALE, v.z * QK_SCALE, v.w * QK_SCALE);
        } else if (r < 2 * HD) {
            *reinterpret_cast<float4*>(&g_Kcat[row * 128 + (r - HD)]) = v;
        } else {
            int d = r - 2 * HD;
            long base = ((long)(b * HH + h) * HD + d) * SQ + s;
            g_Vt[base]          = packf(v.x);
            g_Vt[base + SQ]     = packf(v.y);
            g_Vt[base + 2 * SQ] = packf(v.z);
            g_Vt[base + 3 * SQ] = packf(v.w);
        }
    }
};
struct EpiPE {    // n in [0,1024)
    __device__ void operator()(int, int m, int n, float4 v) const {
        int b = m >> 11, s = m & (SQ - 1);
        int h = n >> 7, r = n & 127;
        long row = ((long)(b * HH + h) * SQ + s);
        if (r < HD)
            *reinterpret_cast<float4*>(&g_Qcat[row * 128 + HD + r]) =
                make_float4(v.x * QK_SCALE, v.y * QK_SCALE, v.z * QK_SCALE, v.w * QK_SCALE);
        else
            *reinterpret_cast<float4*>(&g_Kcat[row * 128 + HD + (r - HD)]) = v;
    }
};
struct EpiOut {
    float* out;
    __device__ void operator()(int, int m, int n, float4 v) const {
        *reinterpret_cast<float4*>(&out[(long)m * EMB + n]) = v;
    }
};

// ------------------------------ row quantization ---------------------------
// One warp per 128-float row: x = s/127 * (h + l/127), s = rowmax.
__global__ void __launch_bounds__(256)
quant_rows(const float* __restrict__ src, unsigned char* __restrict__ h8,
           unsigned char* __restrict__ l8, float* __restrict__ scale)
{
    const int w = threadIdx.x >> 5, l = threadIdx.x & 31;
    const long row = (long)blockIdx.x * 8 + w;
    float4 v = *reinterpret_cast<const float4*>(src + row * 128 + l * 4);
    float mx = fmaxf(fmaxf(fabsf(v.x), fabsf(v.y)), fmaxf(fabsf(v.z), fabsf(v.w)));
#pragma unroll
    for (int o = 16; o > 0; o >>= 1) mx = fmaxf(mx, __shfl_xor_sync(0xffffffffu, mx, o));
    mx = fmaxf(mx, 1e-20f);
    if (l == 0) scale[row] = mx;
    const float inv = 127.0f / mx;

    int hx = __float2int_rn(v.x * inv), hy = __float2int_rn(v.y * inv);
    int hz = __float2int_rn(v.z * inv), hw = __float2int_rn(v.w * inv);
    int lx = __float2int_rn((v.x * inv - (float)hx) * 127.0f);
    int ly = __float2int_rn((v.y * inv - (float)hy) * 127.0f);
    int lz = __float2int_rn((v.z * inv - (float)hz) * 127.0f);
    int lw = __float2int_rn((v.w * inv - (float)hw) * 127.0f);

    unsigned hp = (hx & 255) | ((hy & 255) << 8) | ((hz & 255) << 16) | ((unsigned)(hw & 255) << 24);
    unsigned lp = (lx & 255) | ((ly & 255) << 8) | ((lz & 255) << 16) | ((unsigned)(lw & 255) << 24);
    reinterpret_cast<unsigned*>(h8)[row * 32 + l] = hp;
    reinterpret_cast<unsigned*>(l8)[row * 32 + l] = lp;
}

// ------------------------------ flash attention ----------------------------
// One CTA = 128 q-rows of one (b,h). 8 warps x 16 q-rows.
// S-gemm: int8 2-digit (s32 accum), PV: bf16 3-term. KV chunk = 64 keys.
__global__ void __launch_bounds__(256)
flash_attn(const unsigned char* __restrict__ Qh, const unsigned char* __restrict__ Ql,
           const float* __restrict__ Sq,
           const unsigned char* __restrict__ Kh, const unsigned char* __restrict__ Kl,
           const float* __restrict__ Sk,
           const unsigned* __restrict__ Vt, const float* __restrict__ PE_r,
           unsigned* __restrict__ vals)
{
    extern __shared__ __align__(1024) char smem[];
    constexpr int SKL = 8192, SV_HI = 16384, SV_LO = 32768;
    constexpr int SKS = 49152;
    constexpr int SBIAS = 49408, BIAS_STRIDE = 272, BIAS_BUF = 34816;
    constexpr int NCHUNK = SQ / 64;   // 32

    const int tid = threadIdx.x;
    const int l = tid & 31;
    const int w = tid >> 5;
    const int g = l >> 2;
    const int t = l & 3;
    const int bh = blockIdx.y;
    const int q0 = blockIdx.x * 128;
    const int qw = q0 + w * 16;
    const unsigned sbase = smem_u32(smem);

    const unsigned char* Qhb = Qh + ((long)bh * SQ + qw) * 128;
    const unsigned char* Qlb = Ql + ((long)bh * SQ + qw) * 128;
    const unsigned char* Khb = Kh + (long)bh * SQ * 128;
    const unsigned char* Klb = Kl + (long)bh * SQ * 128;
    const unsigned* Vb = Vt + (long)bh * HD * SQ;
    const float* Pb = PE_r + ((long)(bh & 7) * SQ + q0) * SQ;

    // ---- Q int8 A-frags (4 k32 steps) ----
    unsigned qh[4][4], ql[4][4];
#pragma unroll
    for (int ks = 0; ks < 4; ks++) {
        qh[ks][0] = *reinterpret_cast<const unsigned*>(Qhb + (long)g * 128 + ks * 32 + 4 * t);
        qh[ks][1] = *reinterpret_cast<const unsigned*>(Qhb + (long)(g + 8) * 128 + ks * 32 + 4 * t);
        qh[ks][2] = *reinterpret_cast<const unsigned*>(Qhb + (long)g * 128 + ks * 32 + 16 + 4 * t);
        qh[ks][3] = *reinterpret_cast<const unsigned*>(Qhb + (long)(g + 8) * 128 + ks * 32 + 16 + 4 * t);
        ql[ks][0] = *reinterpret_cast<const unsigned*>(Qlb + (long)g * 128 + ks * 32 + 4 * t);
        ql[ks][1] = *reinterpret_cast<const unsigned*>(Qlb + (long)(g + 8) * 128 + ks * 32 + 4 * t);
        ql[ks][2] = *reinterpret_cast<const unsigned*>(Qlb + (long)g * 128 + ks * 32 + 16 + 4 * t);
        ql[ks][3] = *reinterpret_cast<const unsigned*>(Qlb + (long)(g + 8) * 128 + ks * 32 + 16 + 4 * t);
    }
    const float sq0 = Sq[(long)bh * SQ + qw + g];
    const float sq1 = Sq[(long)bh * SQ + qw + g + 8];

    float oacc[8][4];
#pragma unroll
    for (int j = 0; j < 8; j++)
#pragma unroll
        for (int k = 0; k < 4; k++) oacc[j][k] = 0.0f;
    float m0r = -1e30f, m1r = -1e30f, l0r = 0.0f, l1r = 0.0f;

    const int brow = (l & 7) + ((l >> 4) & 1) * 8;
    const int bkp  = ((l >> 3) & 1) * 16;

    // prefetch bias chunk 0
    {
        unsigned base = sbase + SBIAS;
#pragma unroll
        for (int it = 0; it < 8; it++) {
            int idx = tid + it * 256;
            int r = idx >> 4, ch = idx & 15;
            CP_ASYNC16(base + r * BIAS_STRIDE + ch * 16, Pb + (long)r * SQ + ch * 4);
        }
        CP_COMMIT();
    }

    for (int ck = 0; ck < NCHUNK; ck++) {
        __syncthreads();

        // ---- K int8 tiles: 64 rows x 128 bytes, sw128, hi+lo slabs ----
#pragma unroll
        for (int it = 0; it < 2; it++) {
            int idx = tid + it * 256;
            int r = idx >> 3, c = idx & 7;
            unsigned sw = sw128(r * 128 + c * 16);
            *reinterpret_cast<uint4*>(smem + sw) =
                *reinterpret_cast<const uint4*>(Khb + ((long)(ck * 64 + r)) * 128 + c * 16);
            *reinterpret_cast<uint4*>(smem + SKL + sw) =
                *reinterpret_cast<const uint4*>(Klb + ((long)(ck * 64 + r)) * 128 + c * 16);
        }
        // ---- V tile (packed bf16 pairs) -> hi/lo slabs ----
#pragma unroll
        for (int it = 0; it < 4; it++) {
            int idx = tid + it * 256;
            int r = idx >> 4, q = idx & 15;
            uint4 wv = *reinterpret_cast<const uint4*>(Vb + (long)r * SQ + ck * 64 + q * 4);
            unsigned off = (q >> 3) * 4096 + sw64(r * 64 + (q & 7) * 8);
            *reinterpret_cast<uint2*>(smem + SV_HI + off) =
                make_uint2(__byte_perm(wv.x, wv.y, 0x7632), __byte_perm(wv.z, wv.w, 0x7632));
            *reinterpret_cast<uint2*>(smem + SV_LO + off) =
                make_uint2(__byte_perm(wv.x, wv.y, 0x5410), __byte_perm(wv.z, wv.w, 0x5410));
        }
        // ---- K scales for this chunk ----
        if (tid < 64)
            reinterpret_cast<float*>(smem + SKS)[tid] = Sk[(long)bh * SQ + ck * 64 + tid];

        // ---- prefetch next bias tile ----
        if (ck + 1 < NCHUNK) {
            unsigned base = sbase + SBIAS + ((ck + 1) & 1) * BIAS_BUF;
#pragma unroll
            for (int it = 0; it < 8; it++) {
                int idx = tid + it * 256;
                int r = idx >> 4, ch = idx & 15;
                CP_ASYNC16(base + r * BIAS_STRIDE + ch * 16,
                           Pb + (long)r * SQ + (ck + 1) * 64 + ch * 4);
            }
        }
        CP_COMMIT();
        CP_WAIT1();
        __syncthreads();

        // ---- S = Q K^T in int8: hh + cross accumulators ----
        int hh[8][4], cr[8][4];
#pragma unroll
        for (int j = 0; j < 8; j++)
#pragma unroll
            for (int k = 0; k < 4; k++) { hh[j][k] = 0; cr[j][k] = 0; }

#pragma unroll
        for (int ks = 0; ks < 4; ks++) {
            unsigned kh[4][4], kl[4][4];
#pragma unroll
            for (int p = 0; p < 4; p++) {
                unsigned sw = sw128((p * 16 + brow) * 128 + ks * 32 + bkp);
                LDSM4(kh[p][0], kh[p][1], kh[p][2], kh[p][3], sbase + sw);
                LDSM4(kl[p][0], kl[p][1], kl[p][2], kl[p][3], sbase + SKL + sw);
            }
#pragma unroll
            for (int j = 0; j < 8; j++) {
                const int p = j >> 1, h = (j & 1) * 2;
                MMAS8(hh[j], qh[ks], kh[p][h], kh[p][h + 1]);
                MMAS8(cr[j], qh[ks], kl[p][h], kl[p][h + 1]);
                MMAS8(cr[j], ql[ks], kh[p][h], kh[p][h + 1]);
            }
        }

        // ---- convert to f32 scores + bias add ----
        float sacc[8][4];
        {
            const float* sks = reinterpret_cast<const float*>(smem + SKS);
            const char* bb = smem + SBIAS + (ck & 1) * BIAS_BUF;
            const int r0 = w * 16 + g, r1 = r0 + 8;
            const float c127 = 1.0f / 127.0f, nf = 1.0f / 16129.0f;
            const float f0b = sq0 * nf, f1b = sq1 * nf;
#pragma unroll
            for (int j = 0; j < 8; j++) {
                float sk0 = sks[j * 8 + 2 * t], sk1 = sks[j * 8 + 2 * t + 1];
                float2 b0 = *reinterpret_cast<const float2*>(bb + r0 * BIAS_STRIDE + (j * 8 + 2 * t) * 4);
                float2 b1 = *reinterpret_cast<const float2*>(bb + r1 * BIAS_STRIDE + (j * 8 + 2 * t) * 4);
                sacc[j][0] = fmaf(f0b * sk0, (float)hh[j][0] + (float)cr[j][0] * c127, b0.x);
                sacc[j][1] = fmaf(f0b * sk1, (float)hh[j][1] + (float)cr[j][1] * c127, b0.y);
                sacc[j][2] = fmaf(f1b * sk0, (float)hh[j][2] + (float)cr[j][2] * c127, b1.x);
                sacc[j][3] = fmaf(f1b * sk1, (float)hh[j][3] + (float)cr[j][3] * c127, b1.y);
            }
        }

        // ---- online softmax ----
        float mx0 = -1e30f, mx1 = -1e30f;
#pragma unroll
        for (int j = 0; j < 8; j++) {
            mx0 = fmaxf(mx0, fmaxf(sacc[j][0], sacc[j][1]));
            mx1 = fmaxf(mx1, fmaxf(sacc[j][2], sacc[j][3]));
        }
        mx0 = fmaxf(mx0, __shfl_xor_sync(0xffffffffu, mx0, 1));
        mx0 = fmaxf(mx0, __shfl_xor_sync(0xffffffffu, mx0, 2));
        mx1 = fmaxf(mx1, __shfl_xor_sync(0xffffffffu, mx1, 1));
        mx1 = fmaxf(mx1, __shfl_xor_sync(0xffffffffu, mx1, 2));

        const float mn0 = fmaxf(m0r, mx0), mn1 = fmaxf(m1r, mx1);
        const float cor0 = __expf(m0r - mn0), cor1 = __expf(m1r - mn1);
        m0r = mn0; m1r = mn1;

        float sum0 = 0.0f, sum1 = 0.0f;
#pragma unroll
        for (int j = 0; j < 8; j++) {
            sacc[j][0] = __expf(sacc[j][0] - mn0);
            sacc[j][1] = __expf(sacc[j][1] - mn0);
            sacc[j][2] = __expf(sacc[j][2] - mn1);
            sacc[j][3] = __expf(sacc[j][3] - mn1);
            sum0 += sacc[j][0] + sacc[j][1];
            sum1 += sacc[j][2] + sacc[j][3];
        }
        sum0 += __shfl_xor_sync(0xffffffffu, sum0, 1);
        sum0 += __shfl_xor_sync(0xffffffffu, sum0, 2);
        sum1 += __shfl_xor_sync(0xffffffffu, sum1, 1);
        sum1 += __shfl_xor_sync(0xffffffffu, sum1, 2);
        l0r = l0r * cor0 + sum0;
        l1r = l1r * cor1 + sum1;

#pragma unroll
        for (int j = 0; j < 8; j++) {
            oacc[j][0] *= cor0; oacc[j][1] *= cor0;
            oacc[j][2] *= cor1; oacc[j][3] *= cor1;
        }

        // ---- PV: bf16 3-term ----
#pragma unroll
        for (int kk = 0; kk < 4; kk++) {
            unsigned pH[4], pL[4];
            split2(sacc[2 * kk][0],     sacc[2 * kk][1],     pH[0], pL[0]);
            split2(sacc[2 * kk][2],     sacc[2 * kk][3],     pH[1], pL[1]);
            split2(sacc[2 * kk + 1][0], sacc[2 * kk + 1][1], pH[2], pL[2]);
            split2(sacc[2 * kk + 1][2], sacc[2 * kk + 1][3], pH[3], pL[3]);

            unsigned vH[4][4], vL[4][4];
            const unsigned slab = sbase + SV_HI + (kk >> 1) * 4096;
            const unsigned koff = (kk & 1) * 32 + bkp;
#pragma unroll
            for (int p = 0; p < 4; p++) {
                unsigned sw = sw64((p * 16 + brow) * 64 + koff);
                LDSM4(vH[p][0], vH[p][1], vH[p][2], vH[p][3], slab + sw);
                LDSM4(vL[p][0], vL[p][1], vL[p][2], vL[p][3], slab + (SV_LO - SV_HI) + sw);
            }
#pragma unroll
            for (int j = 0; j < 8; j++) {
                const int p = j >> 1, h = (j & 1) * 2;
                MMA16816(oacc[j], pH, vH[p][h], vH[p][h + 1]);
                MMA16816(oacc[j], pH, vL[p][h], vL[p][h + 1]);
                MMA16816(oacc[j], pL, vH[p][h], vH[p][h + 1]);
            }
        }
    }

    // ---- epilogue ----
    const float inv0 = 1.0f / l0r, inv1 = 1.0f / l1r;
    const int b = bh >> 3, h = bh & 7;
    const long row0 = (long)(b * SQ + qw + g) * EMB + h * HD;
    const long row1 = (long)(b * SQ + qw + g + 8) * EMB + h * HD;
#pragma unroll
    for (int j = 0; j < 8; j++) {
        int col = j * 8 + 2 * t;
        *reinterpret_cast<uint2*>(&vals[row0 + col]) =
            make_uint2(packf(oacc[j][0] * inv0), packf(oacc[j][1] * inv0));
        *reinterpret_cast<uint2*>(&vals[row1 + col]) =
            make_uint2(packf(oacc[j][2] * inv1), packf(oacc[j][3] * inv1));
    }
}

// ------------------------------ launch -------------------------------------
template <typename Epi>
static void launch_gemm(dim3 grid, const unsigned* A, const unsigned* B, int K,
                        int lda, int ldb, long sA, long sB, Epi epi)
{
    gemm_hmma<Epi><<<grid, 256, 49152>>>(A, B, K, lda, ldb, sA, sB, epi);
}

extern "C" void kernel_launch(void* const* d_in, const int* in_sizes, int n_in,
                              void* d_out, int out_size)
{
    const float* x    = (const float*)d_in[0];
    const float* PE   = (const float*)d_in[1];
    const float* PE_r = (const float*)d_in[2];
    const float* Wqkv = (const float*)d_in[3];
    const float* UqUk = (const float*)d_in[4];
    const float* Wo   = (const float*)d_in[5];
    float* out = (float*)d_out;

    void* p;
    cudaGetSymbolAddress(&p, g_x2);   unsigned* x2  = (unsigned*)p;
    cudaGetSymbolAddress(&p, g_PE2);  unsigned* pe2 = (unsigned*)p;
    cudaGetSymbolAddress(&p, g_W2);   unsigned* w2  = (unsigned*)p;
    cudaGetSymbolAddress(&p, g_U2);   unsigned* u2  = (unsigned*)p;
    cudaGetSymbolAddress(&p, g_Wo2);  unsigned* wo2 = (unsigned*)p;
    cudaGetSymbolAddress(&p, g_Qcat); float* Qcf = (float*)p;
    cudaGetSymbolAddress(&p, g_Kcat); float* Kcf = (float*)p;
    cudaGetSymbolAddress(&p, g_Qh);   unsigned char* Qh = (unsigned char*)p;
    cudaGetSymbolAddress(&p, g_Ql);   unsigned char* Ql = (unsigned char*)p;
    cudaGetSymbolAddress(&p, g_Kh);   unsigned char* Kh = (unsigned char*)p;
    cudaGetSymbolAddress(&p, g_Kl);   unsigned char* Kl = (unsigned char*)p;
    cudaGetSymbolAddress(&p, g_sq);   float* Sq = (float*)p;
    cudaGetSymbolAddress(&p, g_sk);   float* Sk = (float*)p;
    cudaGetSymbolAddress(&p, g_Vt);   unsigned* Vt = (unsigned*)p;
    cudaGetSymbolAddress(&p, g_vals); unsigned* Vl = (unsigned*)p;

    auto pk = [](const float* in, unsigned* outp, long n) {
        int n4 = (int)(n / 4);
        pack_kernel<<<(n4 + 255) / 256, 256>>>((const float4*)in, (uint4*)outp, n4);
    };
    pk(x,    x2,  (long)BB * SQ * EMB);
    pk(PE,   pe2, (long)BB * SQ * EMB);
    pk(Wqkv, w2,  (long)3 * EMB * EMB);
    pk(UqUk, u2,  (long)2 * EMB * EMB);
    pk(Wo,   wo2, (long)EMB * EMB);

    // 1) qkv projection
    launch_gemm(dim3(24, 64, 1), x2, w2, EMB, EMB, EMB, 0, 0, EpiQKV{});
    // 2) positional projection
    launch_gemm(dim3(16, 64, 1), pe2, u2, EMB, EMB, EMB, 0, 0, EpiPE{});
    // 3) int8 quantization of Qcat / Kcat (per-row scales)
    quant_rows<<<BB * HH * SQ / 8, 256>>>(Qcf, Qh, Ql, Sq);
    quant_rows<<<BB * HH * SQ / 8, 256>>>(Kcf, Kh, Kl, Sk);
    // 4) fused attention
    static bool attr_set = false;
    if (!attr_set) {
        cudaFuncSetAttribute(flash_attn, cudaFuncAttributeMaxDynamicSharedMemorySize, 119040);
        attr_set = true;
    }
    flash_attn<<<dim3(SQ / 128, BB * HH), 256, 119040>>>(Qh, Ql, Sq, Kh, Kl, Sk, Vt, PE_r, Vl);
    // 5) out projection
    launch_gemm(dim3(8, 64, 1), Vl, wo2, EMB, EMB, EMB, 0, 0, EpiOut{out});
}

// round 7
// speedup vs baseline: 1.8976x; 1.8976x over previous
#include <cuda_runtime.h>
#include <cuda_bf16.h>
#include <cstdint>

// ---------------------------------------------------------------------------
// TUPE multihead attention — bf16 split-precision (hi/lo) HMMA pipeline.
//  Flash middle: K/V stored as pre-split bf16 global images in the exact
//  smem slab layout (sw64 baked in) -> flash loader is pure cp.async,
//  double-buffered. Compute identical to round 5.
//  GEMM rule everywhere: D += Ahi*Bhi + Ahi*Blo + Alo*Bhi  (fp32 accum)
// ---------------------------------------------------------------------------

static constexpr int BB  = 4;
static constexpr int HH  = 8;
static constexpr int SQ  = 2048;
static constexpr int EMB = 512;
static constexpr int HD  = 64;
static constexpr float QK_SCALE = 0.0883883476483184f; // 1/sqrt(2*64)

// ------------------------------ scratch ------------------------------------
__device__ __align__(16) unsigned g_x2  [(size_t)BB * SQ * EMB];
__device__ __align__(16) unsigned g_PE2 [(size_t)BB * SQ * EMB];
__device__ __align__(16) unsigned g_W2  [(size_t)3 * EMB * EMB];
__device__ __align__(16) unsigned g_U2  [(size_t)2 * EMB * EMB];
__device__ __align__(16) unsigned g_Wo2 [(size_t)EMB * EMB];
__device__ __align__(16) unsigned g_Qcat[(size_t)BB * HH * SQ * 128];        // packed u32
// K images: per (bh, ck): 16384 bytes = 4 slabs x 4096 (dims 32dpp, 64B rows, sw64)
__device__ __align__(16) unsigned short g_KH[(size_t)BB * HH * SQ * 128];
__device__ __align__(16) unsigned short g_KL[(size_t)BB * HH * SQ * 128];
// V images: per (bh, ck): 8192 bytes = 2 slabs x 4096 (64 dim-rows x 32 keys, sw64)
__device__ __align__(16) unsigned short g_VH[(size_t)BB * HH * HD * SQ];
__device__ __align__(16) unsigned short g_VL[(size_t)BB * HH * HD * SQ];
__device__ __align__(16) unsigned g_vals[(size_t)BB * SQ * EMB];             // packed u32

// ------------------------------ helpers ------------------------------------
__device__ __forceinline__ unsigned smem_u32(const void* p) {
    unsigned a;
    asm("{ .reg .u64 t; cvta.to.shared.u64 t, %1; cvt.u32.u64 %0, t; }" : "=r"(a) : "l"(p));
    return a;
}
__device__ __forceinline__ unsigned packf(float v) {
    __nv_bfloat16 hi = __float2bfloat16(v);
    float r = v - __bfloat162float(hi);
    __nv_bfloat16 lo = __float2bfloat16(r);
    return ((unsigned)__bfloat16_as_ushort(hi) << 16) | (unsigned)__bfloat16_as_ushort(lo);
}
__device__ __forceinline__ uint4 pack4(float4 v, float sc) {
    return make_uint4(packf(v.x * sc), packf(v.y * sc), packf(v.z * sc), packf(v.w * sc));
}
// split (a,b) into bf16x2 hi frag + bf16x2 lo frag (a in low half)
__device__ __forceinline__ void split2(float a, float b, unsigned& h, unsigned& lo) {
    __nv_bfloat16 ah = __float2bfloat16(a), bh = __float2bfloat16(b);
    float ar = a - __bfloat162float(ah), br = b - __bfloat162float(bh);
    __nv_bfloat16 al = __float2bfloat16(ar), bl = __float2bfloat16(br);
    h  = ((unsigned)__bfloat16_as_ushort(bh) << 16) | (unsigned)__bfloat16_as_ushort(ah);
    lo = ((unsigned)__bfloat16_as_ushort(bl) << 16) | (unsigned)__bfloat16_as_ushort(al);
}
__device__ __forceinline__ void split4(float4 v, uint2& hi, uint2& lo) {
    unsigned h0, l0, h1, l1;
    split2(v.x, v.y, h0, l0);
    split2(v.z, v.w, h1, l1);
    hi = make_uint2(h0, h1);
    lo = make_uint2(l0, l1);
}

__global__ void __launch_bounds__(256)
pack_kernel(const float4* __restrict__ in, uint4* __restrict__ out, int n4)
{
    int i = blockIdx.x * 256 + threadIdx.x;
    if (i < n4) out[i] = pack4(in[i], 1.0f);
}

#define LDSM4(r0, r1, r2, r3, a)                                              \
    asm volatile("ldmatrix.sync.aligned.m8n8.x4.shared.b16 {%0,%1,%2,%3}, [%4];" \
                 : "=r"(r0), "=r"(r1), "=r"(r2), "=r"(r3) : "r"(a))

#define MMA16816(c, a, b0, b1)                                                \
    asm volatile("mma.sync.aligned.m16n8k16.row.col.f32.bf16.bf16.f32 "       \
                 "{%0,%1,%2,%3}, {%4,%5,%6,%7}, {%8,%9}, {%0,%1,%2,%3};"      \
                 : "+f"((c)[0]), "+f"((c)[1]), "+f"((c)[2]), "+f"((c)[3])     \
                 : "r"((a)[0]), "r"((a)[1]), "r"((a)[2]), "r"((a)[3]),        \
                   "r"(b0), "r"(b1))

#define CP_ASYNC16(dst, src) \
    asm volatile("cp.async.cg.shared.global [%0], [%1], 16;" :: "r"(dst), "l"(src))
#define CP_COMMIT() asm volatile("cp.async.commit_group;" ::: "memory")
#define CP_WAIT0()  asm volatile("cp.async.wait_group 0;" ::: "memory")
#define CP_WAIT1()  asm volatile("cp.async.wait_group 1;" ::: "memory")

__device__ __forceinline__ unsigned sw64(unsigned off)  { return off ^ ((off >> 3) & 0x30); }

// ------------------------------ GEMM (projections / out) -------------------
template <typename Epi>
__global__ void __launch_bounds__(256, 2)
gemm_hmma(const unsigned* __restrict__ A, const unsigned* __restrict__ B,
          int K, int lda, int ldb, long sA, long sB, Epi epi)
{
    extern __shared__ __align__(1024) char smem[];
    constexpr int SA_LO = 8192, SB_HI = 16384, SB_LO = 20480, STAGE = 24576;

    const int tid = threadIdx.x;
    const int l   = tid & 31;
    const int w   = tid >> 5;
    const int wm  = w & 3;
    const int wn  = w >> 2;
    const int m0  = wm * 32;
    const int n0  = wn * 32;
    const int bz  = blockIdx.z;
    const unsigned sbase = smem_u32(smem);

    const unsigned* Ab = A + bz * sA + (long)blockIdx.y * 128 * lda;
    const unsigned* Bb = B + bz * sB + (long)blockIdx.x * 64 * ldb;

    float acc[2][4][4];
#pragma unroll
    for (int i = 0; i < 2; i++)
#pragma unroll
        for (int j = 0; j < 4; j++)
#pragma unroll
            for (int k = 0; k < 4; k++) acc[i][j][k] = 0.0f;

    const int arow = (l & 7) + ((l >> 3) & 1) * 8;
    const int akp  = ((l >> 4) & 1) * 16;
    const int brow = (l & 7) + ((l >> 4) & 1) * 8;
    const int bkp  = ((l >> 3) & 1) * 16;

    uint4 ra[4], rb[2];
    const int nChunks = K >> 5;

    auto load_global = [&](int c) {
#pragma unroll
        for (int it = 0; it < 4; it++) {
            int idx = tid + it * 256;
            int r = idx >> 3, q = idx & 7;
            ra[it] = *reinterpret_cast<const uint4*>(Ab + (long)r * lda + c * 32 + q * 4);
        }
#pragma unroll
        for (int it = 0; it < 2; it++) {
            int idx = tid + it * 256;
            int r = idx >> 3, q = idx & 7;
            rb[it] = *reinterpret_cast<const uint4*>(Bb + (long)r * ldb + c * 32 + q * 4);
        }
    };
    auto store_stage = [&](char* buf) {
#pragma unroll
        for (int it = 0; it < 4; it++) {
            int idx = tid + it * 256;
            int r = idx >> 3, q = idx & 7;
            unsigned sw = sw64(r * 64 + q * 8);
            uint4 wv = ra[it];
            *reinterpret_cast<uint2*>(buf + sw) =
                make_uint2(__byte_perm(wv.x, wv.y, 0x7632), __byte_perm(wv.z, wv.w, 0x7632));
            *reinterpret_cast<uint2*>(buf + SA_LO + sw) =
                make_uint2(__byte_perm(wv.x, wv.y, 0x5410), __byte_perm(wv.z, wv.w, 0x5410));
        }
#pragma unroll
        for (int it = 0; it < 2; it++) {
            int idx = tid + it * 256;
            int r = idx >> 3, q = idx & 7;
            unsigned sw = sw64(r * 64 + q * 8);
            uint4 wv = rb[it];
            *reinterpret_cast<uint2*>(buf + SB_HI + sw) =
                make_uint2(__byte_perm(wv.x, wv.y, 0x7632), __byte_perm(wv.z, wv.w, 0x7632));
            *reinterpret_cast<uint2*>(buf + SB_LO + sw) =
                make_uint2(__byte_perm(wv.x, wv.y, 0x5410), __byte_perm(wv.z, wv.w, 0x5410));
        }
    };

    load_global(0);
    store_stage(smem);
    __syncthreads();

    for (int c = 0; c < nChunks; c++) {
        const bool more = (c + 1) < nChunks;
        if (more) load_global(c + 1);

        const unsigned stage = sbase + (c & 1) * STAGE;
#pragma unroll
        for (int ks = 0; ks < 2; ks++) {
            unsigned aH[2][4], aL[2][4], bH[2][4], bL[2][4];
#pragma unroll
            for (int i = 0; i < 2; i++) {
                unsigned off = (m0 + i * 16 + arow) * 64 + ks * 32 + akp;
                unsigned sw = sw64(off);
                LDSM4(aH[i][0], aH[i][1], aH[i][2], aH[i][3], stage + sw);
                LDSM4(aL[i][0], aL[i][1], aL[i][2], aL[i][3], stage + SA_LO + sw);
            }
#pragma unroll
            for (int p = 0; p < 2; p++) {
                unsigned off = (n0 + p * 16 + brow) * 64 + ks * 32 + bkp;
                unsigned sw = sw64(off);
                LDSM4(bH[p][0], bH[p][1], bH[p][2], bH[p][3], stage + SB_HI + sw);
                LDSM4(bL[p][0], bL[p][1], bL[p][2], bL[p][3], stage + SB_LO + sw);
            }
#pragma unroll
            for (int i = 0; i < 2; i++)
#pragma unroll
                for (int j = 0; j < 4; j++) {
                    const int p = j >> 1, h = (j & 1) * 2;
                    MMA16816(acc[i][j], aH[i], bH[p][h], bH[p][h + 1]);
                    MMA16816(acc[i][j], aH[i], bL[p][h], bL[p][h + 1]);
                    MMA16816(acc[i][j], aL[i], bH[p][h], bH[p][h + 1]);
                }
        }

        if (more) store_stage(smem + ((c + 1) & 1) * STAGE);
        __syncthreads();
    }

    float* C = reinterpret_cast<float*>(smem);   // [128][68]
#pragma unroll
    for (int i = 0; i < 2; i++)
#pragma unroll
        for (int j = 0; j < 4; j++) {
            int r0  = m0 + i * 16 + (l >> 2);
            int col = n0 + j * 8 + (l & 3) * 2;
            *reinterpret_cast<float2*>(C + r0 * 68 + col)       = make_float2(acc[i][j][0], acc[i][j][1]);
            *reinterpret_cast<float2*>(C + (r0 + 8) * 68 + col) = make_float2(acc[i][j][2], acc[i][j][3]);
        }
    __syncthreads();

    {
        int r = tid >> 1, seg = (tid & 1) << 5;
        int m  = blockIdx.y * 128 + r;
        int nb = blockIdx.x * 64 + seg;
        const float* Crow = C + r * 68 + seg;
#pragma unroll
        for (int i = 0; i < 8; i++) {
            float4 v = *reinterpret_cast<const float4*>(Crow + i * 4);
            epi(bz, m, nb + i * 4, v);
        }
    }
}

// ------------------------------ epilogues ----------------------------------
struct EpiQKV {   // m in [0,8192), n in [0,1536)
    __device__ void operator()(int, int m, int n, float4 v) const {
        int b = m >> 11, s = m & (SQ - 1);
        int h = n / 192, r = n - h * 192;
        int bh = b * HH + h;
        if (r < HD) {
            long row = ((long)bh * SQ + s);
            *reinterpret_cast<uint4*>(&g_Qcat[row * 128 + r]) = pack4(v, QK_SCALE);
        } else if (r < 2 * HD) {
            // K word part: dims d0..d0+3 (d0 in [0,64), multiple of 4)
            int d0 = r - HD;
            int ck = s >> 6, rr = s & 63;
            long base = ((long)bh * 32 + ck) * 16384;
            unsigned off = (unsigned)((d0 >> 5) * 4096) + sw64(rr * 64 + (d0 & 31) * 2);
            uint2 hi, lo;
            split4(v, hi, lo);
            *reinterpret_cast<uint2*>(reinterpret_cast<char*>(g_KH) + base + off) = hi;
            *reinterpret_cast<uint2*>(reinterpret_cast<char*>(g_KL) + base + off) = lo;
        } else {
            // V: dims d..d+3 for key s
            int d = r - 2 * HD;
            int ck = s >> 6, kc = s & 63;
            long base = ((long)bh * 32 + ck) * 8192 + (kc >> 5) * 4096;
            int kb = (kc & 31) * 2;
#pragma unroll
            for (int i = 0; i < 4; i++) {
                float val = (&v.x)[i];
                __nv_bfloat16 hb = __float2bfloat16(val);
                __nv_bfloat16 lb = __float2bfloat16(val - __bfloat162float(hb));
                unsigned off2 = sw64((d + i) * 64 + kb);
                *reinterpret_cast<__nv_bfloat16*>(reinterpret_cast<char*>(g_VH) + base + off2) = hb;
                *reinterpret_cast<__nv_bfloat16*>(reinterpret_cast<char*>(g_VL) + base + off2) = lb;
            }
        }
    }
};
struct EpiPE {    // n in [0,1024)
    __device__ void operator()(int, int m, int n, float4 v) const {
        int b = m >> 11, s = m & (SQ - 1);
        int h = n >> 7, r = n & 127;
        int bh = b * HH + h;
        if (r < HD) {
            long row = ((long)bh * SQ + s);
            *reinterpret_cast<uint4*>(&g_Qcat[row * 128 + HD + r]) = pack4(v, QK_SCALE);
        } else {
            // K positional part: dims r..r+3 (r in [64,128))
            int d0 = r;
            int ck = s >> 6, rr = s & 63;
            long base = ((long)bh * 32 + ck) * 16384;
            unsigned off = (unsigned)((d0 >> 5) * 4096) + sw64(rr * 64 + (d0 & 31) * 2);
            uint2 hi, lo;
            split4(v, hi, lo);
            *reinterpret_cast<uint2*>(reinterpret_cast<char*>(g_KH) + base + off) = hi;
            *reinterpret_cast<uint2*>(reinterpret_cast<char*>(g_KL) + base + off) = lo;
        }
    }
};
struct EpiOut {
    float* out;
    __device__ void operator()(int, int m, int n, float4 v) const {
        *reinterpret_cast<float4*>(&out[(long)m * EMB + n]) = v;
    }
};

// ------------------------------ flash attention ----------------------------
// One CTA = 128 q-rows of one (b,h). 8 warps x 16 q-rows.
// KV chunk = 64 keys. K/V arrive pre-split + pre-swizzled via cp.async,
// double-buffered; bias double-buffered via cp.async. Compute = round 5.
__global__ void __launch_bounds__(256)
flash_attn(const unsigned* __restrict__ Qc,
           const char* __restrict__ KH, const char* __restrict__ KL,
           const char* __restrict__ VH, const char* __restrict__ VL,
           const float* __restrict__ PE_r, unsigned* __restrict__ vals)
{
    extern __shared__ __align__(1024) char smem[];
    constexpr int KVBUF = 49152;                       // KH 16K | KL 16K | VH 8K | VL 8K
    constexpr int SBIAS = 98304, BIAS_STRIDE = 272, BIAS_BUF = 34816;
    constexpr int NCHUNK = SQ / 64;   // 32

    const int tid = threadIdx.x;
    const int l = tid & 31;
    const int w = tid >> 5;
    const int g = l >> 2;
    const int t = l & 3;
    const int bh = blockIdx.y;
    const int q0 = blockIdx.x * 128;
    const int qw = q0 + w * 16;
    const unsigned sbase = smem_u32(smem);

    const unsigned* Qb = Qc + ((long)bh * SQ + qw) * 128;
    const char* KHb = KH + (long)bh * 32 * 16384;
    const char* KLb = KL + (long)bh * 32 * 16384;
    const char* VHb = VH + (long)bh * 32 * 8192;
    const char* VLb = VL + (long)bh * 32 * 8192;
    const float* Pb = PE_r + ((long)(bh & 7) * SQ + q0) * SQ;

    // ---- Q A-frags in registers (8 k16 steps, hi/lo) ----
    unsigned qH[8][4], qL[8][4];
#pragma unroll
    for (int kc = 0; kc < 8; kc++) {
        uint2 e00 = *reinterpret_cast<const uint2*>(Qb + (long)g * 128 + kc * 16 + 2 * t);
        uint2 e10 = *reinterpret_cast<const uint2*>(Qb + (long)(g + 8) * 128 + kc * 16 + 2 * t);
        uint2 e01 = *reinterpret_cast<const uint2*>(Qb + (long)g * 128 + kc * 16 + 8 + 2 * t);
        uint2 e11 = *reinterpret_cast<const uint2*>(Qb + (long)(g + 8) * 128 + kc * 16 + 8 + 2 * t);
        qH[kc][0] = __byte_perm(e00.x, e00.y, 0x7632); qL[kc][0] = __byte_perm(e00.x, e00.y, 0x5410);
        qH[kc][1] = __byte_perm(e10.x, e10.y, 0x7632); qL[kc][1] = __byte_perm(e10.x, e10.y, 0x5410);
        qH[kc][2] = __byte_perm(e01.x, e01.y, 0x7632); qL[kc][2] = __byte_perm(e01.x, e01.y, 0x5410);
        qH[kc][3] = __byte_perm(e11.x, e11.y, 0x7632); qL[kc][3] = __byte_perm(e11.x, e11.y, 0x5410);
    }

    float oacc[8][4];
#pragma unroll
    for (int j = 0; j < 8; j++)
#pragma unroll
        for (int k = 0; k < 4; k++) oacc[j][k] = 0.0f;
    float m0r = -1e30f, m1r = -1e30f, l0r = 0.0f, l1r = 0.0f;

    const int brow = (l & 7) + ((l >> 4) & 1) * 8;
    const int bkp  = ((l >> 3) & 1) * 16;

    auto prefetch = [&](int ck) {
        const int buf = ck & 1;
        const unsigned sb = sbase + buf * KVBUF;
        const char* kh = KHb + (long)ck * 16384;
        const char* klo = KLb + (long)ck * 16384;
        const char* vh = VHb + (long)ck * 8192;
        const char* vlo = VLb + (long)ck * 8192;
#pragma unroll
        for (int it = 0; it < 4; it++) {
            int o = (tid + it * 256) * 16;
            CP_ASYNC16(sb + o, kh + o);
            CP_ASYNC16(sb + 16384 + o, klo + o);
        }
#pragma unroll
        for (int it = 0; it < 2; it++) {
            int o = (tid + it * 256) * 16;
            CP_ASYNC16(sb + 32768 + o, vh + o);
            CP_ASYNC16(sb + 40960 + o, vlo + o);
        }
        const unsigned bb = sbase + SBIAS + buf * BIAS_BUF;
#pragma unroll
        for (int it = 0; it < 8; it++) {
            int idx = tid + it * 256;
            int r = idx >> 4, c = idx & 15;
            CP_ASYNC16(bb + r * BIAS_STRIDE + c * 16,
                       Pb + (long)r * SQ + ck * 64 + c * 4);
        }
    };

    prefetch(0);
    CP_COMMIT();

    for (int ck = 0; ck < NCHUNK; ck++) {
        if (ck + 1 < NCHUNK) {
            prefetch(ck + 1);
            CP_COMMIT();
            CP_WAIT1();
        } else {
            CP_WAIT0();
        }
        __syncthreads();

        const int buf = ck & 1;
        const unsigned kvb = sbase + buf * KVBUF;

        // ---- S = Q K^T (3-term) ----
        float sacc[8][4];
#pragma unroll
        for (int j = 0; j < 8; j++)
#pragma unroll
            for (int k = 0; k < 4; k++) sacc[j][k] = 0.0f;

#pragma unroll
        for (int kc = 0; kc < 8; kc++) {
            unsigned bH[4][4], bL[4][4];
            const unsigned slab = kvb + (kc >> 1) * 4096;
            const unsigned koff = (kc & 1) * 32 + bkp;
#pragma unroll
            for (int p = 0; p < 4; p++) {
                unsigned sw = sw64((p * 16 + brow) * 64 + koff);
                LDSM4(bH[p][0], bH[p][1], bH[p][2], bH[p][3], slab + sw);
                LDSM4(bL[p][0], bL[p][1], bL[p][2], bL[p][3], slab + 16384 + sw);
            }
#pragma unroll
            for (int j = 0; j < 8; j++) {
                const int p = j >> 1, h = (j & 1) * 2;
                MMA16816(sacc[j], qH[kc], bH[p][h], bH[p][h + 1]);
                MMA16816(sacc[j], qH[kc], bL[p][h], bL[p][h + 1]);
                MMA16816(sacc[j], qL[kc], bH[p][h], bH[p][h + 1]);
            }
        }

        // ---- bias add from smem ----
        {
            const char* bb = smem + SBIAS + buf * BIAS_BUF;
            const int r0 = w * 16 + g, r1 = r0 + 8;
#pragma unroll
            for (int j = 0; j < 8; j++) {
                float2 b0 = *reinterpret_cast<const float2*>(bb + r0 * BIAS_STRIDE + (j * 8 + 2 * t) * 4);
                float2 b1 = *reinterpret_cast<const float2*>(bb + r1 * BIAS_STRIDE + (j * 8 + 2 * t) * 4);
                sacc[j][0] += b0.x; sacc[j][1] += b0.y;
                sacc[j][2] += b1.x; sacc[j][3] += b1.y;
            }
        }

        // ---- online softmax ----
        float mx0 = -1e30f, mx1 = -1e30f;
#pragma unroll
        for (int j = 0; j < 8; j++) {
            mx0 = fmaxf(mx0, fmaxf(sacc[j][0], sacc[j][1]));
            mx1 = fmaxf(mx1, fmaxf(sacc[j][2], sacc[j][3]));
        }
        mx0 = fmaxf(mx0, __shfl_xor_sync(0xffffffffu, mx0, 1));
        mx0 = fmaxf(mx0, __shfl_xor_sync(0xffffffffu, mx0, 2));
        mx1 = fmaxf(mx1, __shfl_xor_sync(0xffffffffu, mx1, 1));
        mx1 = fmaxf(mx1, __shfl_xor_sync(0xffffffffu, mx1, 2));

        const float mn0 = fmaxf(m0r, mx0), mn1 = fmaxf(m1r, mx1);
        const float cor0 = __expf(m0r - mn0), cor1 = __expf(m1r - mn1);
        m0r = mn0; m1r = mn1;

        float sum0 = 0.0f, sum1 = 0.0f;
#pragma unroll
        for (int j = 0; j < 8; j++) {
            sacc[j][0] = __expf(sacc[j][0] - mn0);
            sacc[j][1] = __expf(sacc[j][1] - mn0);
            sacc[j][2] = __expf(sacc[j][2] - mn1);
            sacc[j][3] = __expf(sacc[j][3] - mn1);
            sum0 += sacc[j][0] + sacc[j][1];
            sum1 += sacc[j][2] + sacc[j][3];
        }
        sum0 += __shfl_xor_sync(0xffffffffu, sum0, 1);
        sum0 += __shfl_xor_sync(0xffffffffu, sum0, 2);
        sum1 += __shfl_xor_sync(0xffffffffu, sum1, 1);
        sum1 += __shfl_xor_sync(0xffffffffu, sum1, 2);
        l0r = l0r * cor0 + sum0;
        l1r = l1r * cor1 + sum1;

#pragma unroll
        for (int j = 0; j < 8; j++) {
            oacc[j][0] *= cor0; oacc[j][1] *= cor0;
            oacc[j][2] *= cor1; oacc[j][3] *= cor1;
        }

        // ---- PV: oacc += P @ V (3-term) ----
#pragma unroll
        for (int kk = 0; kk < 4; kk++) {
            unsigned pH[4], pL[4];
            split2(sacc[2 * kk][0],     sacc[2 * kk][1],     pH[0], pL[0]);
            split2(sacc[2 * kk][2],     sacc[2 * kk][3],     pH[1], pL[1]);
            split2(sacc[2 * kk + 1][0], sacc[2 * kk + 1][1], pH[2], pL[2]);
            split2(sacc[2 * kk + 1][2], sacc[2 * kk + 1][3], pH[3], pL[3]);

            unsigned vHf[4][4], vLf[4][4];
            const unsigned slab = kvb + 32768 + (kk >> 1) * 4096;
            const unsigned koff = (kk & 1) * 32 + bkp;
#pragma unroll
            for (int p = 0; p < 4; p++) {
                unsigned sw = sw64((p * 16 + brow) * 64 + koff);
                LDSM4(vHf[p][0], vHf[p][1], vHf[p][2], vHf[p][3], slab + sw);
                LDSM4(vLf[p][0], vLf[p][1], vLf[p][2], vLf[p][3], slab + 8192 + sw);
            }
#pragma unroll
            for (int j = 0; j < 8; j++) {
                const int p = j >> 1, h = (j & 1) * 2;
                MMA16816(oacc[j], pH, vHf[p][h], vHf[p][h + 1]);
                MMA16816(oacc[j], pH, vLf[p][h], vLf[p][h + 1]);
                MMA16816(oacc[j], pL, vHf[p][h], vHf[p][h + 1]);
            }
        }

        __syncthreads();   // done reading this buf before it is re-prefetched
    }

    // ---- epilogue: out = oacc / l, packed to g_vals ----
    const float inv0 = 1.0f / l0r, inv1 = 1.0f / l1r;
    const int b = bh >> 3, h = bh & 7;
    const long row0 = (long)(b * SQ + qw + g) * EMB + h * HD;
    const long row1 = (long)(b * SQ + qw + g + 8) * EMB + h * HD;
#pragma unroll
    for (int j = 0; j < 8; j++) {
        int col = j * 8 + 2 * t;
        *reinterpret_cast<uint2*>(&vals[row0 + col]) =
            make_uint2(packf(oacc[j][0] * inv0), packf(oacc[j][1] * inv0));
        *reinterpret_cast<uint2*>(&vals[row1 + col]) =
            make_uint2(packf(oacc[j][2] * inv1), packf(oacc[j][3] * inv1));
    }
}

// ------------------------------ launch -------------------------------------
template <typename Epi>
static void launch_gemm(dim3 grid, const unsigned* A, const unsigned* B, int K,
                        int lda, int ldb, long sA, long sB, Epi epi)
{
    gemm_hmma<Epi><<<grid, 256, 49152>>>(A, B, K, lda, ldb, sA, sB, epi);
}

extern "C" void kernel_launch(void* const* d_in, const int* in_sizes, int n_in,
                              void* d_out, int out_size)
{
    const float* x    = (const float*)d_in[0];
    const float* PE   = (const float*)d_in[1];
    const float* PE_r = (const float*)d_in[2];
    const float* Wqkv = (const float*)d_in[3];
    const float* UqUk = (const float*)d_in[4];
    const float* Wo   = (const float*)d_in[5];
    float* out = (float*)d_out;

    void* p;
    cudaGetSymbolAddress(&p, g_x2);   unsigned* x2  = (unsigned*)p;
    cudaGetSymbolAddress(&p, g_PE2);  unsigned* pe2 = (unsigned*)p;
    cudaGetSymbolAddress(&p, g_W2);   unsigned* w2  = (unsigned*)p;
    cudaGetSymbolAddress(&p, g_U2);   unsigned* u2  = (unsigned*)p;
    cudaGetSymbolAddress(&p, g_Wo2);  unsigned* wo2 = (unsigned*)p;
    cudaGetSymbolAddress(&p, g_Qcat); unsigned* Qc  = (unsigned*)p;
    cudaGetSymbolAddress(&p, g_KH);   char* KH = (char*)p;
    cudaGetSymbolAddress(&p, g_KL);   char* KL = (char*)p;
    cudaGetSymbolAddress(&p, g_VH);   char* VH = (char*)p;
    cudaGetSymbolAddress(&p, g_VL);   char* VL = (char*)p;
    cudaGetSymbolAddress(&p, g_vals); unsigned* Vl = (unsigned*)p;

    auto pk = [](const float* in, unsigned* outp, long n) {
        int n4 = (int)(n / 4);
        pack_kernel<<<(n4 + 255) / 256, 256>>>((const float4*)in, (uint4*)outp, n4);
    };
    pk(x,    x2,  (long)BB * SQ * EMB);
    pk(PE,   pe2, (long)BB * SQ * EMB);
    pk(Wqkv, w2,  (long)3 * EMB * EMB);
    pk(UqUk, u2,  (long)2 * EMB * EMB);
    pk(Wo,   wo2, (long)EMB * EMB);

    // 1) qkv projection (writes Q packed, K/V split images)
    launch_gemm(dim3(24, 64, 1), x2, w2, EMB, EMB, EMB, 0, 0, EpiQKV{});
    // 2) positional projection (writes Q packed cols 64.., K image dims 64..)
    launch_gemm(dim3(16, 64, 1), pe2, u2, EMB, EMB, EMB, 0, 0, EpiPE{});
    // 3) fused attention
    cudaFuncSetAttribute(flash_attn, cudaFuncAttributeMaxDynamicSharedMemorySize, 167936);
    flash_attn<<<dim3(SQ / 128, BB * HH), 256, 167936>>>(Qc, KH, KL, VH, VL, PE_r, Vl);
    // 4) out projection
    launch_gemm(dim3(8, 64, 1), Vl, wo2, EMB, EMB, EMB, 0, 0, EpiOut{out});
}

// round 8
// speedup vs baseline: 2.3549x; 1.2410x over previous
#include <cuda_runtime.h>
#include <cuda_bf16.h>
#include <cuda_fp16.h>
#include <cstdint>

// ---------------------------------------------------------------------------
// TUPE multihead attention.
//  Projections / out-proj: bf16 split-precision 3-term HMMA (unchanged).
//  Flash middle (fp16 asymmetric digits):
//    S  = (qh+ql) * kh      (Q 2-digit fp16, K 1-digit fp16)  -> 2 mma/step
//    PV = p * (vh+vl)       (P 1-digit fp16, V 2-digit fp16)  -> 2 mma/step
//  K/V stored as pre-split fp16 global images in smem slab layout (sw64),
//  loaded by pure cp.async, double-buffered.
// ---------------------------------------------------------------------------

static constexpr int BB  = 4;
static constexpr int HH  = 8;
static constexpr int SQ  = 2048;
static constexpr int EMB = 512;
static constexpr int HD  = 64;
static constexpr float QK_SCALE = 0.0883883476483184f; // 1/sqrt(2*64)

// ------------------------------ scratch ------------------------------------
__device__ __align__(16) unsigned g_x2  [(size_t)BB * SQ * EMB];
__device__ __align__(16) unsigned g_PE2 [(size_t)BB * SQ * EMB];
__device__ __align__(16) unsigned g_W2  [(size_t)3 * EMB * EMB];
__device__ __align__(16) unsigned g_U2  [(size_t)2 * EMB * EMB];
__device__ __align__(16) unsigned g_Wo2 [(size_t)EMB * EMB];
__device__ __align__(16) unsigned g_Qcat[(size_t)BB * HH * SQ * 128];      // u32 = fp16 hi|lo
// K image (1 digit): per (bh,ck): 16384 B = 4 slabs x (64 rows x 64 B), sw64
__device__ __align__(16) unsigned short g_KH[(size_t)BB * HH * SQ * 128];
// V images (2 digits): per (bh,ck): 8192 B = 2 slabs x 4096, sw64
__device__ __align__(16) unsigned short g_VH[(size_t)BB * HH * HD * SQ];
__device__ __align__(16) unsigned short g_VL[(size_t)BB * HH * HD * SQ];
__device__ __align__(16) unsigned g_vals[(size_t)BB * SQ * EMB];           // packed bf16 pair

// ------------------------------ helpers ------------------------------------
__device__ __forceinline__ unsigned smem_u32(const void* p) {
    unsigned a;
    asm("{ .reg .u64 t; cvta.to.shared.u64 t, %1; cvt.u32.u64 %0, t; }" : "=r"(a) : "l"(p));
    return a;
}
// bf16 hi/lo pack (projection operands + flash output)
__device__ __forceinline__ unsigned packf(float v) {
    __nv_bfloat16 hi = __float2bfloat16(v);
    float r = v - __bfloat162float(hi);
    __nv_bfloat16 lo = __float2bfloat16(r);
    return ((unsigned)__bfloat16_as_ushort(hi) << 16) | (unsigned)__bfloat16_as_ushort(lo);
}
__device__ __forceinline__ uint4 pack4(float4 v, float sc) {
    return make_uint4(packf(v.x * sc), packf(v.y * sc), packf(v.z * sc), packf(v.w * sc));
}
// fp16 hi/lo pack (Q storage)
__device__ __forceinline__ unsigned packh(float v) {
    __half hi = __float2half(v);
    __half lo = __float2half(v - __half2float(hi));
    return ((unsigned)__half_as_ushort(hi) << 16) | (unsigned)__half_as_ushort(lo);
}
__device__ __forceinline__ uint4 pack4h(float4 v, float sc) {
    return make_uint4(packh(v.x * sc), packh(v.y * sc), packh(v.z * sc), packh(v.w * sc));
}
__device__ __forceinline__ unsigned h2u(__half2 h) {
    return *reinterpret_cast<unsigned*>(&h);
}

__global__ void __launch_bounds__(256)
pack_kernel(const float4* __restrict__ in, uint4* __restrict__ out, int n4)
{
    int i = blockIdx.x * 256 + threadIdx.x;
    if (i < n4) out[i] = pack4(in[i], 1.0f);
}

#define LDSM4(r0, r1, r2, r3, a)                                              \
    asm volatile("ldmatrix.sync.aligned.m8n8.x4.shared.b16 {%0,%1,%2,%3}, [%4];" \
                 : "=r"(r0), "=r"(r1), "=r"(r2), "=r"(r3) : "r"(a))

#define MMA16816(c, a, b0, b1)                                                \
    asm volatile("mma.sync.aligned.m16n8k16.row.col.f32.bf16.bf16.f32 "       \
                 "{%0,%1,%2,%3}, {%4,%5,%6,%7}, {%8,%9}, {%0,%1,%2,%3};"      \
                 : "+f"((c)[0]), "+f"((c)[1]), "+f"((c)[2]), "+f"((c)[3])     \
                 : "r"((a)[0]), "r"((a)[1]), "r"((a)[2]), "r"((a)[3]),        \
                   "r"(b0), "r"(b1))

#define MMA16816H(c, a, b0, b1)                                               \
    asm volatile("mma.sync.aligned.m16n8k16.row.col.f32.f16.f16.f32 "         \
                 "{%0,%1,%2,%3}, {%4,%5,%6,%7}, {%8,%9}, {%0,%1,%2,%3};"      \
                 : "+f"((c)[0]), "+f"((c)[1]), "+f"((c)[2]), "+f"((c)[3])     \
                 : "r"((a)[0]), "r"((a)[1]), "r"((a)[2]), "r"((a)[3]),        \
                   "r"(b0), "r"(b1))

#define CP_ASYNC16(dst, src) \
    asm volatile("cp.async.cg.shared.global [%0], [%1], 16;" :: "r"(dst), "l"(src))
#define CP_COMMIT() asm volatile("cp.async.commit_group;" ::: "memory")
#define CP_WAIT0()  asm volatile("cp.async.wait_group 0;" ::: "memory")
#define CP_WAIT1()  asm volatile("cp.async.wait_group 1;" ::: "memory")

__device__ __forceinline__ unsigned sw64(unsigned off)  { return off ^ ((off >> 3) & 0x30); }

// ------------------------------ GEMM (projections / out) -------------------
template <typename Epi>
__global__ void __launch_bounds__(256, 2)
gemm_hmma(const unsigned* __restrict__ A, const unsigned* __restrict__ B,
          int K, int lda, int ldb, long sA, long sB, Epi epi)
{
    extern __shared__ __align__(1024) char smem[];
    constexpr int SA_LO = 8192, SB_HI = 16384, SB_LO = 20480, STAGE = 24576;

    const int tid = threadIdx.x;
    const int l   = tid & 31;
    const int w   = tid >> 5;
    const int wm  = w & 3;
    const int wn  = w >> 2;
    const int m0  = wm * 32;
    const int n0  = wn * 32;
    const int bz  = blockIdx.z;
    const unsigned sbase = smem_u32(smem);

    const unsigned* Ab = A + bz * sA + (long)blockIdx.y * 128 * lda;
    const unsigned* Bb = B + bz * sB + (long)blockIdx.x * 64 * ldb;

    float acc[2][4][4];
#pragma unroll
    for (int i = 0; i < 2; i++)
#pragma unroll
        for (int j = 0; j < 4; j++)
#pragma unroll
            for (int k = 0; k < 4; k++) acc[i][j][k] = 0.0f;

    const int arow = (l & 7) + ((l >> 3) & 1) * 8;
    const int akp  = ((l >> 4) & 1) * 16;
    const int brow = (l & 7) + ((l >> 4) & 1) * 8;
    const int bkp  = ((l >> 3) & 1) * 16;

    uint4 ra[4], rb[2];
    const int nChunks = K >> 5;

    auto load_global = [&](int c) {
#pragma unroll
        for (int it = 0; it < 4; it++) {
            int idx = tid + it * 256;
            int r = idx >> 3, q = idx & 7;
            ra[it] = *reinterpret_cast<const uint4*>(Ab + (long)r * lda + c * 32 + q * 4);
        }
#pragma unroll
        for (int it = 0; it < 2; it++) {
            int idx = tid + it * 256;
            int r = idx >> 3, q = idx & 7;
            rb[it] = *reinterpret_cast<const uint4*>(Bb + (long)r * ldb + c * 32 + q * 4);
        }
    };
    auto store_stage = [&](char* buf) {
#pragma unroll
        for (int it = 0; it < 4; it++) {
            int idx = tid + it * 256;
            int r = idx >> 3, q = idx & 7;
            unsigned sw = sw64(r * 64 + q * 8);
            uint4 wv = ra[it];
            *reinterpret_cast<uint2*>(buf + sw) =
                make_uint2(__byte_perm(wv.x, wv.y, 0x7632), __byte_perm(wv.z, wv.w, 0x7632));
            *reinterpret_cast<uint2*>(buf + SA_LO + sw) =
                make_uint2(__byte_perm(wv.x, wv.y, 0x5410), __byte_perm(wv.z, wv.w, 0x5410));
        }
#pragma unroll
        for (int it = 0; it < 2; it++) {
            int idx = tid + it * 256;
            int r = idx >> 3, q = idx & 7;
            unsigned sw = sw64(r * 64 + q * 8);
            uint4 wv = rb[it];
            *reinterpret_cast<uint2*>(buf + SB_HI + sw) =
                make_uint2(__byte_perm(wv.x, wv.y, 0x7632), __byte_perm(wv.z, wv.w, 0x7632));
            *reinterpret_cast<uint2*>(buf + SB_LO + sw) =
                make_uint2(__byte_perm(wv.x, wv.y, 0x5410), __byte_perm(wv.z, wv.w, 0x5410));
        }
    };

    load_global(0);
    store_stage(smem);
    __syncthreads();

    for (int c = 0; c < nChunks; c++) {
        const bool more = (c + 1) < nChunks;
        if (more) load_global(c + 1);

        const unsigned stage = sbase + (c & 1) * STAGE;
#pragma unroll
        for (int ks = 0; ks < 2; ks++) {
            unsigned aH[2][4], aL[2][4], bH[2][4], bL[2][4];
#pragma unroll
            for (int i = 0; i < 2; i++) {
                unsigned off = (m0 + i * 16 + arow) * 64 + ks * 32 + akp;
                unsigned sw = sw64(off);
                LDSM4(aH[i][0], aH[i][1], aH[i][2], aH[i][3], stage + sw);
                LDSM4(aL[i][0], aL[i][1], aL[i][2], aL[i][3], stage + SA_LO + sw);
            }
#pragma unroll
            for (int p = 0; p < 2; p++) {
                unsigned off = (n0 + p * 16 + brow) * 64 + ks * 32 + bkp;
                unsigned sw = sw64(off);
                LDSM4(bH[p][0], bH[p][1], bH[p][2], bH[p][3], stage + SB_HI + sw);
                LDSM4(bL[p][0], bL[p][1], bL[p][2], bL[p][3], stage + SB_LO + sw);
            }
#pragma unroll
            for (int i = 0; i < 2; i++)
#pragma unroll
                for (int j = 0; j < 4; j++) {
                    const int p = j >> 1, h = (j & 1) * 2;
                    MMA16816(acc[i][j], aH[i], bH[p][h], bH[p][h + 1]);
                    MMA16816(acc[i][j], aH[i], bL[p][h], bL[p][h + 1]);
                    MMA16816(acc[i][j], aL[i], bH[p][h], bH[p][h + 1]);
                }
        }

        if (more) store_stage(smem + ((c + 1) & 1) * STAGE);
        __syncthreads();
    }

    float* C = reinterpret_cast<float*>(smem);   // [128][68]
#pragma unroll
    for (int i = 0; i < 2; i++)
#pragma unroll
        for (int j = 0; j < 4; j++) {
            int r0  = m0 + i * 16 + (l >> 2);
            int col = n0 + j * 8 + (l & 3) * 2;
            *reinterpret_cast<float2*>(C + r0 * 68 + col)       = make_float2(acc[i][j][0], acc[i][j][1]);
            *reinterpret_cast<float2*>(C + (r0 + 8) * 68 + col) = make_float2(acc[i][j][2], acc[i][j][3]);
        }
    __syncthreads();

    {
        int r = tid >> 1, seg = (tid & 1) << 5;
        int m  = blockIdx.y * 128 + r;
        int nb = blockIdx.x * 64 + seg;
        const float* Crow = C + r * 68 + seg;
#pragma unroll
        for (int i = 0; i < 8; i++) {
            float4 v = *reinterpret_cast<const float4*>(Crow + i * 4);
            epi(bz, m, nb + i * 4, v);
        }
    }
}

// ------------------------------ epilogues ----------------------------------
struct EpiQKV {   // m in [0,8192), n in [0,1536)
    __device__ void operator()(int, int m, int n, float4 v) const {
        int b = m >> 11, s = m & (SQ - 1);
        int h = n / 192, r = n - h * 192;
        int bh = b * HH + h;
        if (r < HD) {
            long row = ((long)bh * SQ + s);
            *reinterpret_cast<uint4*>(&g_Qcat[row * 128 + r]) = pack4h(v, QK_SCALE);
        } else if (r < 2 * HD) {
            // K word part (single fp16 digit): dims d0..d0+3
            int d0 = r - HD;
            int ck = s >> 6, rr = s & 63;
            long base = ((long)bh * 32 + ck) * 16384;
            unsigned off = (unsigned)((d0 >> 5) * 4096) + sw64(rr * 64 + (d0 & 31) * 2);
            __half2 p0 = __floats2half2_rn(v.x, v.y);
            __half2 p1 = __floats2half2_rn(v.z, v.w);
            *reinterpret_cast<uint2*>(reinterpret_cast<char*>(g_KH) + base + off) =
                make_uint2(h2u(p0), h2u(p1));
        } else {
            // V (two fp16 digits): dims d..d+3 for key s
            int d = r - 2 * HD;
            int ck = s >> 6, kc = s & 63;
            long base = ((long)bh * 32 + ck) * 8192 + (kc >> 5) * 4096;
            int kb = (kc & 31) * 2;
#pragma unroll
            for (int i = 0; i < 4; i++) {
                float val = (&v.x)[i];
                __half hb = __float2half(val);
                __half lb = __float2half(val - __half2float(hb));
                unsigned off2 = sw64((d + i) * 64 + kb);
                *reinterpret_cast<__half*>(reinterpret_cast<char*>(g_VH) + base + off2) = hb;
                *reinterpret_cast<__half*>(reinterpret_cast<char*>(g_VL) + base + off2) = lb;
            }
        }
    }
};
struct EpiPE {    // n in [0,1024)
    __device__ void operator()(int, int m, int n, float4 v) const {
        int b = m >> 11, s = m & (SQ - 1);
        int h = n >> 7, r = n & 127;
        int bh = b * HH + h;
        if (r < HD) {
            long row = ((long)bh * SQ + s);
            *reinterpret_cast<uint4*>(&g_Qcat[row * 128 + HD + r]) = pack4h(v, QK_SCALE);
        } else {
            int d0 = r;   // positional K dims [64,128)
            int ck = s >> 6, rr = s & 63;
            long base = ((long)bh * 32 + ck) * 16384;
            unsigned off = (unsigned)((d0 >> 5) * 4096) + sw64(rr * 64 + (d0 & 31) * 2);
            __half2 p0 = __floats2half2_rn(v.x, v.y);
            __half2 p1 = __floats2half2_rn(v.z, v.w);
            *reinterpret_cast<uint2*>(reinterpret_cast<char*>(g_KH) + base + off) =
                make_uint2(h2u(p0), h2u(p1));
        }
    }
};
struct EpiOut {
    float* out;
    __device__ void operator()(int, int m, int n, float4 v) const {
        *reinterpret_cast<float4*>(&out[(long)m * EMB + n]) = v;
    }
};

// ------------------------------ flash attention ----------------------------
// One CTA = 128 q-rows of one (b,h). 8 warps x 16 q-rows. KV chunk = 64 keys.
// smem buffer (32KB x2): KH 16K | VH 8K | VL 8K; bias double-buffered.
__global__ void __launch_bounds__(256)
flash_attn(const unsigned* __restrict__ Qc, const char* __restrict__ KH,
           const char* __restrict__ VH, const char* __restrict__ VL,
           const float* __restrict__ PE_r, unsigned* __restrict__ vals)
{
    extern __shared__ __align__(1024) char smem[];
    constexpr int KVBUF = 32768;                       // KH 16K | VH 8K | VL 8K
    constexpr int SBIAS = 65536, BIAS_STRIDE = 272, BIAS_BUF = 34816;
    constexpr int NCHUNK = SQ / 64;   // 32

    const int tid = threadIdx.x;
    const int l = tid & 31;
    const int w = tid >> 5;
    const int g = l >> 2;
    const int t = l & 3;
    const int bh = blockIdx.y;
    const int q0 = blockIdx.x * 128;
    const int qw = q0 + w * 16;
    const unsigned sbase = smem_u32(smem);

    const unsigned* Qb = Qc + ((long)bh * SQ + qw) * 128;
    const char* KHb = KH + (long)bh * 32 * 16384;
    const char* VHb = VH + (long)bh * 32 * 8192;
    const char* VLb = VL + (long)bh * 32 * 8192;
    const float* Pb = PE_r + ((long)(bh & 7) * SQ + q0) * SQ;

    // ---- Q A-frags in registers (8 k16 steps, fp16 hi/lo) ----
    unsigned qH[8][4], qL[8][4];
#pragma unroll
    for (int kc = 0; kc < 8; kc++) {
        uint2 e00 = *reinterpret_cast<const uint2*>(Qb + (long)g * 128 + kc * 16 + 2 * t);
        uint2 e10 = *reinterpret_cast<const uint2*>(Qb + (long)(g + 8) * 128 + kc * 16 + 2 * t);
        uint2 e01 = *reinterpret_cast<const uint2*>(Qb + (long)g * 128 + kc * 16 + 8 + 2 * t);
        uint2 e11 = *reinterpret_cast<const uint2*>(Qb + (long)(g + 8) * 128 + kc * 16 + 8 + 2 * t);
        qH[kc][0] = __byte_perm(e00.x, e00.y, 0x7632); qL[kc][0] = __byte_perm(e00.x, e00.y, 0x5410);
        qH[kc][1] = __byte_perm(e10.x, e10.y, 0x7632); qL[kc][1] = __byte_perm(e10.x, e10.y, 0x5410);
        qH[kc][2] = __byte_perm(e01.x, e01.y, 0x7632); qL[kc][2] = __byte_perm(e01.x, e01.y, 0x5410);
        qH[kc][3] = __byte_perm(e11.x, e11.y, 0x7632); qL[kc][3] = __byte_perm(e11.x, e11.y, 0x5410);
    }

    float oacc[8][4];
#pragma unroll
    for (int j = 0; j < 8; j++)
#pragma unroll
        for (int k = 0; k < 4; k++) oacc[j][k] = 0.0f;
    float m0r = -1e30f, m1r = -1e30f, l0r = 0.0f, l1r = 0.0f;

    const int brow = (l & 7) + ((l >> 4) & 1) * 8;
    const int bkp  = ((l >> 3) & 1) * 16;

    auto prefetch = [&](int ck) {
        const int buf = ck & 1;
        const unsigned sb = sbase + buf * KVBUF;
        const char* kh = KHb + (long)ck * 16384;
        const char* vh = VHb + (long)ck * 8192;
        const char* vlo = VLb + (long)ck * 8192;
#pragma unroll
        for (int it = 0; it < 4; it++) {
            int o = (tid + it * 256) * 16;
            CP_ASYNC16(sb + o, kh + o);
        }
#pragma unroll
        for (int it = 0; it < 2; it++) {
            int o = (tid + it * 256) * 16;
            CP_ASYNC16(sb + 16384 + o, vh + o);
            CP_ASYNC16(sb + 24576 + o, vlo + o);
        }
        const unsigned bb = sbase + SBIAS + buf * BIAS_BUF;
#pragma unroll
        for (int it = 0; it < 8; it++) {
            int idx = tid + it * 256;
            int r = idx >> 4, c = idx & 15;
            CP_ASYNC16(bb + r * BIAS_STRIDE + c * 16,
                       Pb + (long)r * SQ + ck * 64 + c * 4);
        }
    };

    prefetch(0);
    CP_COMMIT();

    for (int ck = 0; ck < NCHUNK; ck++) {
        if (ck + 1 < NCHUNK) {
            prefetch(ck + 1);
            CP_COMMIT();
            CP_WAIT1();
        } else {
            CP_WAIT0();
        }
        __syncthreads();

        const int buf = ck & 1;
        const unsigned kvb = sbase + buf * KVBUF;

        // ---- S = (qh+ql) * kh : 2 mma per step ----
        float sacc[8][4];
#pragma unroll
        for (int j = 0; j < 8; j++)
#pragma unroll
            for (int k = 0; k < 4; k++) sacc[j][k] = 0.0f;

#pragma unroll
        for (int kc = 0; kc < 8; kc++) {
            unsigned bH[4][4];
            const unsigned slab = kvb + (kc >> 1) * 4096;
            const unsigned koff = (kc & 1) * 32 + bkp;
#pragma unroll
            for (int p = 0; p < 4; p++) {
                unsigned sw = sw64((p * 16 + brow) * 64 + koff);
                LDSM4(bH[p][0], bH[p][1], bH[p][2], bH[p][3], slab + sw);
            }
#pragma unroll
            for (int j = 0; j < 8; j++) {
                const int p = j >> 1, h = (j & 1) * 2;
                MMA16816H(sacc[j], qH[kc], bH[p][h], bH[p][h + 1]);
                MMA16816H(sacc[j], qL[kc], bH[p][h], bH[p][h + 1]);
            }
        }

        // ---- bias add from smem ----
        {
            const char* bb = smem + SBIAS + buf * BIAS_BUF;
            const int r0 = w * 16 + g, r1 = r0 + 8;
#pragma unroll
            for (int j = 0; j < 8; j++) {
                float2 b0 = *reinterpret_cast<const float2*>(bb + r0 * BIAS_STRIDE + (j * 8 + 2 * t) * 4);
                float2 b1 = *reinterpret_cast<const float2*>(bb + r1 * BIAS_STRIDE + (j * 8 + 2 * t) * 4);
                sacc[j][0] += b0.x; sacc[j][1] += b0.y;
                sacc[j][2] += b1.x; sacc[j][3] += b1.y;
            }
        }

        // ---- online softmax ----
        float mx0 = -1e30f, mx1 = -1e30f;
#pragma unroll
        for (int j = 0; j < 8; j++) {
            mx0 = fmaxf(mx0, fmaxf(sacc[j][0], sacc[j][1]));
            mx1 = fmaxf(mx1, fmaxf(sacc[j][2], sacc[j][3]));
        }
        mx0 = fmaxf(mx0, __shfl_xor_sync(0xffffffffu, mx0, 1));
        mx0 = fmaxf(mx0, __shfl_xor_sync(0xffffffffu, mx0, 2));
        mx1 = fmaxf(mx1, __shfl_xor_sync(0xffffffffu, mx1, 1));
        mx1 = fmaxf(mx1, __shfl_xor_sync(0xffffffffu, mx1, 2));

        const float mn0 = fmaxf(m0r, mx0), mn1 = fmaxf(m1r, mx1);
        const float cor0 = __expf(m0r - mn0), cor1 = __expf(m1r - mn1);
        m0r = mn0; m1r = mn1;

        float sum0 = 0.0f, sum1 = 0.0f;
#pragma unroll
        for (int j = 0; j < 8; j++) {
            sacc[j][0] = __expf(sacc[j][0] - mn0);
            sacc[j][1] = __expf(sacc[j][1] - mn0);
            sacc[j][2] = __expf(sacc[j][2] - mn1);
            sacc[j][3] = __expf(sacc[j][3] - mn1);
            sum0 += sacc[j][0] + sacc[j][1];
            sum1 += sacc[j][2] + sacc[j][3];
        }
        sum0 += __shfl_xor_sync(0xffffffffu, sum0, 1);
        sum0 += __shfl_xor_sync(0xffffffffu, sum0, 2);
        sum1 += __shfl_xor_sync(0xffffffffu, sum1, 1);
        sum1 += __shfl_xor_sync(0xffffffffu, sum1, 2);
        l0r = l0r * cor0 + sum0;
        l1r = l1r * cor1 + sum1;

#pragma unroll
        for (int j = 0; j < 8; j++) {
            oacc[j][0] *= cor0; oacc[j][1] *= cor0;
            oacc[j][2] *= cor1; oacc[j][3] *= cor1;
        }

        // ---- PV: oacc += p * (vh + vl), P single fp16 digit ----
#pragma unroll
        for (int kk = 0; kk < 4; kk++) {
            unsigned pH[4];
            pH[0] = h2u(__floats2half2_rn(sacc[2 * kk][0],     sacc[2 * kk][1]));
            pH[1] = h2u(__floats2half2_rn(sacc[2 * kk][2],     sacc[2 * kk][3]));
            pH[2] = h2u(__floats2half2_rn(sacc[2 * kk + 1][0], sacc[2 * kk + 1][1]));
            pH[3] = h2u(__floats2half2_rn(sacc[2 * kk + 1][2], sacc[2 * kk + 1][3]));

            unsigned vHf[4][4], vLf[4][4];
            const unsigned slab = kvb + 16384 + (kk >> 1) * 4096;
            const unsigned koff = (kk & 1) * 32 + bkp;
#pragma unroll
            for (int p = 0; p < 4; p++) {
                unsigned sw = sw64((p * 16 + brow) * 64 + koff);
                LDSM4(vHf[p][0], vHf[p][1], vHf[p][2], vHf[p][3], slab + sw);
                LDSM4(vLf[p][0], vLf[p][1], vLf[p][2], vLf[p][3], slab + 8192 + sw);
            }
#pragma unroll
            for (int j = 0; j < 8; j++) {
                const int p = j >> 1, h = (j & 1) * 2;
                MMA16816H(oacc[j], pH, vHf[p][h], vHf[p][h + 1]);
                MMA16816H(oacc[j], pH, vLf[p][h], vLf[p][h + 1]);
            }
        }

        __syncthreads();   // done reading this buf before it is re-prefetched
    }

    // ---- epilogue: out = oacc / l, packed (bf16 pair) to g_vals ----
    const float inv0 = 1.0f / l0r, inv1 = 1.0f / l1r;
    const int b = bh >> 3, h = bh & 7;
    const long row0 = (long)(b * SQ + qw + g) * EMB + h * HD;
    const long row1 = (long)(b * SQ + qw + g + 8) * EMB + h * HD;
#pragma unroll
    for (int j = 0; j < 8; j++) {
        int col = j * 8 + 2 * t;
        *reinterpret_cast<uint2*>(&vals[row0 + col]) =
            make_uint2(packf(oacc[j][0] * inv0), packf(oacc[j][1] * inv0));
        *reinterpret_cast<uint2*>(&vals[row1 + col]) =
            make_uint2(packf(oacc[j][2] * inv1), packf(oacc[j][3] * inv1));
    }
}

// ------------------------------ launch -------------------------------------
template <typename Epi>
static void launch_gemm(dim3 grid, const unsigned* A, const unsigned* B, int K,
                        int lda, int ldb, long sA, long sB, Epi epi)
{
    gemm_hmma<Epi><<<grid, 256, 49152>>>(A, B, K, lda, ldb, sA, sB, epi);
}

extern "C" void kernel_launch(void* const* d_in, const int* in_sizes, int n_in,
                              void* d_out, int out_size)
{
    const float* x    = (const float*)d_in[0];
    const float* PE   = (const float*)d_in[1];
    const float* PE_r = (const float*)d_in[2];
    const float* Wqkv = (const float*)d_in[3];
    const float* UqUk = (const float*)d_in[4];
    const float* Wo   = (const float*)d_in[5];
    float* out = (float*)d_out;

    void* p;
    cudaGetSymbolAddress(&p, g_x2);   unsigned* x2  = (unsigned*)p;
    cudaGetSymbolAddress(&p, g_PE2);  unsigned* pe2 = (unsigned*)p;
    cudaGetSymbolAddress(&p, g_W2);   unsigned* w2  = (unsigned*)p;
    cudaGetSymbolAddress(&p, g_U2);   unsigned* u2  = (unsigned*)p;
    cudaGetSymbolAddress(&p, g_Wo2);  unsigned* wo2 = (unsigned*)p;
    cudaGetSymbolAddress(&p, g_Qcat); unsigned* Qc  = (unsigned*)p;
    cudaGetSymbolAddress(&p, g_KH);   char* KH = (char*)p;
    cudaGetSymbolAddress(&p, g_VH);   char* VH = (char*)p;
    cudaGetSymbolAddress(&p, g_VL);   char* VL = (char*)p;
    cudaGetSymbolAddress(&p, g_vals); unsigned* Vl = (unsigned*)p;

    auto pk = [](const float* in, unsigned* outp, long n) {
        int n4 = (int)(n / 4);
        pack_kernel<<<(n4 + 255) / 256, 256>>>((const float4*)in, (uint4*)outp, n4);
    };
    pk(x,    x2,  (long)BB * SQ * EMB);
    pk(PE,   pe2, (long)BB * SQ * EMB);
    pk(Wqkv, w2,  (long)3 * EMB * EMB);
    pk(UqUk, u2,  (long)2 * EMB * EMB);
    pk(Wo,   wo2, (long)EMB * EMB);

    // 1) qkv projection (writes Q fp16-packed, K/V fp16 images)
    launch_gemm(dim3(24, 64, 1), x2, w2, EMB, EMB, EMB, 0, 0, EpiQKV{});
    // 2) positional projection
    launch_gemm(dim3(16, 64, 1), pe2, u2, EMB, EMB, EMB, 0, 0, EpiPE{});
    // 3) fused attention
    cudaFuncSetAttribute(flash_attn, cudaFuncAttributeMaxDynamicSharedMemorySize, 135168);
    flash_attn<<<dim3(SQ / 128, BB * HH), 256, 135168>>>(Qc, KH, VH, VL, PE_r, Vl);
    // 4) out projection
    launch_gemm(dim3(8, 64, 1), Vl, wo2, EMB, EMB, EMB, 0, 0, EpiOut{out});
}

// round 9
// speedup vs baseline: 2.5281x; 1.0735x over previous
#include <cuda_runtime.h>
#include <cuda_bf16.h>
#include <cuda_fp16.h>
#include <cstdint>

// ---------------------------------------------------------------------------
// TUPE multihead attention — fp16 asymmetric-digit HMMA everywhere.
//  All GEMMs: D += (Ahi + Alo) * Bhi   (A 2-digit fp16, B 1-digit fp16)
//   - projections / out-proj: A = activations (x, PE, vals), B = weights
//   - flash S: A = Q (2-digit), B = K (1-digit)
//   - flash PV: A = P (1-digit, exact-enough post-softmax), B = V (2-digit)
//  K/V stored as pre-split fp16 global images in smem slab layout (sw64),
//  loaded by pure cp.async, double-buffered.
// ---------------------------------------------------------------------------

static constexpr int BB  = 4;
static constexpr int HH  = 8;
static constexpr int SQ  = 2048;
static constexpr int EMB = 512;
static constexpr int HD  = 64;
static constexpr float QK_SCALE = 0.0883883476483184f; // 1/sqrt(2*64)

// ------------------------------ scratch ------------------------------------
__device__ __align__(16) unsigned g_x2  [(size_t)BB * SQ * EMB];         // fp16 hi|lo
__device__ __align__(16) unsigned g_PE2 [(size_t)BB * SQ * EMB];         // fp16 hi|lo
__device__ __align__(16) unsigned short g_W2 [(size_t)3 * EMB * EMB];    // fp16 single
__device__ __align__(16) unsigned short g_U2 [(size_t)2 * EMB * EMB];    // fp16 single
__device__ __align__(16) unsigned short g_Wo2[(size_t)EMB * EMB];        // fp16 single
__device__ __align__(16) unsigned g_Qcat[(size_t)BB * HH * SQ * 128];    // fp16 hi|lo
// K image (1 digit): per (bh,ck): 16384 B = 4 slabs x (64 rows x 64 B), sw64
__device__ __align__(16) unsigned short g_KH[(size_t)BB * HH * SQ * 128];
// V images (2 digits): per (bh,ck): 8192 B = 2 slabs x 4096, sw64
__device__ __align__(16) unsigned short g_VH[(size_t)BB * HH * HD * SQ];
__device__ __align__(16) unsigned short g_VL[(size_t)BB * HH * HD * SQ];
__device__ __align__(16) unsigned g_vals[(size_t)BB * SQ * EMB];         // fp16 hi|lo

// ------------------------------ helpers ------------------------------------
__device__ __forceinline__ unsigned smem_u32(const void* p) {
    unsigned a;
    asm("{ .reg .u64 t; cvta.to.shared.u64 t, %1; cvt.u32.u64 %0, t; }" : "=r"(a) : "l"(p));
    return a;
}
// fp16 hi/lo pack
__device__ __forceinline__ unsigned packh(float v) {
    __half hi = __float2half(v);
    __half lo = __float2half(v - __half2float(hi));
    return ((unsigned)__half_as_ushort(hi) << 16) | (unsigned)__half_as_ushort(lo);
}
__device__ __forceinline__ uint4 pack4h(float4 v, float sc) {
    return make_uint4(packh(v.x * sc), packh(v.y * sc), packh(v.z * sc), packh(v.w * sc));
}
__device__ __forceinline__ unsigned h2u(__half2 h) {
    return *reinterpret_cast<unsigned*>(&h);
}

// activations: f32 -> fp16 hi|lo u32
__global__ void __launch_bounds__(256)
pack_act_kernel(const float4* __restrict__ in, uint4* __restrict__ out, int n4)
{
    int i = blockIdx.x * 256 + threadIdx.x;
    if (i < n4) out[i] = pack4h(in[i], 1.0f);
}
// weights: f32 -> fp16 single digit
__global__ void __launch_bounds__(256)
pack_wt_kernel(const float4* __restrict__ in, uint2* __restrict__ out, int n4)
{
    int i = blockIdx.x * 256 + threadIdx.x;
    if (i < n4) {
        float4 v = in[i];
        out[i] = make_uint2(h2u(__floats2half2_rn(v.x, v.y)),
                            h2u(__floats2half2_rn(v.z, v.w)));
    }
}

#define LDSM4(r0, r1, r2, r3, a)                                              \
    asm volatile("ldmatrix.sync.aligned.m8n8.x4.shared.b16 {%0,%1,%2,%3}, [%4];" \
                 : "=r"(r0), "=r"(r1), "=r"(r2), "=r"(r3) : "r"(a))

#define MMA16816H(c, a, b0, b1)                                               \
    asm volatile("mma.sync.aligned.m16n8k16.row.col.f32.f16.f16.f32 "         \
                 "{%0,%1,%2,%3}, {%4,%5,%6,%7}, {%8,%9}, {%0,%1,%2,%3};"      \
                 : "+f"((c)[0]), "+f"((c)[1]), "+f"((c)[2]), "+f"((c)[3])     \
                 : "r"((a)[0]), "r"((a)[1]), "r"((a)[2]), "r"((a)[3]),        \
                   "r"(b0), "r"(b1))

#define CP_ASYNC16(dst, src) \
    asm volatile("cp.async.cg.shared.global [%0], [%1], 16;" :: "r"(dst), "l"(src))
#define CP_COMMIT() asm volatile("cp.async.commit_group;" ::: "memory")
#define CP_WAIT0()  asm volatile("cp.async.wait_group 0;" ::: "memory")
#define CP_WAIT1()  asm volatile("cp.async.wait_group 1;" ::: "memory")

__device__ __forceinline__ unsigned sw64(unsigned off)  { return off ^ ((off >> 3) & 0x30); }

// ------------------------------ GEMM (projections / out) -------------------
// C[128 x 64]; A fp16 hi|lo u32 [M,K]; B fp16 single [N,K]; K mult of 32.
// Stage (20KB): Ahi[128x32]@0, Alo@8192, Bh[64x32]@16384.
template <typename Epi>
__global__ void __launch_bounds__(256, 2)
gemm_fp16a(const unsigned* __restrict__ A, const unsigned short* __restrict__ B,
           int K, int lda, int ldb, long sA, long sB, Epi epi)
{
    extern __shared__ __align__(1024) char smem[];
    constexpr int SA_LO = 8192, SB = 16384, STAGE = 20480;

    const int tid = threadIdx.x;
    const int l   = tid & 31;
    const int w   = tid >> 5;
    const int wm  = w & 3;
    const int wn  = w >> 2;
    const int m0  = wm * 32;
    const int n0  = wn * 32;
    const int bz  = blockIdx.z;
    const unsigned sbase = smem_u32(smem);

    const unsigned* Ab = A + bz * sA + (long)blockIdx.y * 128 * lda;
    const unsigned short* Bb = B + bz * sB + (long)blockIdx.x * 64 * ldb;

    float acc[2][4][4];
#pragma unroll
    for (int i = 0; i < 2; i++)
#pragma unroll
        for (int j = 0; j < 4; j++)
#pragma unroll
            for (int k = 0; k < 4; k++) acc[i][j][k] = 0.0f;

    const int arow = (l & 7) + ((l >> 3) & 1) * 8;
    const int akp  = ((l >> 4) & 1) * 16;
    const int brow = (l & 7) + ((l >> 4) & 1) * 8;
    const int bkp  = ((l >> 3) & 1) * 16;

    uint4 ra[4], rb;
    const int nChunks = K >> 5;

    auto load_global = [&](int c) {
#pragma unroll
        for (int it = 0; it < 4; it++) {
            int idx = tid + it * 256;
            int r = idx >> 3, q = idx & 7;
            ra[it] = *reinterpret_cast<const uint4*>(Ab + (long)r * lda + c * 32 + q * 4);
        }
        {
            int r = tid >> 2, q = tid & 3;
            rb = *reinterpret_cast<const uint4*>(Bb + (long)r * ldb + c * 32 + q * 8);
        }
    };
    auto store_stage = [&](char* buf) {
#pragma unroll
        for (int it = 0; it < 4; it++) {
            int idx = tid + it * 256;
            int r = idx >> 3, q = idx & 7;
            unsigned sw = sw64(r * 64 + q * 8);
            uint4 wv = ra[it];
            *reinterpret_cast<uint2*>(buf + sw) =
                make_uint2(__byte_perm(wv.x, wv.y, 0x7632), __byte_perm(wv.z, wv.w, 0x7632));
            *reinterpret_cast<uint2*>(buf + SA_LO + sw) =
                make_uint2(__byte_perm(wv.x, wv.y, 0x5410), __byte_perm(wv.z, wv.w, 0x5410));
        }
        {
            int r = tid >> 2, q = tid & 3;
            *reinterpret_cast<uint4*>(buf + SB + sw64(r * 64 + q * 16)) = rb;
        }
    };

    load_global(0);
    store_stage(smem);
    __syncthreads();

    for (int c = 0; c < nChunks; c++) {
        const bool more = (c + 1) < nChunks;
        if (more) load_global(c + 1);

        const unsigned stage = sbase + (c & 1) * STAGE;
#pragma unroll
        for (int ks = 0; ks < 2; ks++) {
            unsigned aH[2][4], aL[2][4], bH[2][4];
#pragma unroll
            for (int i = 0; i < 2; i++) {
                unsigned off = (m0 + i * 16 + arow) * 64 + ks * 32 + akp;
                unsigned sw = sw64(off);
                LDSM4(aH[i][0], aH[i][1], aH[i][2], aH[i][3], stage + sw);
                LDSM4(aL[i][0], aL[i][1], aL[i][2], aL[i][3], stage + SA_LO + sw);
            }
#pragma unroll
            for (int p = 0; p < 2; p++) {
                unsigned off = (n0 + p * 16 + brow) * 64 + ks * 32 + bkp;
                unsigned sw = sw64(off);
                LDSM4(bH[p][0], bH[p][1], bH[p][2], bH[p][3], stage + SB + sw);
            }
#pragma unroll
            for (int i = 0; i < 2; i++)
#pragma unroll
                for (int j = 0; j < 4; j++) {
                    const int p = j >> 1, h = (j & 1) * 2;
                    MMA16816H(acc[i][j], aH[i], bH[p][h], bH[p][h + 1]);
                    MMA16816H(acc[i][j], aL[i], bH[p][h], bH[p][h + 1]);
                }
        }

        if (more) store_stage(smem + ((c + 1) & 1) * STAGE);
        __syncthreads();
    }

    float* C = reinterpret_cast<float*>(smem);   // [128][68]
#pragma unroll
    for (int i = 0; i < 2; i++)
#pragma unroll
        for (int j = 0; j < 4; j++) {
            int r0  = m0 + i * 16 + (l >> 2);
            int col = n0 + j * 8 + (l & 3) * 2;
            *reinterpret_cast<float2*>(C + r0 * 68 + col)       = make_float2(acc[i][j][0], acc[i][j][1]);
            *reinterpret_cast<float2*>(C + (r0 + 8) * 68 + col) = make_float2(acc[i][j][2], acc[i][j][3]);
        }
    __syncthreads();

    {
        int r = tid >> 1, seg = (tid & 1) << 5;
        int m  = blockIdx.y * 128 + r;
        int nb = blockIdx.x * 64 + seg;
        const float* Crow = C + r * 68 + seg;
#pragma unroll
        for (int i = 0; i < 8; i++) {
            float4 v = *reinterpret_cast<const float4*>(Crow + i * 4);
            epi(bz, m, nb + i * 4, v);
        }
    }
}

// ------------------------------ epilogues ----------------------------------
struct EpiQKV {   // m in [0,8192), n in [0,1536)
    __device__ void operator()(int, int m, int n, float4 v) const {
        int b = m >> 11, s = m & (SQ - 1);
        int h = n / 192, r = n - h * 192;
        int bh = b * HH + h;
        if (r < HD) {
            long row = ((long)bh * SQ + s);
            *reinterpret_cast<uint4*>(&g_Qcat[row * 128 + r]) = pack4h(v, QK_SCALE);
        } else if (r < 2 * HD) {
            // K word part (single fp16 digit): dims d0..d0+3
            int d0 = r - HD;
            int ck = s >> 6, rr = s & 63;
            long base = ((long)bh * 32 + ck) * 16384;
            unsigned off = (unsigned)((d0 >> 5) * 4096) + sw64(rr * 64 + (d0 & 31) * 2);
            __half2 p0 = __floats2half2_rn(v.x, v.y);
            __half2 p1 = __floats2half2_rn(v.z, v.w);
            *reinterpret_cast<uint2*>(reinterpret_cast<char*>(g_KH) + base + off) =
                make_uint2(h2u(p0), h2u(p1));
        } else {
            // V (two fp16 digits): dims d..d+3 for key s
            int d = r - 2 * HD;
            int ck = s >> 6, kc = s & 63;
            long base = ((long)bh * 32 + ck) * 8192 + (kc >> 5) * 4096;
            int kb = (kc & 31) * 2;
#pragma unroll
            for (int i = 0; i < 4; i++) {
                float val = (&v.x)[i];
                __half hb = __float2half(val);
                __half lb = __float2half(val - __half2float(hb));
                unsigned off2 = sw64((d + i) * 64 + kb);
                *reinterpret_cast<__half*>(reinterpret_cast<char*>(g_VH) + base + off2) = hb;
                *reinterpret_cast<__half*>(reinterpret_cast<char*>(g_VL) + base + off2) = lb;
            }
        }
    }
};
struct EpiPE {    // n in [0,1024)
    __device__ void operator()(int, int m, int n, float4 v) const {
        int b = m >> 11, s = m & (SQ - 1);
        int h = n >> 7, r = n & 127;
        int bh = b * HH + h;
        if (r < HD) {
            long row = ((long)bh * SQ + s);
            *reinterpret_cast<uint4*>(&g_Qcat[row * 128 + HD + r]) = pack4h(v, QK_SCALE);
        } else {
            int d0 = r;   // positional K dims [64,128)
            int ck = s >> 6, rr = s & 63;
            long base = ((long)bh * 32 + ck) * 16384;
            unsigned off = (unsigned)((d0 >> 5) * 4096) + sw64(rr * 64 + (d0 & 31) * 2);
            __half2 p0 = __floats2half2_rn(v.x, v.y);
            __half2 p1 = __floats2half2_rn(v.z, v.w);
            *reinterpret_cast<uint2*>(reinterpret_cast<char*>(g_KH) + base + off) =
                make_uint2(h2u(p0), h2u(p1));
        }
    }
};
struct EpiOut {
    float* out;
    __device__ void operator()(int, int m, int n, float4 v) const {
        *reinterpret_cast<float4*>(&out[(long)m * EMB + n]) = v;
    }
};

// ------------------------------ flash attention ----------------------------
// One CTA = 128 q-rows of one (b,h). 8 warps x 16 q-rows. KV chunk = 64 keys.
// smem buffer (32KB x2): KH 16K | VH 8K | VL 8K; bias double-buffered.
__global__ void __launch_bounds__(256)
flash_attn(const unsigned* __restrict__ Qc, const char* __restrict__ KH,
           const char* __restrict__ VH, const char* __restrict__ VL,
           const float* __restrict__ PE_r, unsigned* __restrict__ vals)
{
    extern __shared__ __align__(1024) char smem[];
    constexpr int KVBUF = 32768;                       // KH 16K | VH 8K | VL 8K
    constexpr int SBIAS = 65536, BIAS_STRIDE = 272, BIAS_BUF = 34816;
    constexpr int NCHUNK = SQ / 64;   // 32

    const int tid = threadIdx.x;
    const int l = tid & 31;
    const int w = tid >> 5;
    const int g = l >> 2;
    const int t = l & 3;
    const int bh = blockIdx.y;
    const int q0 = blockIdx.x * 128;
    const int qw = q0 + w * 16;
    const unsigned sbase = smem_u32(smem);

    const unsigned* Qb = Qc + ((long)bh * SQ + qw) * 128;
    const char* KHb = KH + (long)bh * 32 * 16384;
    const char* VHb = VH + (long)bh * 32 * 8192;
    const char* VLb = VL + (long)bh * 32 * 8192;
    const float* Pb = PE_r + ((long)(bh & 7) * SQ + q0) * SQ;

    // ---- Q A-frags in registers (8 k16 steps, fp16 hi/lo) ----
    unsigned qH[8][4], qL[8][4];
#pragma unroll
    for (int kc = 0; kc < 8; kc++) {
        uint2 e00 = *reinterpret_cast<const uint2*>(Qb + (long)g * 128 + kc * 16 + 2 * t);
        uint2 e10 = *reinterpret_cast<const uint2*>(Qb + (long)(g + 8) * 128 + kc * 16 + 2 * t);
        uint2 e01 = *reinterpret_cast<const uint2*>(Qb + (long)g * 128 + kc * 16 + 8 + 2 * t);
        uint2 e11 = *reinterpret_cast<const uint2*>(Qb + (long)(g + 8) * 128 + kc * 16 + 8 + 2 * t);
        qH[kc][0] = __byte_perm(e00.x, e00.y, 0x7632); qL[kc][0] = __byte_perm(e00.x, e00.y, 0x5410);
        qH[kc][1] = __byte_perm(e10.x, e10.y, 0x7632); qL[kc][1] = __byte_perm(e10.x, e10.y, 0x5410);
        qH[kc][2] = __byte_perm(e01.x, e01.y, 0x7632); qL[kc][2] = __byte_perm(e01.x, e01.y, 0x5410);
        qH[kc][3] = __byte_perm(e11.x, e11.y, 0x7632); qL[kc][3] = __byte_perm(e11.x, e11.y, 0x5410);
    }

    float oacc[8][4];
#pragma unroll
    for (int j = 0; j < 8; j++)
#pragma unroll
        for (int k = 0; k < 4; k++) oacc[j][k] = 0.0f;
    float m0r = -1e30f, m1r = -1e30f, l0r = 0.0f, l1r = 0.0f;

    const int brow = (l & 7) + ((l >> 4) & 1) * 8;
    const int bkp  = ((l >> 3) & 1) * 16;

    auto prefetch = [&](int ck) {
        const int buf = ck & 1;
        const unsigned sb = sbase + buf * KVBUF;
        const char* kh = KHb + (long)ck * 16384;
        const char* vh = VHb + (long)ck * 8192;
        const char* vlo = VLb + (long)ck * 8192;
#pragma unroll
        for (int it = 0; it < 4; it++) {
            int o = (tid + it * 256) * 16;
            CP_ASYNC16(sb + o, kh + o);
        }
#pragma unroll
        for (int it = 0; it < 2; it++) {
            int o = (tid + it * 256) * 16;
            CP_ASYNC16(sb + 16384 + o, vh + o);
            CP_ASYNC16(sb + 24576 + o, vlo + o);
        }
        const unsigned bb = sbase + SBIAS + buf * BIAS_BUF;
#pragma unroll
        for (int it = 0; it < 8; it++) {
            int idx = tid + it * 256;
            int r = idx >> 4, c = idx & 15;
            CP_ASYNC16(bb + r * BIAS_STRIDE + c * 16,
                       Pb + (long)r * SQ + ck * 64 + c * 4);
        }
    };

    prefetch(0);
    CP_COMMIT();

    for (int ck = 0; ck < NCHUNK; ck++) {
        if (ck + 1 < NCHUNK) {
            prefetch(ck + 1);
            CP_COMMIT();
            CP_WAIT1();
        } else {
            CP_WAIT0();
        }
        __syncthreads();

        const int buf = ck & 1;
        const unsigned kvb = sbase + buf * KVBUF;

        // ---- S = (qh+ql) * kh : 2 mma per step ----
        float sacc[8][4];
#pragma unroll
        for (int j = 0; j < 8; j++)
#pragma unroll
            for (int k = 0; k < 4; k++) sacc[j][k] = 0.0f;

#pragma unroll
        for (int kc = 0; kc < 8; kc++) {
            unsigned bH[4][4];
            const unsigned slab = kvb + (kc >> 1) * 4096;
            const unsigned koff = (kc & 1) * 32 + bkp;
#pragma unroll
            for (int p = 0; p < 4; p++) {
                unsigned sw = sw64((p * 16 + brow) * 64 + koff);
                LDSM4(bH[p][0], bH[p][1], bH[p][2], bH[p][3], slab + sw);
            }
#pragma unroll
            for (int j = 0; j < 8; j++) {
                const int p = j >> 1, h = (j & 1) * 2;
                MMA16816H(sacc[j], qH[kc], bH[p][h], bH[p][h + 1]);
                MMA16816H(sacc[j], qL[kc], bH[p][h], bH[p][h + 1]);
            }
        }

        // ---- bias add from smem ----
        {
            const char* bb = smem + SBIAS + buf * BIAS_BUF;
            const int r0 = w * 16 + g, r1 = r0 + 8;
#pragma unroll
            for (int j = 0; j < 8; j++) {
                float2 b0 = *reinterpret_cast<const float2*>(bb + r0 * BIAS_STRIDE + (j * 8 + 2 * t) * 4);
                float2 b1 = *reinterpret_cast<const float2*>(bb + r1 * BIAS_STRIDE + (j * 8 + 2 * t) * 4);
                sacc[j][0] += b0.x; sacc[j][1] += b0.y;
                sacc[j][2] += b1.x; sacc[j][3] += b1.y;
            }
        }

        // ---- online softmax ----
        float mx0 = -1e30f, mx1 = -1e30f;
#pragma unroll
        for (int j = 0; j < 8; j++) {
            mx0 = fmaxf(mx0, fmaxf(sacc[j][0], sacc[j][1]));
            mx1 = fmaxf(mx1, fmaxf(sacc[j][2], sacc[j][3]));
        }
        mx0 = fmaxf(mx0, __shfl_xor_sync(0xffffffffu, mx0, 1));
        mx0 = fmaxf(mx0, __shfl_xor_sync(0xffffffffu, mx0, 2));
        mx1 = fmaxf(mx1, __shfl_xor_sync(0xffffffffu, mx1, 1));
        mx1 = fmaxf(mx1, __shfl_xor_sync(0xffffffffu, mx1, 2));

        const float mn0 = fmaxf(m0r, mx0), mn1 = fmaxf(m1r, mx1);
        const float cor0 = __expf(m0r - mn0), cor1 = __expf(m1r - mn1);
        m0r = mn0; m1r = mn1;

        float sum0 = 0.0f, sum1 = 0.0f;
#pragma unroll
        for (int j = 0; j < 8; j++) {
            sacc[j][0] = __expf(sacc[j][0] - mn0);
            sacc[j][1] = __expf(sacc[j][1] - mn0);
            sacc[j][2] = __expf(sacc[j][2] - mn1);
            sacc[j][3] = __expf(sacc[j][3] - mn1);
            sum0 += sacc[j][0] + sacc[j][1];
            sum1 += sacc[j][2] + sacc[j][3];
        }
        sum0 += __shfl_xor_sync(0xffffffffu, sum0, 1);
        sum0 += __shfl_xor_sync(0xffffffffu, sum0, 2);
        sum1 += __shfl_xor_sync(0xffffffffu, sum1, 1);
        sum1 += __shfl_xor_sync(0xffffffffu, sum1, 2);
        l0r = l0r * cor0 + sum0;
        l1r = l1r * cor1 + sum1;

#pragma unroll
        for (int j = 0; j < 8; j++) {
            oacc[j][0] *= cor0; oacc[j][1] *= cor0;
            oacc[j][2] *= cor1; oacc[j][3] *= cor1;
        }

        // ---- PV: oacc += p * (vh + vl), P single fp16 digit ----
#pragma unroll
        for (int kk = 0; kk < 4; kk++) {
            unsigned pH[4];
            pH[0] = h2u(__floats2half2_rn(sacc[2 * kk][0],     sacc[2 * kk][1]));
            pH[1] = h2u(__floats2half2_rn(sacc[2 * kk][2],     sacc[2 * kk][3]));
            pH[2] = h2u(__floats2half2_rn(sacc[2 * kk + 1][0], sacc[2 * kk + 1][1]));
            pH[3] = h2u(__floats2half2_rn(sacc[2 * kk + 1][2], sacc[2 * kk + 1][3]));

            unsigned vHf[4][4], vLf[4][4];
            const unsigned slab = kvb + 16384 + (kk >> 1) * 4096;
            const unsigned koff = (kk & 1) * 32 + bkp;
#pragma unroll
            for (int p = 0; p < 4; p++) {
                unsigned sw = sw64((p * 16 + brow) * 64 + koff);
                LDSM4(vHf[p][0], vHf[p][1], vHf[p][2], vHf[p][3], slab + sw);
                LDSM4(vLf[p][0], vLf[p][1], vLf[p][2], vLf[p][3], slab + 8192 + sw);
            }
#pragma unroll
            for (int j = 0; j < 8; j++) {
                const int p = j >> 1, h = (j & 1) * 2;
                MMA16816H(oacc[j], pH, vHf[p][h], vHf[p][h + 1]);
                MMA16816H(oacc[j], pH, vLf[p][h], vLf[p][h + 1]);
            }
        }

        __syncthreads();   // done reading this buf before it is re-prefetched
    }

    // ---- epilogue: out = oacc / l, fp16 hi|lo packed to g_vals ----
    const float inv0 = 1.0f / l0r, inv1 = 1.0f / l1r;
    const int b = bh >> 3, h = bh & 7;
    const long row0 = (long)(b * SQ + qw + g) * EMB + h * HD;
    const long row1 = (long)(b * SQ + qw + g + 8) * EMB + h * HD;
#pragma unroll
    for (int j = 0; j < 8; j++) {
        int col = j * 8 + 2 * t;
        *reinterpret_cast<uint2*>(&vals[row0 + col]) =
            make_uint2(packh(oacc[j][0] * inv0), packh(oacc[j][1] * inv0));
        *reinterpret_cast<uint2*>(&vals[row1 + col]) =
            make_uint2(packh(oacc[j][2] * inv1), packh(oacc[j][3] * inv1));
    }
}

// ------------------------------ launch -------------------------------------
template <typename Epi>
static void launch_gemm(dim3 grid, const unsigned* A, const unsigned short* B, int K,
                        int lda, int ldb, long sA, long sB, Epi epi)
{
    gemm_fp16a<Epi><<<grid, 256, 40960>>>(A, B, K, lda, ldb, sA, sB, epi);
}

extern "C" void kernel_launch(void* const* d_in, const int* in_sizes, int n_in,
                              void* d_out, int out_size)
{
    const float* x    = (const float*)d_in[0];
    const float* PE   = (const float*)d_in[1];
    const float* PE_r = (const float*)d_in[2];
    const float* Wqkv = (const float*)d_in[3];
    const float* UqUk = (const float*)d_in[4];
    const float* Wo   = (const float*)d_in[5];
    float* out = (float*)d_out;

    void* p;
    cudaGetSymbolAddress(&p, g_x2);   unsigned* x2  = (unsigned*)p;
    cudaGetSymbolAddress(&p, g_PE2);  unsigned* pe2 = (unsigned*)p;
    cudaGetSymbolAddress(&p, g_W2);   unsigned short* w2  = (unsigned short*)p;
    cudaGetSymbolAddress(&p, g_U2);   unsigned short* u2  = (unsigned short*)p;
    cudaGetSymbolAddress(&p, g_Wo2);  unsigned short* wo2 = (unsigned short*)p;
    cudaGetSymbolAddress(&p, g_Qcat); unsigned* Qc  = (unsigned*)p;
    cudaGetSymbolAddress(&p, g_KH);   char* KH = (char*)p;
    cudaGetSymbolAddress(&p, g_VH);   char* VH = (char*)p;
    cudaGetSymbolAddress(&p, g_VL);   char* VL = (char*)p;
    cudaGetSymbolAddress(&p, g_vals); unsigned* Vl = (unsigned*)p;

    auto pka = [](const float* in, unsigned* outp, long n) {
        int n4 = (int)(n / 4);
        pack_act_kernel<<<(n4 + 255) / 256, 256>>>((const float4*)in, (uint4*)outp, n4);
    };
    auto pkw = [](const float* in, unsigned short* outp, long n) {
        int n4 = (int)(n / 4);
        pack_wt_kernel<<<(n4 + 255) / 256, 256>>>((const float4*)in, (uint2*)outp, n4);
    };
    pka(x,    x2,  (long)BB * SQ * EMB);
    pka(PE,   pe2, (long)BB * SQ * EMB);
    pkw(Wqkv, w2,  (long)3 * EMB * EMB);
    pkw(UqUk, u2,  (long)2 * EMB * EMB);
    pkw(Wo,   wo2, (long)EMB * EMB);

    // 1) qkv projection (writes Q fp16-packed, K/V fp16 images)
    launch_gemm(dim3(24, 64, 1), x2, w2, EMB, EMB, EMB, 0, 0, EpiQKV{});
    // 2) positional projection
    launch_gemm(dim3(16, 64, 1), pe2, u2, EMB, EMB, EMB, 0, 0, EpiPE{});
    // 3) fused attention
    cudaFuncSetAttribute(flash_attn, cudaFuncAttributeMaxDynamicSharedMemorySize, 135168);
    flash_attn<<<dim3(SQ / 128, BB * HH), 256, 135168>>>(Qc, KH, VH, VL, PE_r, Vl);
    // 4) out projection
    launch_gemm(dim3(8, 64, 1), Vl, wo2, EMB, EMB, EMB, 0, 0, EpiOut{out});
}

// round 10
// speedup vs baseline: 3.3306x; 1.3174x over previous
#include <cuda_runtime.h>
#include <cuda_fp16.h>
#include <cstdint>

// ---------------------------------------------------------------------------
// TUPE multihead attention — plain fp16 HMMA (fp32 accumulate) everywhere.
//  All GEMMs: D += Ah * Bh  (single fp16 digit each side, fp32 accum).
//  Error model (validated rounds 8-9): ~2.4e-4 RMS per digit dropped per
//  stage; predicted total ~6.7e-4 < 1e-3.
//  K/V stored as fp16 global images in the exact smem slab layout (sw64),
//  loaded by pure cp.async, double-buffered.
// ---------------------------------------------------------------------------

static constexpr int BB  = 4;
static constexpr int HH  = 8;
static constexpr int SQ  = 2048;
static constexpr int EMB = 512;
static constexpr int HD  = 64;
static constexpr float QK_SCALE = 0.0883883476483184f; // 1/sqrt(2*64)

// ------------------------------ scratch ------------------------------------
__device__ __align__(16) unsigned short g_x2  [(size_t)BB * SQ * EMB];   // fp16
__device__ __align__(16) unsigned short g_PE2 [(size_t)BB * SQ * EMB];   // fp16
__device__ __align__(16) unsigned short g_W2  [(size_t)3 * EMB * EMB];   // fp16
__device__ __align__(16) unsigned short g_U2  [(size_t)2 * EMB * EMB];   // fp16
__device__ __align__(16) unsigned short g_Wo2 [(size_t)EMB * EMB];       // fp16
__device__ __align__(16) unsigned short g_Qcat[(size_t)BB * HH * SQ * 128]; // fp16 (scaled)
// K image: per (bh,ck): 16384 B = 4 slabs x (64 keys x 64 B), sw64
__device__ __align__(16) unsigned short g_KH[(size_t)BB * HH * SQ * 128];
// V image: per (bh,ck): 8192 B = 2 slabs x 4096 (64 dims x 32 keys), sw64
__device__ __align__(16) unsigned short g_VH[(size_t)BB * HH * HD * SQ];
__device__ __align__(16) unsigned short g_vals[(size_t)BB * SQ * EMB];   // fp16

// ------------------------------ helpers ------------------------------------
__device__ __forceinline__ unsigned smem_u32(const void* p) {
    unsigned a;
    asm("{ .reg .u64 t; cvta.to.shared.u64 t, %1; cvt.u32.u64 %0, t; }" : "=r"(a) : "l"(p));
    return a;
}
__device__ __forceinline__ unsigned h2u(__half2 h) {
    return *reinterpret_cast<unsigned*>(&h);
}

// f32 -> fp16 (all inputs)
__global__ void __launch_bounds__(256)
pack_h_kernel(const float4* __restrict__ in, uint2* __restrict__ out, int n4)
{
    int i = blockIdx.x * 256 + threadIdx.x;
    if (i < n4) {
        float4 v = in[i];
        out[i] = make_uint2(h2u(__floats2half2_rn(v.x, v.y)),
                            h2u(__floats2half2_rn(v.z, v.w)));
    }
}

#define LDSM4(r0, r1, r2, r3, a)                                              \
    asm volatile("ldmatrix.sync.aligned.m8n8.x4.shared.b16 {%0,%1,%2,%3}, [%4];" \
                 : "=r"(r0), "=r"(r1), "=r"(r2), "=r"(r3) : "r"(a))

#define MMA16816H(c, a, b0, b1)                                               \
    asm volatile("mma.sync.aligned.m16n8k16.row.col.f32.f16.f16.f32 "         \
                 "{%0,%1,%2,%3}, {%4,%5,%6,%7}, {%8,%9}, {%0,%1,%2,%3};"      \
                 : "+f"((c)[0]), "+f"((c)[1]), "+f"((c)[2]), "+f"((c)[3])     \
                 : "r"((a)[0]), "r"((a)[1]), "r"((a)[2]), "r"((a)[3]),        \
                   "r"(b0), "r"(b1))

#define CP_ASYNC16(dst, src) \
    asm volatile("cp.async.cg.shared.global [%0], [%1], 16;" :: "r"(dst), "l"(src))
#define CP_COMMIT() asm volatile("cp.async.commit_group;" ::: "memory")
#define CP_WAIT0()  asm volatile("cp.async.wait_group 0;" ::: "memory")
#define CP_WAIT1()  asm volatile("cp.async.wait_group 1;" ::: "memory")

__device__ __forceinline__ unsigned sw64(unsigned off)  { return off ^ ((off >> 3) & 0x30); }

// ------------------------------ GEMM (projections / out) -------------------
// C[128 x 64]; A fp16 [M,K]; B fp16 [N,K]; K mult of 32.
// Stage (12KB): A[128x32]@0, B[64x32]@8192. Epilogue reuses smem (34816 B).
template <typename Epi>
__global__ void __launch_bounds__(256, 2)
gemm_fp16s(const unsigned short* __restrict__ A, const unsigned short* __restrict__ B,
           int K, int lda, int ldb, long sA, long sB, Epi epi)
{
    extern __shared__ __align__(1024) char smem[];
    constexpr int SB = 8192, STAGE = 12288;

    const int tid = threadIdx.x;
    const int l   = tid & 31;
    const int w   = tid >> 5;
    const int wm  = w & 3;
    const int wn  = w >> 2;
    const int m0  = wm * 32;
    const int n0  = wn * 32;
    const int bz  = blockIdx.z;
    const unsigned sbase = smem_u32(smem);

    const unsigned short* Ab = A + bz * sA + (long)blockIdx.y * 128 * lda;
    const unsigned short* Bb = B + bz * sB + (long)blockIdx.x * 64 * ldb;

    float acc[2][4][4];
#pragma unroll
    for (int i = 0; i < 2; i++)
#pragma unroll
        for (int j = 0; j < 4; j++)
#pragma unroll
            for (int k = 0; k < 4; k++) acc[i][j][k] = 0.0f;

    const int arow = (l & 7) + ((l >> 3) & 1) * 8;
    const int akp  = ((l >> 4) & 1) * 16;
    const int brow = (l & 7) + ((l >> 4) & 1) * 8;
    const int bkp  = ((l >> 3) & 1) * 16;

    uint4 ra[2], rb;
    const int nChunks = K >> 5;

    auto load_global = [&](int c) {
#pragma unroll
        for (int it = 0; it < 2; it++) {
            int idx = tid + it * 256;
            int r = idx >> 2, q = idx & 3;
            ra[it] = *reinterpret_cast<const uint4*>(Ab + (long)r * lda + c * 32 + q * 8);
        }
        {
            int r = tid >> 2, q = tid & 3;
            rb = *reinterpret_cast<const uint4*>(Bb + (long)r * ldb + c * 32 + q * 8);
        }
    };
    auto store_stage = [&](char* buf) {
#pragma unroll
        for (int it = 0; it < 2; it++) {
            int idx = tid + it * 256;
            int r = idx >> 2, q = idx & 3;
            *reinterpret_cast<uint4*>(buf + sw64(r * 64 + q * 16)) = ra[it];
        }
        {
            int r = tid >> 2, q = tid & 3;
            *reinterpret_cast<uint4*>(buf + SB + sw64(r * 64 + q * 16)) = rb;
        }
    };

    load_global(0);
    store_stage(smem);
    __syncthreads();

    for (int c = 0; c < nChunks; c++) {
        const bool more = (c + 1) < nChunks;
        if (more) load_global(c + 1);

        const unsigned stage = sbase + (c & 1) * STAGE;
#pragma unroll
        for (int ks = 0; ks < 2; ks++) {
            unsigned aH[2][4], bH[2][4];
#pragma unroll
            for (int i = 0; i < 2; i++) {
                unsigned off = (m0 + i * 16 + arow) * 64 + ks * 32 + akp;
                LDSM4(aH[i][0], aH[i][1], aH[i][2], aH[i][3], stage + sw64(off));
            }
#pragma unroll
            for (int p = 0; p < 2; p++) {
                unsigned off = (n0 + p * 16 + brow) * 64 + ks * 32 + bkp;
                LDSM4(bH[p][0], bH[p][1], bH[p][2], bH[p][3], stage + SB + sw64(off));
            }
#pragma unroll
            for (int i = 0; i < 2; i++)
#pragma unroll
                for (int j = 0; j < 4; j++) {
                    const int p = j >> 1, h = (j & 1) * 2;
                    MMA16816H(acc[i][j], aH[i], bH[p][h], bH[p][h + 1]);
                }
        }

        if (more) store_stage(smem + ((c + 1) & 1) * STAGE);
        __syncthreads();
    }

    float* C = reinterpret_cast<float*>(smem);   // [128][68]
#pragma unroll
    for (int i = 0; i < 2; i++)
#pragma unroll
        for (int j = 0; j < 4; j++) {
            int r0  = m0 + i * 16 + (l >> 2);
            int col = n0 + j * 8 + (l & 3) * 2;
            *reinterpret_cast<float2*>(C + r0 * 68 + col)       = make_float2(acc[i][j][0], acc[i][j][1]);
            *reinterpret_cast<float2*>(C + (r0 + 8) * 68 + col) = make_float2(acc[i][j][2], acc[i][j][3]);
        }
    __syncthreads();

    {
        int r = tid >> 1, seg = (tid & 1) << 5;
        int m  = blockIdx.y * 128 + r;
        int nb = blockIdx.x * 64 + seg;
        const float* Crow = C + r * 68 + seg;
#pragma unroll
        for (int i = 0; i < 8; i++) {
            float4 v = *reinterpret_cast<const float4*>(Crow + i * 4);
            epi(bz, m, nb + i * 4, v);
        }
    }
}

// ------------------------------ epilogues ----------------------------------
struct EpiQKV {   // m in [0,8192), n in [0,1536)
    __device__ void operator()(int, int m, int n, float4 v) const {
        int b = m >> 11, s = m & (SQ - 1);
        int h = n / 192, r = n - h * 192;
        int bh = b * HH + h;
        if (r < HD) {
            long row = ((long)bh * SQ + s);
            *reinterpret_cast<uint2*>(&g_Qcat[row * 128 + r]) =
                make_uint2(h2u(__floats2half2_rn(v.x * QK_SCALE, v.y * QK_SCALE)),
                           h2u(__floats2half2_rn(v.z * QK_SCALE, v.w * QK_SCALE)));
        } else if (r < 2 * HD) {
            // K: dims d0..d0+3 for key s
            int d0 = r - HD;
            int ck = s >> 6, rr = s & 63;
            long base = ((long)bh * 32 + ck) * 16384;
            unsigned off = (unsigned)((d0 >> 5) * 4096) + sw64(rr * 64 + (d0 & 31) * 2);
            *reinterpret_cast<uint2*>(reinterpret_cast<char*>(g_KH) + base + off) =
                make_uint2(h2u(__floats2half2_rn(v.x, v.y)),
                           h2u(__floats2half2_rn(v.z, v.w)));
        } else {
            // V: dims d..d+3 for key s
            int d = r - 2 * HD;
            int ck = s >> 6, kc = s & 63;
            long base = ((long)bh * 32 + ck) * 8192 + (kc >> 5) * 4096;
            int kb = (kc & 31) * 2;
#pragma unroll
            for (int i = 0; i < 4; i++) {
                float val = (&v.x)[i];
                unsigned off2 = sw64((d + i) * 64 + kb);
                *reinterpret_cast<__half*>(reinterpret_cast<char*>(g_VH) + base + off2) =
                    __float2half(val);
            }
        }
    }
};
struct EpiPE {    // n in [0,1024)
    __device__ void operator()(int, int m, int n, float4 v) const {
        int b = m >> 11, s = m & (SQ - 1);
        int h = n >> 7, r = n & 127;
        int bh = b * HH + h;
        if (r < HD) {
            long row = ((long)bh * SQ + s);
            *reinterpret_cast<uint2*>(&g_Qcat[row * 128 + HD + r]) =
                make_uint2(h2u(__floats2half2_rn(v.x * QK_SCALE, v.y * QK_SCALE)),
                           h2u(__floats2half2_rn(v.z * QK_SCALE, v.w * QK_SCALE)));
        } else {
            int d0 = r;   // positional K dims [64,128)
            int ck = s >> 6, rr = s & 63;
            long base = ((long)bh * 32 + ck) * 16384;
            unsigned off = (unsigned)((d0 >> 5) * 4096) + sw64(rr * 64 + (d0 & 31) * 2);
            *reinterpret_cast<uint2*>(reinterpret_cast<char*>(g_KH) + base + off) =
                make_uint2(h2u(__floats2half2_rn(v.x, v.y)),
                           h2u(__floats2half2_rn(v.z, v.w)));
        }
    }
};
struct EpiOut {
    float* out;
    __device__ void operator()(int, int m, int n, float4 v) const {
        *reinterpret_cast<float4*>(&out[(long)m * EMB + n]) = v;
    }
};

// ------------------------------ flash attention ----------------------------
// One CTA = 128 q-rows of one (b,h). 8 warps x 16 q-rows. KV chunk = 64 keys.
// smem buffer (24KB x2): KH 16K | VH 8K; bias double-buffered.
__global__ void __launch_bounds__(256)
flash_attn(const unsigned short* __restrict__ Qc, const char* __restrict__ KH,
           const char* __restrict__ VH,
           const float* __restrict__ PE_r, unsigned short* __restrict__ vals)
{
    extern __shared__ __align__(1024) char smem[];
    constexpr int KVBUF = 24576;                       // KH 16K | VH 8K
    constexpr int SBIAS = 49152, BIAS_STRIDE = 272, BIAS_BUF = 34816;
    constexpr int NCHUNK = SQ / 64;   // 32

    const int tid = threadIdx.x;
    const int l = tid & 31;
    const int w = tid >> 5;
    const int g = l >> 2;
    const int t = l & 3;
    const int bh = blockIdx.y;
    const int q0 = blockIdx.x * 128;
    const int qw = q0 + w * 16;
    const unsigned sbase = smem_u32(smem);

    const unsigned short* Qb = Qc + ((long)bh * SQ + qw) * 128;
    const char* KHb = KH + (long)bh * 32 * 16384;
    const char* VHb = VH + (long)bh * 32 * 8192;
    const float* Pb = PE_r + ((long)(bh & 7) * SQ + q0) * SQ;

    // ---- Q A-frags in registers (8 k16 steps, fp16 single digit) ----
    unsigned qH[8][4];
#pragma unroll
    for (int kc = 0; kc < 8; kc++) {
        qH[kc][0] = *reinterpret_cast<const unsigned*>(Qb + (long)g * 128 + kc * 16 + 2 * t);
        qH[kc][1] = *reinterpret_cast<const unsigned*>(Qb + (long)(g + 8) * 128 + kc * 16 + 2 * t);
        qH[kc][2] = *reinterpret_cast<const unsigned*>(Qb + (long)g * 128 + kc * 16 + 8 + 2 * t);
        qH[kc][3] = *reinterpret_cast<const unsigned*>(Qb + (long)(g + 8) * 128 + kc * 16 + 8 + 2 * t);
    }

    float oacc[8][4];
#pragma unroll
    for (int j = 0; j < 8; j++)
#pragma unroll
        for (int k = 0; k < 4; k++) oacc[j][k] = 0.0f;
    float m0r = -1e30f, m1r = -1e30f, l0r = 0.0f, l1r = 0.0f;

    const int brow = (l & 7) + ((l >> 4) & 1) * 8;
    const int bkp  = ((l >> 3) & 1) * 16;

    auto prefetch = [&](int ck) {
        const int buf = ck & 1;
        const unsigned sb = sbase + buf * KVBUF;
        const char* kh = KHb + (long)ck * 16384;
        const char* vh = VHb + (long)ck * 8192;
#pragma unroll
        for (int it = 0; it < 4; it++) {
            int o = (tid + it * 256) * 16;
            CP_ASYNC16(sb + o, kh + o);
        }
#pragma unroll
        for (int it = 0; it < 2; it++) {
            int o = (tid + it * 256) * 16;
            CP_ASYNC16(sb + 16384 + o, vh + o);
        }
        const unsigned bb = sbase + SBIAS + buf * BIAS_BUF;
#pragma unroll
        for (int it = 0; it < 8; it++) {
            int idx = tid + it * 256;
            int r = idx >> 4, c = idx & 15;
            CP_ASYNC16(bb + r * BIAS_STRIDE + c * 16,
                       Pb + (long)r * SQ + ck * 64 + c * 4);
        }
    };

    prefetch(0);
    CP_COMMIT();

    for (int ck = 0; ck < NCHUNK; ck++) {
        if (ck + 1 < NCHUNK) {
            prefetch(ck + 1);
            CP_COMMIT();
            CP_WAIT1();
        } else {
            CP_WAIT0();
        }
        __syncthreads();

        const int buf = ck & 1;
        const unsigned kvb = sbase + buf * KVBUF;

        // ---- S = qh * kh : 1 mma per step ----
        float sacc[8][4];
#pragma unroll
        for (int j = 0; j < 8; j++)
#pragma unroll
            for (int k = 0; k < 4; k++) sacc[j][k] = 0.0f;

#pragma unroll
        for (int kc = 0; kc < 8; kc++) {
            unsigned bH[4][4];
            const unsigned slab = kvb + (kc >> 1) * 4096;
            const unsigned koff = (kc & 1) * 32 + bkp;
#pragma unroll
            for (int p = 0; p < 4; p++) {
                unsigned sw = sw64((p * 16 + brow) * 64 + koff);
                LDSM4(bH[p][0], bH[p][1], bH[p][2], bH[p][3], slab + sw);
            }
#pragma unroll
            for (int j = 0; j < 8; j++) {
                const int p = j >> 1, h = (j & 1) * 2;
                MMA16816H(sacc[j], qH[kc], bH[p][h], bH[p][h + 1]);
            }
        }

        // ---- bias add from smem ----
        {
            const char* bb = smem + SBIAS + buf * BIAS_BUF;
            const int r0 = w * 16 + g, r1 = r0 + 8;
#pragma unroll
            for (int j = 0; j < 8; j++) {
                float2 b0 = *reinterpret_cast<const float2*>(bb + r0 * BIAS_STRIDE + (j * 8 + 2 * t) * 4);
                float2 b1 = *reinterpret_cast<const float2*>(bb + r1 * BIAS_STRIDE + (j * 8 + 2 * t) * 4);
                sacc[j][0] += b0.x; sacc[j][1] += b0.y;
                sacc[j][2] += b1.x; sacc[j][3] += b1.y;
            }
        }

        // ---- online softmax ----
        float mx0 = -1e30f, mx1 = -1e30f;
#pragma unroll
        for (int j = 0; j < 8; j++) {
            mx0 = fmaxf(mx0, fmaxf(sacc[j][0], sacc[j][1]));
            mx1 = fmaxf(mx1, fmaxf(sacc[j][2], sacc[j][3]));
        }
        mx0 = fmaxf(mx0, __shfl_xor_sync(0xffffffffu, mx0, 1));
        mx0 = fmaxf(mx0, __shfl_xor_sync(0xffffffffu, mx0, 2));
        mx1 = fmaxf(mx1, __shfl_xor_sync(0xffffffffu, mx1, 1));
        mx1 = fmaxf(mx1, __shfl_xor_sync(0xffffffffu, mx1, 2));

        const float mn0 = fmaxf(m0r, mx0), mn1 = fmaxf(m1r, mx1);
        const float cor0 = __expf(m0r - mn0), cor1 = __expf(m1r - mn1);
        m0r = mn0; m1r = mn1;

        float sum0 = 0.0f, sum1 = 0.0f;
#pragma unroll
        for (int j = 0; j < 8; j++) {
            sacc[j][0] = __expf(sacc[j][0] - mn0);
            sacc[j][1] = __expf(sacc[j][1] - mn0);
            sacc[j][2] = __expf(sacc[j][2] - mn1);
            sacc[j][3] = __expf(sacc[j][3] - mn1);
            sum0 += sacc[j][0] + sacc[j][1];
            sum1 += sacc[j][2] + sacc[j][3];
        }
        sum0 += __shfl_xor_sync(0xffffffffu, sum0, 1);
        sum0 += __shfl_xor_sync(0xffffffffu, sum0, 2);
        sum1 += __shfl_xor_sync(0xffffffffu, sum1, 1);
        sum1 += __shfl_xor_sync(0xffffffffu, sum1, 2);
        l0r = l0r * cor0 + sum0;
        l1r = l1r * cor1 + sum1;

#pragma unroll
        for (int j = 0; j < 8; j++) {
            oacc[j][0] *= cor0; oacc[j][1] *= cor0;
            oacc[j][2] *= cor1; oacc[j][3] *= cor1;
        }

        // ---- PV: oacc += p * vh ----
#pragma unroll
        for (int kk = 0; kk < 4; kk++) {
            unsigned pH[4];
            pH[0] = h2u(__floats2half2_rn(sacc[2 * kk][0],     sacc[2 * kk][1]));
            pH[1] = h2u(__floats2half2_rn(sacc[2 * kk][2],     sacc[2 * kk][3]));
            pH[2] = h2u(__floats2half2_rn(sacc[2 * kk + 1][0], sacc[2 * kk + 1][1]));
            pH[3] = h2u(__floats2half2_rn(sacc[2 * kk + 1][2], sacc[2 * kk + 1][3]));

            unsigned vHf[4][4];
            const unsigned slab = kvb + 16384 + (kk >> 1) * 4096;
            const unsigned koff = (kk & 1) * 32 + bkp;
#pragma unroll
            for (int p = 0; p < 4; p++) {
                unsigned sw = sw64((p * 16 + brow) * 64 + koff);
                LDSM4(vHf[p][0], vHf[p][1], vHf[p][2], vHf[p][3], slab + sw);
            }
#pragma unroll
            for (int j = 0; j < 8; j++) {
                const int p = j >> 1, h = (j & 1) * 2;
                MMA16816H(oacc[j], pH, vHf[p][h], vHf[p][h + 1]);
            }
        }

        __syncthreads();   // done reading this buf before it is re-prefetched
    }

    // ---- epilogue: out = oacc / l, fp16 to g_vals ----
    const float inv0 = 1.0f / l0r, inv1 = 1.0f / l1r;
    const int b = bh >> 3, h = bh & 7;
    const long row0 = (long)(b * SQ + qw + g) * EMB + h * HD;
    const long row1 = (long)(b * SQ + qw + g + 8) * EMB + h * HD;
#pragma unroll
    for (int j = 0; j < 8; j++) {
        int col = j * 8 + 2 * t;
        *reinterpret_cast<unsigned*>(&vals[row0 + col]) =
            h2u(__floats2half2_rn(oacc[j][0] * inv0, oacc[j][1] * inv0));
        *reinterpret_cast<unsigned*>(&vals[row1 + col]) =
            h2u(__floats2half2_rn(oacc[j][2] * inv1, oacc[j][3] * inv1));
    }
}

// ------------------------------ launch -------------------------------------
template <typename Epi>
static void launch_gemm(dim3 grid, const unsigned short* A, const unsigned short* B,
                        int K, int lda, int ldb, long sA, long sB, Epi epi)
{
    gemm_fp16s<Epi><<<grid, 256, 34816>>>(A, B, K, lda, ldb, sA, sB, epi);
}

extern "C" void kernel_launch(void* const* d_in, const int* in_sizes, int n_in,
                              void* d_out, int out_size)
{
    const float* x    = (const float*)d_in[0];
    const float* PE   = (const float*)d_in[1];
    const float* PE_r = (const float*)d_in[2];
    const float* Wqkv = (const float*)d_in[3];
    const float* UqUk = (const float*)d_in[4];
    const float* Wo   = (const float*)d_in[5];
    float* out = (float*)d_out;

    void* p;
    cudaGetSymbolAddress(&p, g_x2);   unsigned short* x2  = (unsigned short*)p;
    cudaGetSymbolAddress(&p, g_PE2);  unsigned short* pe2 = (unsigned short*)p;
    cudaGetSymbolAddress(&p, g_W2);   unsigned short* w2  = (unsigned short*)p;
    cudaGetSymbolAddress(&p, g_U2);   unsigned short* u2  = (unsigned short*)p;
    cudaGetSymbolAddress(&p, g_Wo2);  unsigned short* wo2 = (unsigned short*)p;
    cudaGetSymbolAddress(&p, g_Qcat); unsigned short* Qc  = (unsigned short*)p;
    cudaGetSymbolAddress(&p, g_KH);   char* KH = (char*)p;
    cudaGetSymbolAddress(&p, g_VH);   char* VH = (char*)p;
    cudaGetSymbolAddress(&p, g_vals); unsigned short* Vl = (unsigned short*)p;

    auto pk = [](const float* in, unsigned short* outp, long n) {
        int n4 = (int)(n / 4);
        pack_h_kernel<<<(n4 + 255) / 256, 256>>>((const float4*)in, (uint2*)outp, n4);
    };
    pk(x,    x2,  (long)BB * SQ * EMB);
    pk(PE,   pe2, (long)BB * SQ * EMB);
    pk(Wqkv, w2,  (long)3 * EMB * EMB);
    pk(UqUk, u2,  (long)2 * EMB * EMB);
    pk(Wo,   wo2, (long)EMB * EMB);

    // 1) qkv projection (writes Q scaled fp16, K/V fp16 images)
    launch_gemm(dim3(24, 64, 1), x2, w2, EMB, EMB, EMB, 0, 0, EpiQKV{});
    // 2) positional projection
    launch_gemm(dim3(16, 64, 1), pe2, u2, EMB, EMB, EMB, 0, 0, EpiPE{});
    // 3) fused attention
    cudaFuncSetAttribute(flash_attn, cudaFuncAttributeMaxDynamicSharedMemorySize, 118784);
    flash_attn<<<dim3(SQ / 128, BB * HH), 256, 118784>>>(Qc, KH, VH, PE_r, Vl);
    // 4) out projection
    launch_gemm(dim3(8, 64, 1), Vl, wo2, EMB, EMB, EMB, 0, 0, EpiOut{out});
}

// round 11
// speedup vs baseline: 3.5104x; 1.0540x over previous
#include <cuda_runtime.h>
#include <cuda_fp16.h>
#include <cstdint>

// ---------------------------------------------------------------------------
// TUPE multihead attention — plain fp16 HMMA (fp32 accumulate) everywhere.
//  Flash middle: software-pipelined (S(ck+1) overlaps softmax/PV(ck)),
//  4-deep KV + 3-deep bias cp.async rings, one barrier per chunk,
//  softmax in log2 domain (ex2.approx).
// ---------------------------------------------------------------------------

static constexpr int BB  = 4;
static constexpr int HH  = 8;
static constexpr int SQ  = 2048;
static constexpr int EMB = 512;
static constexpr int HD  = 64;
static constexpr float LOG2E = 1.4426950408889634f;
static constexpr float QK_SCALE_L2E = 0.0883883476483184f * LOG2E; // 1/sqrt(128) * log2(e)

// ------------------------------ scratch ------------------------------------
__device__ __align__(16) unsigned short g_x2  [(size_t)BB * SQ * EMB];   // fp16
__device__ __align__(16) unsigned short g_PE2 [(size_t)BB * SQ * EMB];   // fp16
__device__ __align__(16) unsigned short g_W2  [(size_t)3 * EMB * EMB];   // fp16
__device__ __align__(16) unsigned short g_U2  [(size_t)2 * EMB * EMB];   // fp16
__device__ __align__(16) unsigned short g_Wo2 [(size_t)EMB * EMB];       // fp16
__device__ __align__(16) unsigned short g_Qcat[(size_t)BB * HH * SQ * 128]; // fp16 (scaled by QK_SCALE_L2E)
// K image: per (bh,ck): 16384 B = 4 slabs x (64 keys x 64 B), sw64
__device__ __align__(16) unsigned short g_KH[(size_t)BB * HH * SQ * 128];
// V image: per (bh,ck): 8192 B = 2 slabs x 4096 (64 dims x 32 keys), sw64
__device__ __align__(16) unsigned short g_VH[(size_t)BB * HH * HD * SQ];
__device__ __align__(16) unsigned short g_vals[(size_t)BB * SQ * EMB];   // fp16

// ------------------------------ helpers ------------------------------------
__device__ __forceinline__ unsigned smem_u32(const void* p) {
    unsigned a;
    asm("{ .reg .u64 t; cvta.to.shared.u64 t, %1; cvt.u32.u64 %0, t; }" : "=r"(a) : "l"(p));
    return a;
}
__device__ __forceinline__ unsigned h2u(__half2 h) {
    return *reinterpret_cast<unsigned*>(&h);
}
__device__ __forceinline__ float ex2f(float x) {
    float r;
    asm("ex2.approx.f32 %0, %1;" : "=f"(r) : "f"(x));
    return r;
}

// one merged pack: all five f32 inputs -> fp16, segment dispatch by index
__global__ void __launch_bounds__(256)
pack_all_kernel(const float4* __restrict__ x,  const float4* __restrict__ pe,
                const float4* __restrict__ w,  const float4* __restrict__ u,
                const float4* __restrict__ wo,
                uint2* __restrict__ ox, uint2* __restrict__ ope,
                uint2* __restrict__ ow, uint2* __restrict__ ou,
                uint2* __restrict__ owo)
{
    const int N0 = 1048576, N1 = 2097152, N2 = 2293760, N3 = 2424832, N4 = 2490368;
    int i = blockIdx.x * 256 + threadIdx.x;
    if (i >= N4) return;
    const float4* src; uint2* dst; int j;
    if (i < N0)      { src = x;  dst = ox;  j = i; }
    else if (i < N1) { src = pe; dst = ope; j = i - N0; }
    else if (i < N2) { src = w;  dst = ow;  j = i - N1; }
    else if (i < N3) { src = u;  dst = ou;  j = i - N2; }
    else             { src = wo; dst = owo; j = i - N3; }
    float4 v = src[j];
    dst[j] = make_uint2(h2u(__floats2half2_rn(v.x, v.y)),
                        h2u(__floats2half2_rn(v.z, v.w)));
}

#define LDSM4(r0, r1, r2, r3, a)                                              \
    asm volatile("ldmatrix.sync.aligned.m8n8.x4.shared.b16 {%0,%1,%2,%3}, [%4];" \
                 : "=r"(r0), "=r"(r1), "=r"(r2), "=r"(r3) : "r"(a))

#define MMA16816H(c, a, b0, b1)                                               \
    asm volatile("mma.sync.aligned.m16n8k16.row.col.f32.f16.f16.f32 "         \
                 "{%0,%1,%2,%3}, {%4,%5,%6,%7}, {%8,%9}, {%0,%1,%2,%3};"      \
                 : "+f"((c)[0]), "+f"((c)[1]), "+f"((c)[2]), "+f"((c)[3])     \
                 : "r"((a)[0]), "r"((a)[1]), "r"((a)[2]), "r"((a)[3]),        \
                   "r"(b0), "r"(b1))

#define CP_ASYNC16(dst, src) \
    asm volatile("cp.async.cg.shared.global [%0], [%1], 16;" :: "r"(dst), "l"(src))
#define CP_COMMIT() asm volatile("cp.async.commit_group;" ::: "memory")
#define CP_WAIT0()  asm volatile("cp.async.wait_group 0;" ::: "memory")
#define CP_WAIT1()  asm volatile("cp.async.wait_group 1;" ::: "memory")

__device__ __forceinline__ unsigned sw64(unsigned off)  { return off ^ ((off >> 3) & 0x30); }

// ------------------------------ GEMM (projections / out) -------------------
// C[128 x 64]; A fp16 [M,K]; B fp16 [N,K]; K mult of 32.  (round-10, proven)
template <typename Epi>
__global__ void __launch_bounds__(256, 2)
gemm_fp16s(const unsigned short* __restrict__ A, const unsigned short* __restrict__ B,
           int K, int lda, int ldb, long sA, long sB, Epi epi)
{
    extern __shared__ __align__(1024) char smem[];
    constexpr int SB = 8192, STAGE = 12288;

    const int tid = threadIdx.x;
    const int l   = tid & 31;
    const int w   = tid >> 5;
    const int wm  = w & 3;
    const int wn  = w >> 2;
    const int m0  = wm * 32;
    const int n0  = wn * 32;
    const int bz  = blockIdx.z;
    const unsigned sbase = smem_u32(smem);

    const unsigned short* Ab = A + bz * sA + (long)blockIdx.y * 128 * lda;
    const unsigned short* Bb = B + bz * sB + (long)blockIdx.x * 64 * ldb;

    float acc[2][4][4];
#pragma unroll
    for (int i = 0; i < 2; i++)
#pragma unroll
        for (int j = 0; j < 4; j++)
#pragma unroll
            for (int k = 0; k < 4; k++) acc[i][j][k] = 0.0f;

    const int arow = (l & 7) + ((l >> 3) & 1) * 8;
    const int akp  = ((l >> 4) & 1) * 16;
    const int brow = (l & 7) + ((l >> 4) & 1) * 8;
    const int bkp  = ((l >> 3) & 1) * 16;

    uint4 ra[2], rb;
    const int nChunks = K >> 5;

    auto load_global = [&](int c) {
#pragma unroll
        for (int it = 0; it < 2; it++) {
            int idx = tid + it * 256;
            int r = idx >> 2, q = idx & 3;
            ra[it] = *reinterpret_cast<const uint4*>(Ab + (long)r * lda + c * 32 + q * 8);
        }
        {
            int r = tid >> 2, q = tid & 3;
            rb = *reinterpret_cast<const uint4*>(Bb + (long)r * ldb + c * 32 + q * 8);
        }
    };
    auto store_stage = [&](char* buf) {
#pragma unroll
        for (int it = 0; it < 2; it++) {
            int idx = tid + it * 256;
            int r = idx >> 2, q = idx & 3;
            *reinterpret_cast<uint4*>(buf + sw64(r * 64 + q * 16)) = ra[it];
        }
        {
            int r = tid >> 2, q = tid & 3;
            *reinterpret_cast<uint4*>(buf + SB + sw64(r * 64 + q * 16)) = rb;
        }
    };

    load_global(0);
    store_stage(smem);
    __syncthreads();

    for (int c = 0; c < nChunks; c++) {
        const bool more = (c + 1) < nChunks;
        if (more) load_global(c + 1);

        const unsigned stage = sbase + (c & 1) * STAGE;
#pragma unroll
        for (int ks = 0; ks < 2; ks++) {
            unsigned aH[2][4], bH[2][4];
#pragma unroll
            for (int i = 0; i < 2; i++) {
                unsigned off = (m0 + i * 16 + arow) * 64 + ks * 32 + akp;
                LDSM4(aH[i][0], aH[i][1], aH[i][2], aH[i][3], stage + sw64(off));
            }
#pragma unroll
            for (int p = 0; p < 2; p++) {
                unsigned off = (n0 + p * 16 + brow) * 64 + ks * 32 + bkp;
                LDSM4(bH[p][0], bH[p][1], bH[p][2], bH[p][3], stage + SB + sw64(off));
            }
#pragma unroll
            for (int i = 0; i < 2; i++)
#pragma unroll
                for (int j = 0; j < 4; j++) {
                    const int p = j >> 1, h = (j & 1) * 2;
                    MMA16816H(acc[i][j], aH[i], bH[p][h], bH[p][h + 1]);
                }
        }

        if (more) store_stage(smem + ((c + 1) & 1) * STAGE);
        __syncthreads();
    }

    float* C = reinterpret_cast<float*>(smem);   // [128][68]
#pragma unroll
    for (int i = 0; i < 2; i++)
#pragma unroll
        for (int j = 0; j < 4; j++) {
            int r0  = m0 + i * 16 + (l >> 2);
            int col = n0 + j * 8 + (l & 3) * 2;
            *reinterpret_cast<float2*>(C + r0 * 68 + col)       = make_float2(acc[i][j][0], acc[i][j][1]);
            *reinterpret_cast<float2*>(C + (r0 + 8) * 68 + col) = make_float2(acc[i][j][2], acc[i][j][3]);
        }
    __syncthreads();

    {
        int r = tid >> 1, seg = (tid & 1) << 5;
        int m  = blockIdx.y * 128 + r;
        int nb = blockIdx.x * 64 + seg;
        const float* Crow = C + r * 68 + seg;
#pragma unroll
        for (int i = 0; i < 8; i++) {
            float4 v = *reinterpret_cast<const float4*>(Crow + i * 4);
            epi(bz, m, nb + i * 4, v);
        }
    }
}

// ------------------------------ epilogues ----------------------------------
struct EpiQKV {   // m in [0,8192), n in [0,1536)
    __device__ void operator()(int, int m, int n, float4 v) const {
        int b = m >> 11, s = m & (SQ - 1);
        int h = n / 192, r = n - h * 192;
        int bh = b * HH + h;
        if (r < HD) {
            long row = ((long)bh * SQ + s);
            *reinterpret_cast<uint2*>(&g_Qcat[row * 128 + r]) =
                make_uint2(h2u(__floats2half2_rn(v.x * QK_SCALE_L2E, v.y * QK_SCALE_L2E)),
                           h2u(__floats2half2_rn(v.z * QK_SCALE_L2E, v.w * QK_SCALE_L2E)));
        } else if (r < 2 * HD) {
            int d0 = r - HD;
            int ck = s >> 6, rr = s & 63;
            long base = ((long)bh * 32 + ck) * 16384;
            unsigned off = (unsigned)((d0 >> 5) * 4096) + sw64(rr * 64 + (d0 & 31) * 2);
            *reinterpret_cast<uint2*>(reinterpret_cast<char*>(g_KH) + base + off) =
                make_uint2(h2u(__floats2half2_rn(v.x, v.y)),
                           h2u(__floats2half2_rn(v.z, v.w)));
        } else {
            int d = r - 2 * HD;
            int ck = s >> 6, kc = s & 63;
            long base = ((long)bh * 32 + ck) * 8192 + (kc >> 5) * 4096;
            int kb = (kc & 31) * 2;
#pragma unroll
            for (int i = 0; i < 4; i++) {
                float val = (&v.x)[i];
                unsigned off2 = sw64((d + i) * 64 + kb);
                *reinterpret_cast<__half*>(reinterpret_cast<char*>(g_VH) + base + off2) =
                    __float2half(val);
            }
        }
    }
};
struct EpiPE {    // n in [0,1024)
    __device__ void operator()(int, int m, int n, float4 v) const {
        int b = m >> 11, s = m & (SQ - 1);
        int h = n >> 7, r = n & 127;
        int bh = b * HH + h;
        if (r < HD) {
            long row = ((long)bh * SQ + s);
            *reinterpret_cast<uint2*>(&g_Qcat[row * 128 + HD + r]) =
                make_uint2(h2u(__floats2half2_rn(v.x * QK_SCALE_L2E, v.y * QK_SCALE_L2E)),
                           h2u(__floats2half2_rn(v.z * QK_SCALE_L2E, v.w * QK_SCALE_L2E)));
        } else {
            int d0 = r;
            int ck = s >> 6, rr = s & 63;
            long base = ((long)bh * 32 + ck) * 16384;
            unsigned off = (unsigned)((d0 >> 5) * 4096) + sw64(rr * 64 + (d0 & 31) * 2);
            *reinterpret_cast<uint2*>(reinterpret_cast<char*>(g_KH) + base + off) =
                make_uint2(h2u(__floats2half2_rn(v.x, v.y)),
                           h2u(__floats2half2_rn(v.z, v.w)));
        }
    }
};
struct EpiOut {
    float* out;
    __device__ void operator()(int, int m, int n, float4 v) const {
        *reinterpret_cast<float4*>(&out[(long)m * EMB + n]) = v;
    }
};

// ------------------------------ flash attention ----------------------------
// One CTA = 128 q-rows of one (b,h). 8 warps x 16 q-rows. KV chunk = 64 keys.
// Pipelined: softmax(ck) overlaps tensor-pipe drain of S(ck+1)/PV(ck).
// smem: KV ring x4 (24KB each) @0; bias ring x3 (34816 each) @98304.
__global__ void __launch_bounds__(256)
flash_attn(const unsigned short* __restrict__ Qc, const char* __restrict__ KH,
           const char* __restrict__ VH,
           const float* __restrict__ PE_r, unsigned short* __restrict__ vals)
{
    extern __shared__ __align__(1024) char smem[];
    constexpr int KVBUF = 24576;     // KH 16K | VH 8K
    constexpr int SBIAS = 98304, BIAS_STRIDE = 272, BIAS_BUF = 34816;
    constexpr int NCHUNK = SQ / 64;  // 32 (even)

    const int tid = threadIdx.x;
    const int l = tid & 31;
    const int w = tid >> 5;
    const int g = l >> 2;
    const int t = l & 3;
    const int bh = blockIdx.y;
    const int q0 = blockIdx.x * 128;
    const int qw = q0 + w * 16;
    const unsigned sbase = smem_u32(smem);

    const unsigned short* Qb = Qc + ((long)bh * SQ + qw) * 128;
    const char* KHb = KH + (long)bh * 32 * 16384;
    const char* VHb = VH + (long)bh * 32 * 8192;
    const float* Pb = PE_r + ((long)(bh & 7) * SQ + q0) * SQ;

    // ---- Q A-frags in registers (8 k16 steps, fp16, pre-scaled by s*log2e) ----
    unsigned qH[8][4];
#pragma unroll
    for (int kc = 0; kc < 8; kc++) {
        qH[kc][0] = *reinterpret_cast<const unsigned*>(Qb + (long)g * 128 + kc * 16 + 2 * t);
        qH[kc][1] = *reinterpret_cast<const unsigned*>(Qb + (long)(g + 8) * 128 + kc * 16 + 2 * t);
        qH[kc][2] = *reinterpret_cast<const unsigned*>(Qb + (long)g * 128 + kc * 16 + 8 + 2 * t);
        qH[kc][3] = *reinterpret_cast<const unsigned*>(Qb + (long)(g + 8) * 128 + kc * 16 + 8 + 2 * t);
    }

    float oacc[8][4];
#pragma unroll
    for (int j = 0; j < 8; j++)
#pragma unroll
        for (int k = 0; k < 4; k++) oacc[j][k] = 0.0f;
    float m0r = -1e30f, m1r = -1e30f, l0r = 0.0f, l1r = 0.0f;

    const int brow = (l & 7) + ((l >> 4) & 1) * 8;
    const int bkp  = ((l >> 3) & 1) * 16;

    auto prefetch = [&](int ck) {
        const unsigned sb = sbase + (ck & 3) * KVBUF;
        const char* kh = KHb + (long)ck * 16384;
        const char* vh = VHb + (long)ck * 8192;
#pragma unroll
        for (int it = 0; it < 4; it++) {
            int o = (tid + it * 256) * 16;
            CP_ASYNC16(sb + o, kh + o);
        }
#pragma unroll
        for (int it = 0; it < 2; it++) {
            int o = (tid + it * 256) * 16;
            CP_ASYNC16(sb + 16384 + o, vh + o);
        }
        const unsigned bb = sbase + SBIAS + (ck % 3) * BIAS_BUF;
#pragma unroll
        for (int it = 0; it < 8; it++) {
            int idx = tid + it * 256;
            int r = idx >> 4, c = idx & 15;
            CP_ASYNC16(bb + r * BIAS_STRIDE + c * 16,
                       Pb + (long)r * SQ + ck * 64 + c * 4);
        }
    };

    auto s_gemm = [&](float (&sacc)[8][4], int ck) {
        const unsigned kvb = sbase + (ck & 3) * KVBUF;
#pragma unroll
        for (int j = 0; j < 8; j++)
#pragma unroll
            for (int k = 0; k < 4; k++) sacc[j][k] = 0.0f;
#pragma unroll
        for (int kc = 0; kc < 8; kc++) {
            unsigned bH[4][4];
            const unsigned slab = kvb + (kc >> 1) * 4096;
            const unsigned koff = (kc & 1) * 32 + bkp;
#pragma unroll
            for (int p = 0; p < 4; p++) {
                unsigned sw = sw64((p * 16 + brow) * 64 + koff);
                LDSM4(bH[p][0], bH[p][1], bH[p][2], bH[p][3], slab + sw);
            }
#pragma unroll
            for (int j = 0; j < 8; j++) {
                const int p = j >> 1, h = (j & 1) * 2;
                MMA16816H(sacc[j], qH[kc], bH[p][h], bH[p][h + 1]);
            }
        }
    };

    // softmax in log2 domain (scores already scaled by log2e)
    auto softmax = [&](float (&sacc)[8][4], int ck) {
        const char* bb = smem + SBIAS + (ck % 3) * BIAS_BUF;
        const int r0 = w * 16 + g, r1 = r0 + 8;
#pragma unroll
        for (int j = 0; j < 8; j++) {
            float2 b0 = *reinterpret_cast<const float2*>(bb + r0 * BIAS_STRIDE + (j * 8 + 2 * t) * 4);
            float2 b1 = *reinterpret_cast<const float2*>(bb + r1 * BIAS_STRIDE + (j * 8 + 2 * t) * 4);
            sacc[j][0] = fmaf(b0.x, LOG2E, sacc[j][0]);
            sacc[j][1] = fmaf(b0.y, LOG2E, sacc[j][1]);
            sacc[j][2] = fmaf(b1.x, LOG2E, sacc[j][2]);
            sacc[j][3] = fmaf(b1.y, LOG2E, sacc[j][3]);
        }
        float mx0 = -1e30f, mx1 = -1e30f;
#pragma unroll
        for (int j = 0; j < 8; j++) {
            mx0 = fmaxf(mx0, fmaxf(sacc[j][0], sacc[j][1]));
            mx1 = fmaxf(mx1, fmaxf(sacc[j][2], sacc[j][3]));
        }
        mx0 = fmaxf(mx0, __shfl_xor_sync(0xffffffffu, mx0, 1));
        mx0 = fmaxf(mx0, __shfl_xor_sync(0xffffffffu, mx0, 2));
        mx1 = fmaxf(mx1, __shfl_xor_sync(0xffffffffu, mx1, 1));
        mx1 = fmaxf(mx1, __shfl_xor_sync(0xffffffffu, mx1, 2));

        const float mn0 = fmaxf(m0r, mx0), mn1 = fmaxf(m1r, mx1);
        const float cor0 = ex2f(m0r - mn0), cor1 = ex2f(m1r - mn1);
        m0r = mn0; m1r = mn1;

        float sum0 = 0.0f, sum1 = 0.0f;
#pragma unroll
        for (int j = 0; j < 8; j++) {
            sacc[j][0] = ex2f(sacc[j][0] - mn0);
            sacc[j][1] = ex2f(sacc[j][1] - mn0);
            sacc[j][2] = ex2f(sacc[j][2] - mn1);
            sacc[j][3] = ex2f(sacc[j][3] - mn1);
            sum0 += sacc[j][0] + sacc[j][1];
            sum1 += sacc[j][2] + sacc[j][3];
        }
        sum0 += __shfl_xor_sync(0xffffffffu, sum0, 1);
        sum0 += __shfl_xor_sync(0xffffffffu, sum0, 2);
        sum1 += __shfl_xor_sync(0xffffffffu, sum1, 1);
        sum1 += __shfl_xor_sync(0xffffffffu, sum1, 2);
        l0r = l0r * cor0 + sum0;
        l1r = l1r * cor1 + sum1;

#pragma unroll
        for (int j = 0; j < 8; j++) {
            oacc[j][0] *= cor0; oacc[j][1] *= cor0;
            oacc[j][2] *= cor1; oacc[j][3] *= cor1;
        }
    };

    auto pv = [&](float (&sacc)[8][4], int ck) {
        const unsigned kvb = sbase + (ck & 3) * KVBUF;
#pragma unroll
        for (int kk = 0; kk < 4; kk++) {
            unsigned pH[4];
            pH[0] = h2u(__floats2half2_rn(sacc[2 * kk][0],     sacc[2 * kk][1]));
            pH[1] = h2u(__floats2half2_rn(sacc[2 * kk][2],     sacc[2 * kk][3]));
            pH[2] = h2u(__floats2half2_rn(sacc[2 * kk + 1][0], sacc[2 * kk + 1][1]));
            pH[3] = h2u(__floats2half2_rn(sacc[2 * kk + 1][2], sacc[2 * kk + 1][3]));

            unsigned vHf[4][4];
            const unsigned slab = kvb + 16384 + (kk >> 1) * 4096;
            const unsigned koff = (kk & 1) * 32 + bkp;
#pragma unroll
            for (int p = 0; p < 4; p++) {
                unsigned sw = sw64((p * 16 + brow) * 64 + koff);
                LDSM4(vHf[p][0], vHf[p][1], vHf[p][2], vHf[p][3], slab + sw);
            }
#pragma unroll
            for (int j = 0; j < 8; j++) {
                const int p = j >> 1, h = (j & 1) * 2;
                MMA16816H(oacc[j], pH, vHf[p][h], vHf[p][h + 1]);
            }
        }
    };

    float sE[8][4], sO[8][4];

    prefetch(0); CP_COMMIT();
    prefetch(1); CP_COMMIT();
    CP_WAIT1();                 // group 0 complete
    __syncthreads();
    s_gemm(sE, 0);

    for (int ck = 0; ck < NCHUNK; ck += 2) {
        // ---- even phase (ck) ----
        if (ck + 2 < NCHUNK) { prefetch(ck + 2); CP_COMMIT(); }
        softmax(sE, ck);
        if (ck + 2 < NCHUNK) CP_WAIT1(); else CP_WAIT0();
        __syncthreads();
        s_gemm(sO, ck + 1);     // overlaps with softmax ALU retire + PV below
        pv(sE, ck);

        // ---- odd phase (ck+1) ----
        if (ck + 3 < NCHUNK) { prefetch(ck + 3); CP_COMMIT(); }
        softmax(sO, ck + 1);
        if (ck + 3 < NCHUNK) CP_WAIT1(); else CP_WAIT0();
        __syncthreads();
        if (ck + 2 < NCHUNK) s_gemm(sE, ck + 2);
        pv(sO, ck + 1);
    }

    // ---- epilogue: out = oacc / l, fp16 to g_vals ----
    const float inv0 = 1.0f / l0r, inv1 = 1.0f / l1r;
    const int b = bh >> 3, h = bh & 7;
    const long row0 = (long)(b * SQ + qw + g) * EMB + h * HD;
    const long row1 = (long)(b * SQ + qw + g + 8) * EMB + h * HD;
#pragma unroll
    for (int j = 0; j < 8; j++) {
        int col = j * 8 + 2 * t;
        *reinterpret_cast<unsigned*>(&vals[row0 + col]) =
            h2u(__floats2half2_rn(oacc[j][0] * inv0, oacc[j][1] * inv0));
        *reinterpret_cast<unsigned*>(&vals[row1 + col]) =
            h2u(__floats2half2_rn(oacc[j][2] * inv1, oacc[j][3] * inv1));
    }
}

// ------------------------------ launch -------------------------------------
template <typename Epi>
static void launch_gemm(dim3 grid, const unsigned short* A, const unsigned short* B,
                        int K, int lda, int ldb, long sA, long sB, Epi epi)
{
    gemm_fp16s<Epi><<<grid, 256, 34816>>>(A, B, K, lda, ldb, sA, sB, epi);
}

extern "C" void kernel_launch(void* const* d_in, const int* in_sizes, int n_in,
                              void* d_out, int out_size)
{
    const float* x    = (const float*)d_in[0];
    const float* PE   = (const float*)d_in[1];
    const float* PE_r = (const float*)d_in[2];
    const float* Wqkv = (const float*)d_in[3];
    const float* UqUk = (const float*)d_in[4];
    const float* Wo   = (const float*)d_in[5];
    float* out = (float*)d_out;

    void* p;
    cudaGetSymbolAddress(&p, g_x2);   unsigned short* x2  = (unsigned short*)p;
    cudaGetSymbolAddress(&p, g_PE2);  unsigned short* pe2 = (unsigned short*)p;
    cudaGetSymbolAddress(&p, g_W2);   unsigned short* w2  = (unsigned short*)p;
    cudaGetSymbolAddress(&p, g_U2);   unsigned short* u2  = (unsigned short*)p;
    cudaGetSymbolAddress(&p, g_Wo2);  unsigned short* wo2 = (unsigned short*)p;
    cudaGetSymbolAddress(&p, g_Qcat); unsigned short* Qc  = (unsigned short*)p;
    cudaGetSymbolAddress(&p, g_KH);   char* KH = (char*)p;
    cudaGetSymbolAddress(&p, g_VH);   char* VH = (char*)p;
    cudaGetSymbolAddress(&p, g_vals); unsigned short* Vl = (unsigned short*)p;

    // 0) single merged pack of all five inputs (9728 blocks covers 2,490,368 float4s)
    pack_all_kernel<<<9728, 256>>>((const float4*)x, (const float4*)PE,
                                   (const float4*)Wqkv, (const float4*)UqUk,
                                   (const float4*)Wo,
                                   (uint2*)x2, (uint2*)pe2,
                                   (uint2*)w2, (uint2*)u2, (uint2*)wo2);

    // 1) qkv projection (writes Q scaled fp16, K/V fp16 images)
    launch_gemm(dim3(24, 64, 1), x2, w2, EMB, EMB, EMB, 0, 0, EpiQKV{});
    // 2) positional projection
    launch_gemm(dim3(16, 64, 1), pe2, u2, EMB, EMB, EMB, 0, 0, EpiPE{});
    // 3) fused attention (pipelined)
    cudaFuncSetAttribute(flash_attn, cudaFuncAttributeMaxDynamicSharedMemorySize, 202752);
    flash_attn<<<dim3(SQ / 128, BB * HH), 256, 202752>>>(Qc, KH, VH, PE_r, Vl);
    // 4) out projection
    launch_gemm(dim3(8, 64, 1), Vl, wo2, EMB, EMB, EMB, 0, 0, EpiOut{out});
}

// round 12
// speedup vs baseline: 3.7238x; 1.0608x over previous
#include <cuda_runtime.h>
#include <cuda_fp16.h>
#include <cstdint>

// ---------------------------------------------------------------------------
// TUPE multihead attention — plain fp16 HMMA (fp32 accumulate) everywhere.
//  Flash middle: 2 CTAs/SM (inter-CTA latency hiding). KV double-buffered
//  cp.async; PE_r bias pre-packed fp16 (x log2e) and double-buffered;
//  softmax in log2 domain (ex2.approx).
// ---------------------------------------------------------------------------

static constexpr int BB  = 4;
static constexpr int HH  = 8;
static constexpr int SQ  = 2048;
static constexpr int EMB = 512;
static constexpr int HD  = 64;
static constexpr float LOG2E = 1.4426950408889634f;
static constexpr float QK_SCALE_L2E = 0.0883883476483184f * LOG2E;

// ------------------------------ scratch ------------------------------------
__device__ __align__(16) unsigned short g_x2  [(size_t)BB * SQ * EMB];
__device__ __align__(16) unsigned short g_PE2 [(size_t)BB * SQ * EMB];
__device__ __align__(16) unsigned short g_W2  [(size_t)3 * EMB * EMB];
__device__ __align__(16) unsigned short g_U2  [(size_t)2 * EMB * EMB];
__device__ __align__(16) unsigned short g_Wo2 [(size_t)EMB * EMB];
__device__ __align__(16) unsigned short g_PEr16[(size_t)HH * SQ * SQ];      // fp16, x log2e
__device__ __align__(16) unsigned short g_Qcat[(size_t)BB * HH * SQ * 128]; // fp16 (x s*log2e)
__device__ __align__(16) unsigned short g_KH[(size_t)BB * HH * SQ * 128];   // K image sw64
__device__ __align__(16) unsigned short g_VH[(size_t)BB * HH * HD * SQ];    // V image sw64
__device__ __align__(16) unsigned short g_vals[(size_t)BB * SQ * EMB];

// ------------------------------ helpers ------------------------------------
__device__ __forceinline__ unsigned smem_u32(const void* p) {
    unsigned a;
    asm("{ .reg .u64 t; cvta.to.shared.u64 t, %1; cvt.u32.u64 %0, t; }" : "=r"(a) : "l"(p));
    return a;
}
__device__ __forceinline__ unsigned h2u(__half2 h) {
    return *reinterpret_cast<unsigned*>(&h);
}
__device__ __forceinline__ float ex2f(float x) {
    float r;
    asm("ex2.approx.f32 %0, %1;" : "=f"(r) : "f"(x));
    return r;
}

// merged pack: five f32 inputs -> fp16, segment dispatch by index
__global__ void __launch_bounds__(256)
pack_all_kernel(const float4* __restrict__ x,  const float4* __restrict__ pe,
                const float4* __restrict__ w,  const float4* __restrict__ u,
                const float4* __restrict__ wo,
                uint2* __restrict__ ox, uint2* __restrict__ ope,
                uint2* __restrict__ ow, uint2* __restrict__ ou,
                uint2* __restrict__ owo)
{
    const int N0 = 1048576, N1 = 2097152, N2 = 2293760, N3 = 2424832, N4 = 2490368;
    int i = blockIdx.x * 256 + threadIdx.x;
    if (i >= N4) return;
    const float4* src; uint2* dst; int j;
    if (i < N0)      { src = x;  dst = ox;  j = i; }
    else if (i < N1) { src = pe; dst = ope; j = i - N0; }
    else if (i < N2) { src = w;  dst = ow;  j = i - N1; }
    else if (i < N3) { src = u;  dst = ou;  j = i - N2; }
    else             { src = wo; dst = owo; j = i - N3; }
    float4 v = src[j];
    dst[j] = make_uint2(h2u(__floats2half2_rn(v.x, v.y)),
                        h2u(__floats2half2_rn(v.z, v.w)));
}

// PE_r f32 -> fp16 scaled by log2e
__global__ void __launch_bounds__(256)
pack_bias_kernel(const float4* __restrict__ in, uint2* __restrict__ out, int n4)
{
    int i = blockIdx.x * 256 + threadIdx.x;
    if (i < n4) {
        float4 v = in[i];
        out[i] = make_uint2(h2u(__floats2half2_rn(v.x * LOG2E, v.y * LOG2E)),
                            h2u(__floats2half2_rn(v.z * LOG2E, v.w * LOG2E)));
    }
}

#define LDSM4(r0, r1, r2, r3, a)                                              \
    asm volatile("ldmatrix.sync.aligned.m8n8.x4.shared.b16 {%0,%1,%2,%3}, [%4];" \
                 : "=r"(r0), "=r"(r1), "=r"(r2), "=r"(r3) : "r"(a))

#define MMA16816H(c, a, b0, b1)                                               \
    asm volatile("mma.sync.aligned.m16n8k16.row.col.f32.f16.f16.f32 "         \
                 "{%0,%1,%2,%3}, {%4,%5,%6,%7}, {%8,%9}, {%0,%1,%2,%3};"      \
                 : "+f"((c)[0]), "+f"((c)[1]), "+f"((c)[2]), "+f"((c)[3])     \
                 : "r"((a)[0]), "r"((a)[1]), "r"((a)[2]), "r"((a)[3]),        \
                   "r"(b0), "r"(b1))

#define CP_ASYNC16(dst, src) \
    asm volatile("cp.async.cg.shared.global [%0], [%1], 16;" :: "r"(dst), "l"(src))
#define CP_COMMIT() asm volatile("cp.async.commit_group;" ::: "memory")
#define CP_WAIT0()  asm volatile("cp.async.wait_group 0;" ::: "memory")
#define CP_WAIT1()  asm volatile("cp.async.wait_group 1;" ::: "memory")

__device__ __forceinline__ unsigned sw64(unsigned off)  { return off ^ ((off >> 3) & 0x30); }

// ------------------------------ GEMM (projections / out) -------------------
// C[128 x 64]; A fp16 [M,K]; B fp16 [N,K]; K mult of 32.  (round-10, proven)
template <typename Epi>
__global__ void __launch_bounds__(256, 2)
gemm_fp16s(const unsigned short* __restrict__ A, const unsigned short* __restrict__ B,
           int K, int lda, int ldb, long sA, long sB, Epi epi)
{
    extern __shared__ __align__(1024) char smem[];
    constexpr int SB = 8192, STAGE = 12288;

    const int tid = threadIdx.x;
    const int l   = tid & 31;
    const int w   = tid >> 5;
    const int wm  = w & 3;
    const int wn  = w >> 2;
    const int m0  = wm * 32;
    const int n0  = wn * 32;
    const int bz  = blockIdx.z;
    const unsigned sbase = smem_u32(smem);

    const unsigned short* Ab = A + bz * sA + (long)blockIdx.y * 128 * lda;
    const unsigned short* Bb = B + bz * sB + (long)blockIdx.x * 64 * ldb;

    float acc[2][4][4];
#pragma unroll
    for (int i = 0; i < 2; i++)
#pragma unroll
        for (int j = 0; j < 4; j++)
#pragma unroll
            for (int k = 0; k < 4; k++) acc[i][j][k] = 0.0f;

    const int arow = (l & 7) + ((l >> 3) & 1) * 8;
    const int akp  = ((l >> 4) & 1) * 16;
    const int brow = (l & 7) + ((l >> 4) & 1) * 8;
    const int bkp  = ((l >> 3) & 1) * 16;

    uint4 ra[2], rb;
    const int nChunks = K >> 5;

    auto load_global = [&](int c) {
#pragma unroll
        for (int it = 0; it < 2; it++) {
            int idx = tid + it * 256;
            int r = idx >> 2, q = idx & 3;
            ra[it] = *reinterpret_cast<const uint4*>(Ab + (long)r * lda + c * 32 + q * 8);
        }
        {
            int r = tid >> 2, q = tid & 3;
            rb = *reinterpret_cast<const uint4*>(Bb + (long)r * ldb + c * 32 + q * 8);
        }
    };
    auto store_stage = [&](char* buf) {
#pragma unroll
        for (int it = 0; it < 2; it++) {
            int idx = tid + it * 256;
            int r = idx >> 2, q = idx & 3;
            *reinterpret_cast<uint4*>(buf + sw64(r * 64 + q * 16)) = ra[it];
        }
        {
            int r = tid >> 2, q = tid & 3;
            *reinterpret_cast<uint4*>(buf + SB + sw64(r * 64 + q * 16)) = rb;
        }
    };

    load_global(0);
    store_stage(smem);
    __syncthreads();

    for (int c = 0; c < nChunks; c++) {
        const bool more = (c + 1) < nChunks;
        if (more) load_global(c + 1);

        const unsigned stage = sbase + (c & 1) * STAGE;
#pragma unroll
        for (int ks = 0; ks < 2; ks++) {
            unsigned aH[2][4], bH[2][4];
#pragma unroll
            for (int i = 0; i < 2; i++) {
                unsigned off = (m0 + i * 16 + arow) * 64 + ks * 32 + akp;
                LDSM4(aH[i][0], aH[i][1], aH[i][2], aH[i][3], stage + sw64(off));
            }
#pragma unroll
            for (int p = 0; p < 2; p++) {
                unsigned off = (n0 + p * 16 + brow) * 64 + ks * 32 + bkp;
                LDSM4(bH[p][0], bH[p][1], bH[p][2], bH[p][3], stage + SB + sw64(off));
            }
#pragma unroll
            for (int i = 0; i < 2; i++)
#pragma unroll
                for (int j = 0; j < 4; j++) {
                    const int p = j >> 1, h = (j & 1) * 2;
                    MMA16816H(acc[i][j], aH[i], bH[p][h], bH[p][h + 1]);
                }
        }

        if (more) store_stage(smem + ((c + 1) & 1) * STAGE);
        __syncthreads();
    }

    float* C = reinterpret_cast<float*>(smem);   // [128][68]
#pragma unroll
    for (int i = 0; i < 2; i++)
#pragma unroll
        for (int j = 0; j < 4; j++) {
            int r0  = m0 + i * 16 + (l >> 2);
            int col = n0 + j * 8 + (l & 3) * 2;
            *reinterpret_cast<float2*>(C + r0 * 68 + col)       = make_float2(acc[i][j][0], acc[i][j][1]);
            *reinterpret_cast<float2*>(C + (r0 + 8) * 68 + col) = make_float2(acc[i][j][2], acc[i][j][3]);
        }
    __syncthreads();

    {
        int r = tid >> 1, seg = (tid & 1) << 5;
        int m  = blockIdx.y * 128 + r;
        int nb = blockIdx.x * 64 + seg;
        const float* Crow = C + r * 68 + seg;
#pragma unroll
        for (int i = 0; i < 8; i++) {
            float4 v = *reinterpret_cast<const float4*>(Crow + i * 4);
            epi(bz, m, nb + i * 4, v);
        }
    }
}

// ------------------------------ epilogues ----------------------------------
struct EpiQKV {   // m in [0,8192), n in [0,1536)
    __device__ void operator()(int, int m, int n, float4 v) const {
        int b = m >> 11, s = m & (SQ - 1);
        int h = n / 192, r = n - h * 192;
        int bh = b * HH + h;
        if (r < HD) {
            long row = ((long)bh * SQ + s);
            *reinterpret_cast<uint2*>(&g_Qcat[row * 128 + r]) =
                make_uint2(h2u(__floats2half2_rn(v.x * QK_SCALE_L2E, v.y * QK_SCALE_L2E)),
                           h2u(__floats2half2_rn(v.z * QK_SCALE_L2E, v.w * QK_SCALE_L2E)));
        } else if (r < 2 * HD) {
            int d0 = r - HD;
            int ck = s >> 6, rr = s & 63;
            long base = ((long)bh * 32 + ck) * 16384;
            unsigned off = (unsigned)((d0 >> 5) * 4096) + sw64(rr * 64 + (d0 & 31) * 2);
            *reinterpret_cast<uint2*>(reinterpret_cast<char*>(g_KH) + base + off) =
                make_uint2(h2u(__floats2half2_rn(v.x, v.y)),
                           h2u(__floats2half2_rn(v.z, v.w)));
        } else {
            int d = r - 2 * HD;
            int ck = s >> 6, kc = s & 63;
            long base = ((long)bh * 32 + ck) * 8192 + (kc >> 5) * 4096;
            int kb = (kc & 31) * 2;
#pragma unroll
            for (int i = 0; i < 4; i++) {
                float val = (&v.x)[i];
                unsigned off2 = sw64((d + i) * 64 + kb);
                *reinterpret_cast<__half*>(reinterpret_cast<char*>(g_VH) + base + off2) =
                    __float2half(val);
            }
        }
    }
};
struct EpiPE {    // n in [0,1024)
    __device__ void operator()(int, int m, int n, float4 v) const {
        int b = m >> 11, s = m & (SQ - 1);
        int h = n >> 7, r = n & 127;
        int bh = b * HH + h;
        if (r < HD) {
            long row = ((long)bh * SQ + s);
            *reinterpret_cast<uint2*>(&g_Qcat[row * 128 + HD + r]) =
                make_uint2(h2u(__floats2half2_rn(v.x * QK_SCALE_L2E, v.y * QK_SCALE_L2E)),
                           h2u(__floats2half2_rn(v.z * QK_SCALE_L2E, v.w * QK_SCALE_L2E)));
        } else {
            int d0 = r;
            int ck = s >> 6, rr = s & 63;
            long base = ((long)bh * 32 + ck) * 16384;
            unsigned off = (unsigned)((d0 >> 5) * 4096) + sw64(rr * 64 + (d0 & 31) * 2);
            *reinterpret_cast<uint2*>(reinterpret_cast<char*>(g_KH) + base + off) =
                make_uint2(h2u(__floats2half2_rn(v.x, v.y)),
                           h2u(__floats2half2_rn(v.z, v.w)));
        }
    }
};
struct EpiOut {
    float* out;
    __device__ void operator()(int, int m, int n, float4 v) const {
        *reinterpret_cast<float4*>(&out[(long)m * EMB + n]) = v;
    }
};

// ------------------------------ flash attention ----------------------------
// One CTA = 128 q-rows of one (b,h). 8 warps x 16 q-rows. KV chunk = 64 keys.
// 2 CTAs/SM: smem 86KB (KV x2 @0, fp16 bias x2 @49152), regs capped at 128.
__global__ void __launch_bounds__(256, 2)
flash_attn(const unsigned short* __restrict__ Qc, const char* __restrict__ KH,
           const char* __restrict__ VH, const char* __restrict__ PEr,
           unsigned short* __restrict__ vals)
{
    extern __shared__ __align__(1024) char smem[];
    constexpr int KVBUF = 24576;     // KH 16K | VH 8K
    constexpr int SBIAS = 49152, BIAS_STRIDE = 144, BIAS_BUF = 18432;
    constexpr int NCHUNK = SQ / 64;  // 32

    const int tid = threadIdx.x;
    const int l = tid & 31;
    const int w = tid >> 5;
    const int g = l >> 2;
    const int t = l & 3;
    const int bh = blockIdx.y;
    const int q0 = blockIdx.x * 128;
    const int qw = q0 + w * 16;
    const unsigned sbase = smem_u32(smem);

    const unsigned short* Qb = Qc + ((long)bh * SQ + qw) * 128;
    const char* KHb = KH + (long)bh * 32 * 16384;
    const char* VHb = VH + (long)bh * 32 * 8192;
    const char* Pb = PEr + (((long)(bh & 7) * SQ + q0) * SQ) * 2;   // fp16 bias

    // ---- Q A-frags in registers (8 k16 steps, fp16, pre-scaled) ----
    unsigned qH[8][4];
#pragma unroll
    for (int kc = 0; kc < 8; kc++) {
        qH[kc][0] = *reinterpret_cast<const unsigned*>(Qb + (long)g * 128 + kc * 16 + 2 * t);
        qH[kc][1] = *reinterpret_cast<const unsigned*>(Qb + (long)(g + 8) * 128 + kc * 16 + 2 * t);
        qH[kc][2] = *reinterpret_cast<const unsigned*>(Qb + (long)g * 128 + kc * 16 + 8 + 2 * t);
        qH[kc][3] = *reinterpret_cast<const unsigned*>(Qb + (long)(g + 8) * 128 + kc * 16 + 8 + 2 * t);
    }

    float oacc[8][4];
#pragma unroll
    for (int j = 0; j < 8; j++)
#pragma unroll
        for (int k = 0; k < 4; k++) oacc[j][k] = 0.0f;
    float m0r = -1e30f, m1r = -1e30f, l0r = 0.0f, l1r = 0.0f;

    const int brow = (l & 7) + ((l >> 4) & 1) * 8;
    const int bkp  = ((l >> 3) & 1) * 16;

    auto prefetch = [&](int ck) {
        const int buf = ck & 1;
        const unsigned sb = sbase + buf * KVBUF;
        const char* kh = KHb + (long)ck * 16384;
        const char* vh = VHb + (long)ck * 8192;
#pragma unroll
        for (int it = 0; it < 4; it++) {
            int o = (tid + it * 256) * 16;
            CP_ASYNC16(sb + o, kh + o);
        }
#pragma unroll
        for (int it = 0; it < 2; it++) {
            int o = (tid + it * 256) * 16;
            CP_ASYNC16(sb + 16384 + o, vh + o);
        }
        // bias tile: 128 rows x 64 fp16 (128B) per chunk
        const unsigned bb = sbase + SBIAS + buf * BIAS_BUF;
#pragma unroll
        for (int it = 0; it < 4; it++) {
            int idx = tid + it * 256;
            int r = idx >> 3, c = idx & 7;
            CP_ASYNC16(bb + r * BIAS_STRIDE + c * 16,
                       Pb + ((long)r * SQ + ck * 64 + c * 8) * 2);
        }
    };

    prefetch(0);
    CP_COMMIT();

    for (int ck = 0; ck < NCHUNK; ck++) {
        if (ck + 1 < NCHUNK) {
            prefetch(ck + 1);
            CP_COMMIT();
            CP_WAIT1();
        } else {
            CP_WAIT0();
        }
        __syncthreads();

        const int buf = ck & 1;
        const unsigned kvb = sbase + buf * KVBUF;

        // ---- S = qh * kh : 1 mma per step (log2-domain scores) ----
        float sacc[8][4];
#pragma unroll
        for (int j = 0; j < 8; j++)
#pragma unroll
            for (int k = 0; k < 4; k++) sacc[j][k] = 0.0f;

#pragma unroll
        for (int kc = 0; kc < 8; kc++) {
            unsigned bH[4][4];
            const unsigned slab = kvb + (kc >> 1) * 4096;
            const unsigned koff = (kc & 1) * 32 + bkp;
#pragma unroll
            for (int p = 0; p < 4; p++) {
                unsigned sw = sw64((p * 16 + brow) * 64 + koff);
                LDSM4(bH[p][0], bH[p][1], bH[p][2], bH[p][3], slab + sw);
            }
#pragma unroll
            for (int j = 0; j < 8; j++) {
                const int p = j >> 1, h = (j & 1) * 2;
                MMA16816H(sacc[j], qH[kc], bH[p][h], bH[p][h + 1]);
            }
        }

        // ---- bias add (fp16 smem, already x log2e) ----
        {
            const char* bb = smem + SBIAS + buf * BIAS_BUF;
            const int r0 = w * 16 + g, r1 = r0 + 8;
#pragma unroll
            for (int j = 0; j < 8; j++) {
                float2 b0 = __half22float2(*reinterpret_cast<const __half2*>(
                    bb + r0 * BIAS_STRIDE + (j * 8 + 2 * t) * 2));
                float2 b1 = __half22float2(*reinterpret_cast<const __half2*>(
                    bb + r1 * BIAS_STRIDE + (j * 8 + 2 * t) * 2));
                sacc[j][0] += b0.x; sacc[j][1] += b0.y;
                sacc[j][2] += b1.x; sacc[j][3] += b1.y;
            }
        }

        // ---- online softmax (log2 domain) ----
        float mx0 = -1e30f, mx1 = -1e30f;
#pragma unroll
        for (int j = 0; j < 8; j++) {
            mx0 = fmaxf(mx0, fmaxf(sacc[j][0], sacc[j][1]));
            mx1 = fmaxf(mx1, fmaxf(sacc[j][2], sacc[j][3]));
        }
        mx0 = fmaxf(mx0, __shfl_xor_sync(0xffffffffu, mx0, 1));
        mx0 = fmaxf(mx0, __shfl_xor_sync(0xffffffffu, mx0, 2));
        mx1 = fmaxf(mx1, __shfl_xor_sync(0xffffffffu, mx1, 1));
        mx1 = fmaxf(mx1, __shfl_xor_sync(0xffffffffu, mx1, 2));

        const float mn0 = fmaxf(m0r, mx0), mn1 = fmaxf(m1r, mx1);
        const float cor0 = ex2f(m0r - mn0), cor1 = ex2f(m1r - mn1);
        m0r = mn0; m1r = mn1;

        float sum0 = 0.0f, sum1 = 0.0f;
#pragma unroll
        for (int j = 0; j < 8; j++) {
            sacc[j][0] = ex2f(sacc[j][0] - mn0);
            sacc[j][1] = ex2f(sacc[j][1] - mn0);
            sacc[j][2] = ex2f(sacc[j][2] - mn1);
            sacc[j][3] = ex2f(sacc[j][3] - mn1);
            sum0 += sacc[j][0] + sacc[j][1];
            sum1 += sacc[j][2] + sacc[j][3];
        }
        sum0 += __shfl_xor_sync(0xffffffffu, sum0, 1);
        sum0 += __shfl_xor_sync(0xffffffffu, sum0, 2);
        sum1 += __shfl_xor_sync(0xffffffffu, sum1, 1);
        sum1 += __shfl_xor_sync(0xffffffffu, sum1, 2);
        l0r = l0r * cor0 + sum0;
        l1r = l1r * cor1 + sum1;

#pragma unroll
        for (int j = 0; j < 8; j++) {
            oacc[j][0] *= cor0; oacc[j][1] *= cor0;
            oacc[j][2] *= cor1; oacc[j][3] *= cor1;
        }

        // ---- PV: oacc += p * vh ----
#pragma unroll
        for (int kk = 0; kk < 4; kk++) {
            unsigned pH[4];
            pH[0] = h2u(__floats2half2_rn(sacc[2 * kk][0],     sacc[2 * kk][1]));
            pH[1] = h2u(__floats2half2_rn(sacc[2 * kk][2],     sacc[2 * kk][3]));
            pH[2] = h2u(__floats2half2_rn(sacc[2 * kk + 1][0], sacc[2 * kk + 1][1]));
            pH[3] = h2u(__floats2half2_rn(sacc[2 * kk + 1][2], sacc[2 * kk + 1][3]));

            unsigned vHf[4][4];
            const unsigned slab = kvb + 16384 + (kk >> 1) * 4096;
            const unsigned koff = (kk & 1) * 32 + bkp;
#pragma unroll
            for (int p = 0; p < 4; p++) {
                unsigned sw = sw64((p * 16 + brow) * 64 + koff);
                LDSM4(vHf[p][0], vHf[p][1], vHf[p][2], vHf[p][3], slab + sw);
            }
#pragma unroll
            for (int j = 0; j < 8; j++) {
                const int p = j >> 1, h = (j & 1) * 2;
                MMA16816H(oacc[j], pH, vHf[p][h], vHf[p][h + 1]);
            }
        }

        __syncthreads();
    }

    // ---- epilogue: out = oacc / l, fp16 to g_vals ----
    const float inv0 = 1.0f / l0r, inv1 = 1.0f / l1r;
    const int b = bh >> 3, h = bh & 7;
    const long row0 = (long)(b * SQ + qw + g) * EMB + h * HD;
    const long row1 = (long)(b * SQ + qw + g + 8) * EMB + h * HD;
#pragma unroll
    for (int j = 0; j < 8; j++) {
        int col = j * 8 + 2 * t;
        *reinterpret_cast<unsigned*>(&vals[row0 + col]) =
            h2u(__floats2half2_rn(oacc[j][0] * inv0, oacc[j][1] * inv0));
        *reinterpret_cast<unsigned*>(&vals[row1 + col]) =
            h2u(__floats2half2_rn(oacc[j][2] * inv1, oacc[j][3] * inv1));
    }
}

// ------------------------------ launch -------------------------------------
template <typename Epi>
static void launch_gemm(dim3 grid, const unsigned short* A, const unsigned short* B,
                        int K, int lda, int ldb, long sA, long sB, Epi epi)
{
    gemm_fp16s<Epi><<<grid, 256, 34816>>>(A, B, K, lda, ldb, sA, sB, epi);
}

extern "C" void kernel_launch(void* const* d_in, const int* in_sizes, int n_in,
                              void* d_out, int out_size)
{
    const float* x    = (const float*)d_in[0];
    const float* PE   = (const float*)d_in[1];
    const float* PE_r = (const float*)d_in[2];
    const float* Wqkv = (const float*)d_in[3];
    const float* UqUk = (const float*)d_in[4];
    const float* Wo   = (const float*)d_in[5];
    float* out = (float*)d_out;

    void* p;
    cudaGetSymbolAddress(&p, g_x2);    unsigned short* x2  = (unsigned short*)p;
    cudaGetSymbolAddress(&p, g_PE2);   unsigned short* pe2 = (unsigned short*)p;
    cudaGetSymbolAddress(&p, g_W2);    unsigned short* w2  = (unsigned short*)p;
    cudaGetSymbolAddress(&p, g_U2);    unsigned short* u2  = (unsigned short*)p;
    cudaGetSymbolAddress(&p, g_Wo2);   unsigned short* wo2 = (unsigned short*)p;
    cudaGetSymbolAddress(&p, g_PEr16); unsigned short* pr16 = (unsigned short*)p;
    cudaGetSymbolAddress(&p, g_Qcat);  unsigned short* Qc  = (unsigned short*)p;
    cudaGetSymbolAddress(&p, g_KH);    char* KH = (char*)p;
    cudaGetSymbolAddress(&p, g_VH);    char* VH = (char*)p;
    cudaGetSymbolAddress(&p, g_vals);  unsigned short* Vl = (unsigned short*)p;

    // 0) packs
    pack_all_kernel<<<9728, 256>>>((const float4*)x, (const float4*)PE,
                                   (const float4*)Wqkv, (const float4*)UqUk,
                                   (const float4*)Wo,
                                   (uint2*)x2, (uint2*)pe2,
                                   (uint2*)w2, (uint2*)u2, (uint2*)wo2);
    pack_bias_kernel<<<32768, 256>>>((const float4*)PE_r, (uint2*)pr16,
                                     (int)((size_t)HH * SQ * SQ / 4));

    // 1) qkv projection (writes Q scaled fp16, K/V fp16 images)
    launch_gemm(dim3(24, 64, 1), x2, w2, EMB, EMB, EMB, 0, 0, EpiQKV{});
    // 2) positional projection
    launch_gemm(dim3(16, 64, 1), pe2, u2, EMB, EMB, EMB, 0, 0, EpiPE{});
    // 3) fused attention (2 CTAs/SM)
    cudaFuncSetAttribute(flash_attn, cudaFuncAttributeMaxDynamicSharedMemorySize, 86016);
    flash_attn<<<dim3(SQ / 128, BB * HH), 256, 86016>>>(Qc, KH, VH, (const char*)pr16, Vl);
    // 4) out projection
    launch_gemm(dim3(8, 64, 1), Vl, wo2, EMB, EMB, EMB, 0, 0, EpiOut{out});
}

// round 13
// speedup vs baseline: 4.1485x; 1.1140x over previous
#include <cuda_runtime.h>
#include <cuda_fp16.h>
#include <cstdint>

// ---------------------------------------------------------------------------
// TUPE multihead attention — plain fp16 HMMA (fp32 accumulate) everywhere.
//  Projections: 128x128x32 tile, warp 32x64, cp.async double-buffered.
//  Flash middle: 2 CTAs/SM, KV + fp16 bias double-buffered (round 12, proven).
// ---------------------------------------------------------------------------

static constexpr int BB  = 4;
static constexpr int HH  = 8;
static constexpr int SQ  = 2048;
static constexpr int EMB = 512;
static constexpr int HD  = 64;
static constexpr float LOG2E = 1.4426950408889634f;
static constexpr float QK_SCALE_L2E = 0.0883883476483184f * LOG2E;

// ------------------------------ scratch ------------------------------------
__device__ __align__(16) unsigned short g_x2  [(size_t)BB * SQ * EMB];
__device__ __align__(16) unsigned short g_PE2 [(size_t)BB * SQ * EMB];
__device__ __align__(16) unsigned short g_W2  [(size_t)3 * EMB * EMB];
__device__ __align__(16) unsigned short g_U2  [(size_t)2 * EMB * EMB];
__device__ __align__(16) unsigned short g_Wo2 [(size_t)EMB * EMB];
__device__ __align__(16) unsigned short g_PEr16[(size_t)HH * SQ * SQ];      // fp16, x log2e
__device__ __align__(16) unsigned short g_Qcat[(size_t)BB * HH * SQ * 128]; // fp16 (x s*log2e)
__device__ __align__(16) unsigned short g_KH[(size_t)BB * HH * SQ * 128];   // K image sw64
__device__ __align__(16) unsigned short g_VH[(size_t)BB * HH * HD * SQ];    // V image sw64
__device__ __align__(16) unsigned short g_vals[(size_t)BB * SQ * EMB];

// ------------------------------ helpers ------------------------------------
__device__ __forceinline__ unsigned smem_u32(const void* p) {
    unsigned a;
    asm("{ .reg .u64 t; cvta.to.shared.u64 t, %1; cvt.u32.u64 %0, t; }" : "=r"(a) : "l"(p));
    return a;
}
__device__ __forceinline__ unsigned h2u(__half2 h) {
    return *reinterpret_cast<unsigned*>(&h);
}
__device__ __forceinline__ float ex2f(float x) {
    float r;
    asm("ex2.approx.f32 %0, %1;" : "=f"(r) : "f"(x));
    return r;
}

// merged pack: five f32 inputs -> fp16, segment dispatch by index
__global__ void __launch_bounds__(256)
pack_all_kernel(const float4* __restrict__ x,  const float4* __restrict__ pe,
                const float4* __restrict__ w,  const float4* __restrict__ u,
                const float4* __restrict__ wo,
                uint2* __restrict__ ox, uint2* __restrict__ ope,
                uint2* __restrict__ ow, uint2* __restrict__ ou,
                uint2* __restrict__ owo)
{
    const int N0 = 1048576, N1 = 2097152, N2 = 2293760, N3 = 2424832, N4 = 2490368;
    int i = blockIdx.x * 256 + threadIdx.x;
    if (i >= N4) return;
    const float4* src; uint2* dst; int j;
    if (i < N0)      { src = x;  dst = ox;  j = i; }
    else if (i < N1) { src = pe; dst = ope; j = i - N0; }
    else if (i < N2) { src = w;  dst = ow;  j = i - N1; }
    else if (i < N3) { src = u;  dst = ou;  j = i - N2; }
    else             { src = wo; dst = owo; j = i - N3; }
    float4 v = src[j];
    dst[j] = make_uint2(h2u(__floats2half2_rn(v.x, v.y)),
                        h2u(__floats2half2_rn(v.z, v.w)));
}

// PE_r f32 -> fp16 scaled by log2e
__global__ void __launch_bounds__(256)
pack_bias_kernel(const float4* __restrict__ in, uint2* __restrict__ out, int n4)
{
    int i = blockIdx.x * 256 + threadIdx.x;
    if (i < n4) {
        float4 v = in[i];
        out[i] = make_uint2(h2u(__floats2half2_rn(v.x * LOG2E, v.y * LOG2E)),
                            h2u(__floats2half2_rn(v.z * LOG2E, v.w * LOG2E)));
    }
}

#define LDSM4(r0, r1, r2, r3, a)                                              \
    asm volatile("ldmatrix.sync.aligned.m8n8.x4.shared.b16 {%0,%1,%2,%3}, [%4];" \
                 : "=r"(r0), "=r"(r1), "=r"(r2), "=r"(r3) : "r"(a))

#define MMA16816H(c, a, b0, b1)                                               \
    asm volatile("mma.sync.aligned.m16n8k16.row.col.f32.f16.f16.f32 "         \
                 "{%0,%1,%2,%3}, {%4,%5,%6,%7}, {%8,%9}, {%0,%1,%2,%3};"      \
                 : "+f"((c)[0]), "+f"((c)[1]), "+f"((c)[2]), "+f"((c)[3])     \
                 : "r"((a)[0]), "r"((a)[1]), "r"((a)[2]), "r"((a)[3]),        \
                   "r"(b0), "r"(b1))

#define CP_ASYNC16(dst, src) \
    asm volatile("cp.async.cg.shared.global [%0], [%1], 16;" :: "r"(dst), "l"(src))
#define CP_COMMIT() asm volatile("cp.async.commit_group;" ::: "memory")
#define CP_WAIT0()  asm volatile("cp.async.wait_group 0;" ::: "memory")
#define CP_WAIT1()  asm volatile("cp.async.wait_group 1;" ::: "memory")

__device__ __forceinline__ unsigned sw64(unsigned off)  { return off ^ ((off >> 3) & 0x30); }

// ------------------------------ GEMM (projections / out) -------------------
// C[128 x 128]; A fp16 [M,K]; B fp16 [N,K]; K mult of 32. Warp tile 32x64.
// Stage (16KB): A[128x32]@0, B[128x32]@8192; cp.async double-buffered.
// Epilogue stages C through smem [128][132] f32 (67584 B dynamic smem).
template <typename Epi>
__global__ void __launch_bounds__(256, 2)
gemm_fp16c(const unsigned short* __restrict__ A, const unsigned short* __restrict__ B,
           int K, int lda, int ldb, long sA, long sB, Epi epi)
{
    extern __shared__ __align__(1024) char smem[];
    constexpr int SB = 8192, STAGE = 16384;

    const int tid = threadIdx.x;
    const int l   = tid & 31;
    const int w   = tid >> 5;
    const int m0  = (w & 3) * 32;
    const int n0  = (w >> 2) * 64;
    const int bz  = blockIdx.z;
    const unsigned sbase = smem_u32(smem);

    const unsigned short* Ab = A + bz * sA + (long)blockIdx.y * 128 * lda;
    const unsigned short* Bb = B + bz * sB + (long)blockIdx.x * 128 * ldb;

    float acc[2][8][4];
#pragma unroll
    for (int i = 0; i < 2; i++)
#pragma unroll
        for (int j = 0; j < 8; j++)
#pragma unroll
            for (int k = 0; k < 4; k++) acc[i][j][k] = 0.0f;

    const int arow = (l & 7) + ((l >> 3) & 1) * 8;
    const int akp  = ((l >> 4) & 1) * 16;
    const int brow = (l & 7) + ((l >> 4) & 1) * 8;
    const int bkp  = ((l >> 3) & 1) * 16;

    const int nChunks = K >> 5;

    auto prefetch = [&](int c) {
        const unsigned sb = sbase + (c & 1) * STAGE;
#pragma unroll
        for (int it = 0; it < 2; it++) {
            int idx = tid + it * 256;
            int r = idx >> 2, q = idx & 3;
            CP_ASYNC16(sb + sw64(r * 64 + q * 16), Ab + (long)r * lda + c * 32 + q * 8);
        }
#pragma unroll
        for (int it = 0; it < 2; it++) {
            int idx = tid + it * 256;
            int r = idx >> 2, q = idx & 3;
            CP_ASYNC16(sb + SB + sw64(r * 64 + q * 16), Bb + (long)r * ldb + c * 32 + q * 8);
        }
    };

    prefetch(0);
    CP_COMMIT();

    for (int c = 0; c < nChunks; c++) {
        if (c + 1 < nChunks) {
            prefetch(c + 1);
            CP_COMMIT();
            CP_WAIT1();
        } else {
            CP_WAIT0();
        }
        __syncthreads();

        const unsigned stage = sbase + (c & 1) * STAGE;
#pragma unroll
        for (int ks = 0; ks < 2; ks++) {
            unsigned aH[2][4], bH[4][4];
#pragma unroll
            for (int i = 0; i < 2; i++) {
                unsigned off = (m0 + i * 16 + arow) * 64 + ks * 32 + akp;
                LDSM4(aH[i][0], aH[i][1], aH[i][2], aH[i][3], stage + sw64(off));
            }
#pragma unroll
            for (int p = 0; p < 4; p++) {
                unsigned off = (n0 + p * 16 + brow) * 64 + ks * 32 + bkp;
                LDSM4(bH[p][0], bH[p][1], bH[p][2], bH[p][3], stage + SB + sw64(off));
            }
#pragma unroll
            for (int i = 0; i < 2; i++)
#pragma unroll
                for (int j = 0; j < 8; j++) {
                    const int p = j >> 1, h = (j & 1) * 2;
                    MMA16816H(acc[i][j], aH[i], bH[p][h], bH[p][h + 1]);
                }
        }
        __syncthreads();   // compute done before next prefetch overwrites buf
    }

    // ---- epilogue: stage through smem [128][132], coalesced functor stores ----
    float* C = reinterpret_cast<float*>(smem);
#pragma unroll
    for (int i = 0; i < 2; i++)
#pragma unroll
        for (int j = 0; j < 8; j++) {
            int r0  = m0 + i * 16 + (l >> 2);
            int col = n0 + j * 8 + (l & 3) * 2;
            *reinterpret_cast<float2*>(C + r0 * 132 + col)       = make_float2(acc[i][j][0], acc[i][j][1]);
            *reinterpret_cast<float2*>(C + (r0 + 8) * 132 + col) = make_float2(acc[i][j][2], acc[i][j][3]);
        }
    __syncthreads();

    {
        int r = tid >> 1, seg = (tid & 1) << 6;
        int m  = blockIdx.y * 128 + r;
        int nb = blockIdx.x * 128 + seg;
        const float* Crow = C + r * 132 + seg;
#pragma unroll
        for (int i = 0; i < 16; i++) {
            float4 v = *reinterpret_cast<const float4*>(Crow + i * 4);
            epi(bz, m, nb + i * 4, v);
        }
    }
}

// ------------------------------ epilogues ----------------------------------
struct EpiQKV {   // m in [0,8192), n in [0,1536)
    __device__ void operator()(int, int m, int n, float4 v) const {
        int b = m >> 11, s = m & (SQ - 1);
        int h = n / 192, r = n - h * 192;
        int bh = b * HH + h;
        if (r < HD) {
            long row = ((long)bh * SQ + s);
            *reinterpret_cast<uint2*>(&g_Qcat[row * 128 + r]) =
                make_uint2(h2u(__floats2half2_rn(v.x * QK_SCALE_L2E, v.y * QK_SCALE_L2E)),
                           h2u(__floats2half2_rn(v.z * QK_SCALE_L2E, v.w * QK_SCALE_L2E)));
        } else if (r < 2 * HD) {
            int d0 = r - HD;
            int ck = s >> 6, rr = s & 63;
            long base = ((long)bh * 32 + ck) * 16384;
            unsigned off = (unsigned)((d0 >> 5) * 4096) + sw64(rr * 64 + (d0 & 31) * 2);
            *reinterpret_cast<uint2*>(reinterpret_cast<char*>(g_KH) + base + off) =
                make_uint2(h2u(__floats2half2_rn(v.x, v.y)),
                           h2u(__floats2half2_rn(v.z, v.w)));
        } else {
            int d = r - 2 * HD;
            int ck = s >> 6, kc = s & 63;
            long base = ((long)bh * 32 + ck) * 8192 + (kc >> 5) * 4096;
            int kb = (kc & 31) * 2;
#pragma unroll
            for (int i = 0; i < 4; i++) {
                float val = (&v.x)[i];
                unsigned off2 = sw64((d + i) * 64 + kb);
                *reinterpret_cast<__half*>(reinterpret_cast<char*>(g_VH) + base + off2) =
                    __float2half(val);
            }
        }
    }
};
struct EpiPE {    // n in [0,1024)
    __device__ void operator()(int, int m, int n, float4 v) const {
        int b = m >> 11, s = m & (SQ - 1);
        int h = n >> 7, r = n & 127;
        int bh = b * HH + h;
        if (r < HD) {
            long row = ((long)bh * SQ + s);
            *reinterpret_cast<uint2*>(&g_Qcat[row * 128 + HD + r]) =
                make_uint2(h2u(__floats2half2_rn(v.x * QK_SCALE_L2E, v.y * QK_SCALE_L2E)),
                           h2u(__floats2half2_rn(v.z * QK_SCALE_L2E, v.w * QK_SCALE_L2E)));
        } else {
            int d0 = r;
            int ck = s >> 6, rr = s & 63;
            long base = ((long)bh * 32 + ck) * 16384;
            unsigned off = (unsigned)((d0 >> 5) * 4096) + sw64(rr * 64 + (d0 & 31) * 2);
            *reinterpret_cast<uint2*>(reinterpret_cast<char*>(g_KH) + base + off) =
                make_uint2(h2u(__floats2half2_rn(v.x, v.y)),
                           h2u(__floats2half2_rn(v.z, v.w)));
        }
    }
};
struct EpiOut {
    float* out;
    __device__ void operator()(int, int m, int n, float4 v) const {
        *reinterpret_cast<float4*>(&out[(long)m * EMB + n]) = v;
    }
};

// ------------------------------ flash attention ----------------------------
// One CTA = 128 q-rows of one (b,h). 8 warps x 16 q-rows. KV chunk = 64 keys.
// 2 CTAs/SM: smem 86KB (KV x2 @0, fp16 bias x2 @49152), regs capped at 128.
__global__ void __launch_bounds__(256, 2)
flash_attn(const unsigned short* __restrict__ Qc, const char* __restrict__ KH,
           const char* __restrict__ VH, const char* __restrict__ PEr,
           unsigned short* __restrict__ vals)
{
    extern __shared__ __align__(1024) char smem[];
    constexpr int KVBUF = 24576;     // KH 16K | VH 8K
    constexpr int SBIAS = 49152, BIAS_STRIDE = 144, BIAS_BUF = 18432;
    constexpr int NCHUNK = SQ / 64;  // 32

    const int tid = threadIdx.x;
    const int l = tid & 31;
    const int w = tid >> 5;
    const int g = l >> 2;
    const int t = l & 3;
    const int bh = blockIdx.y;
    const int q0 = blockIdx.x * 128;
    const int qw = q0 + w * 16;
    const unsigned sbase = smem_u32(smem);

    const unsigned short* Qb = Qc + ((long)bh * SQ + qw) * 128;
    const char* KHb = KH + (long)bh * 32 * 16384;
    const char* VHb = VH + (long)bh * 32 * 8192;
    const char* Pb = PEr + (((long)(bh & 7) * SQ + q0) * SQ) * 2;

    unsigned qH[8][4];
#pragma unroll
    for (int kc = 0; kc < 8; kc++) {
        qH[kc][0] = *reinterpret_cast<const unsigned*>(Qb + (long)g * 128 + kc * 16 + 2 * t);
        qH[kc][1] = *reinterpret_cast<const unsigned*>(Qb + (long)(g + 8) * 128 + kc * 16 + 2 * t);
        qH[kc][2] = *reinterpret_cast<const unsigned*>(Qb + (long)g * 128 + kc * 16 + 8 + 2 * t);
        qH[kc][3] = *reinterpret_cast<const unsigned*>(Qb + (long)(g + 8) * 128 + kc * 16 + 8 + 2 * t);
    }

    float oacc[8][4];
#pragma unroll
    for (int j = 0; j < 8; j++)
#pragma unroll
        for (int k = 0; k < 4; k++) oacc[j][k] = 0.0f;
    float m0r = -1e30f, m1r = -1e30f, l0r = 0.0f, l1r = 0.0f;

    const int brow = (l & 7) + ((l >> 4) & 1) * 8;
    const int bkp  = ((l >> 3) & 1) * 16;

    auto prefetch = [&](int ck) {
        const int buf = ck & 1;
        const unsigned sb = sbase + buf * KVBUF;
        const char* kh = KHb + (long)ck * 16384;
        const char* vh = VHb + (long)ck * 8192;
#pragma unroll
        for (int it = 0; it < 4; it++) {
            int o = (tid + it * 256) * 16;
            CP_ASYNC16(sb + o, kh + o);
        }
#pragma unroll
        for (int it = 0; it < 2; it++) {
            int o = (tid + it * 256) * 16;
            CP_ASYNC16(sb + 16384 + o, vh + o);
        }
        const unsigned bb = sbase + SBIAS + buf * BIAS_BUF;
#pragma unroll
        for (int it = 0; it < 4; it++) {
            int idx = tid + it * 256;
            int r = idx >> 3, c = idx & 7;
            CP_ASYNC16(bb + r * BIAS_STRIDE + c * 16,
                       Pb + ((long)r * SQ + ck * 64 + c * 8) * 2);
        }
    };

    prefetch(0);
    CP_COMMIT();

    for (int ck = 0; ck < NCHUNK; ck++) {
        if (ck + 1 < NCHUNK) {
            prefetch(ck + 1);
            CP_COMMIT();
            CP_WAIT1();
        } else {
            CP_WAIT0();
        }
        __syncthreads();

        const int buf = ck & 1;
        const unsigned kvb = sbase + buf * KVBUF;

        float sacc[8][4];
#pragma unroll
        for (int j = 0; j < 8; j++)
#pragma unroll
            for (int k = 0; k < 4; k++) sacc[j][k] = 0.0f;

#pragma unroll
        for (int kc = 0; kc < 8; kc++) {
            unsigned bH[4][4];
            const unsigned slab = kvb + (kc >> 1) * 4096;
            const unsigned koff = (kc & 1) * 32 + bkp;
#pragma unroll
            for (int p = 0; p < 4; p++) {
                unsigned sw = sw64((p * 16 + brow) * 64 + koff);
                LDSM4(bH[p][0], bH[p][1], bH[p][2], bH[p][3], slab + sw);
            }
#pragma unroll
            for (int j = 0; j < 8; j++) {
                const int p = j >> 1, h = (j & 1) * 2;
                MMA16816H(sacc[j], qH[kc], bH[p][h], bH[p][h + 1]);
            }
        }

        {
            const char* bb = smem + SBIAS + buf * BIAS_BUF;
            const int r0 = w * 16 + g, r1 = r0 + 8;
#pragma unroll
            for (int j = 0; j < 8; j++) {
                float2 b0 = __half22float2(*reinterpret_cast<const __half2*>(
                    bb + r0 * BIAS_STRIDE + (j * 8 + 2 * t) * 2));
                float2 b1 = __half22float2(*reinterpret_cast<const __half2*>(
                    bb + r1 * BIAS_STRIDE + (j * 8 + 2 * t) * 2));
                sacc[j][0] += b0.x; sacc[j][1] += b0.y;
                sacc[j][2] += b1.x; sacc[j][3] += b1.y;
            }
        }

        float mx0 = -1e30f, mx1 = -1e30f;
#pragma unroll
        for (int j = 0; j < 8; j++) {
            mx0 = fmaxf(mx0, fmaxf(sacc[j][0], sacc[j][1]));
            mx1 = fmaxf(mx1, fmaxf(sacc[j][2], sacc[j][3]));
        }
        mx0 = fmaxf(mx0, __shfl_xor_sync(0xffffffffu, mx0, 1));
        mx0 = fmaxf(mx0, __shfl_xor_sync(0xffffffffu, mx0, 2));
        mx1 = fmaxf(mx1, __shfl_xor_sync(0xffffffffu, mx1, 1));
        mx1 = fmaxf(mx1, __shfl_xor_sync(0xffffffffu, mx1, 2));

        const float mn0 = fmaxf(m0r, mx0), mn1 = fmaxf(m1r, mx1);
        const float cor0 = ex2f(m0r - mn0), cor1 = ex2f(m1r - mn1);
        m0r = mn0; m1r = mn1;

        float sum0 = 0.0f, sum1 = 0.0f;
#pragma unroll
        for (int j = 0; j < 8; j++) {
            sacc[j][0] = ex2f(sacc[j][0] - mn0);
            sacc[j][1] = ex2f(sacc[j][1] - mn0);
            sacc[j][2] = ex2f(sacc[j][2] - mn1);
            sacc[j][3] = ex2f(sacc[j][3] - mn1);
            sum0 += sacc[j][0] + sacc[j][1];
            sum1 += sacc[j][2] + sacc[j][3];
        }
        sum0 += __shfl_xor_sync(0xffffffffu, sum0, 1);
        sum0 += __shfl_xor_sync(0xffffffffu, sum0, 2);
        sum1 += __shfl_xor_sync(0xffffffffu, sum1, 1);
        sum1 += __shfl_xor_sync(0xffffffffu, sum1, 2);
        l0r = l0r * cor0 + sum0;
        l1r = l1r * cor1 + sum1;

#pragma unroll
        for (int j = 0; j < 8; j++) {
            oacc[j][0] *= cor0; oacc[j][1] *= cor0;
            oacc[j][2] *= cor1; oacc[j][3] *= cor1;
        }

#pragma unroll
        for (int kk = 0; kk < 4; kk++) {
            unsigned pH[4];
            pH[0] = h2u(__floats2half2_rn(sacc[2 * kk][0],     sacc[2 * kk][1]));
            pH[1] = h2u(__floats2half2_rn(sacc[2 * kk][2],     sacc[2 * kk][3]));
            pH[2] = h2u(__floats2half2_rn(sacc[2 * kk + 1][0], sacc[2 * kk + 1][1]));
            pH[3] = h2u(__floats2half2_rn(sacc[2 * kk + 1][2], sacc[2 * kk + 1][3]));

            unsigned vHf[4][4];
            const unsigned slab = kvb + 16384 + (kk >> 1) * 4096;
            const unsigned koff = (kk & 1) * 32 + bkp;
#pragma unroll
            for (int p = 0; p < 4; p++) {
                unsigned sw = sw64((p * 16 + brow) * 64 + koff);
                LDSM4(vHf[p][0], vHf[p][1], vHf[p][2], vHf[p][3], slab + sw);
            }
#pragma unroll
            for (int j = 0; j < 8; j++) {
                const int p = j >> 1, h = (j & 1) * 2;
                MMA16816H(oacc[j], pH, vHf[p][h], vHf[p][h + 1]);
            }
        }

        __syncthreads();
    }

    const float inv0 = 1.0f / l0r, inv1 = 1.0f / l1r;
    const int b = bh >> 3, h = bh & 7;
    const long row0 = (long)(b * SQ + qw + g) * EMB + h * HD;
    const long row1 = (long)(b * SQ + qw + g + 8) * EMB + h * HD;
#pragma unroll
    for (int j = 0; j < 8; j++) {
        int col = j * 8 + 2 * t;
        *reinterpret_cast<unsigned*>(&vals[row0 + col]) =
            h2u(__floats2half2_rn(oacc[j][0] * inv0, oacc[j][1] * inv0));
        *reinterpret_cast<unsigned*>(&vals[row1 + col]) =
            h2u(__floats2half2_rn(oacc[j][2] * inv1, oacc[j][3] * inv1));
    }
}

// ------------------------------ launch -------------------------------------
template <typename Epi>
static void launch_gemm(dim3 grid, const unsigned short* A, const unsigned short* B,
                        int K, int lda, int ldb, long sA, long sB, Epi epi)
{
    cudaFuncSetAttribute(gemm_fp16c<Epi>, cudaFuncAttributeMaxDynamicSharedMemorySize, 67584);
    gemm_fp16c<Epi><<<grid, 256, 67584>>>(A, B, K, lda, ldb, sA, sB, epi);
}

extern "C" void kernel_launch(void* const* d_in, const int* in_sizes, int n_in,
                              void* d_out, int out_size)
{
    const float* x    = (const float*)d_in[0];
    const float* PE   = (const float*)d_in[1];
    const float* PE_r = (const float*)d_in[2];
    const float* Wqkv = (const float*)d_in[3];
    const float* UqUk = (const float*)d_in[4];
    const float* Wo   = (const float*)d_in[5];
    float* out = (float*)d_out;

    void* p;
    cudaGetSymbolAddress(&p, g_x2);    unsigned short* x2  = (unsigned short*)p;
    cudaGetSymbolAddress(&p, g_PE2);   unsigned short* pe2 = (unsigned short*)p;
    cudaGetSymbolAddress(&p, g_W2);    unsigned short* w2  = (unsigned short*)p;
    cudaGetSymbolAddress(&p, g_U2);    unsigned short* u2  = (unsigned short*)p;
    cudaGetSymbolAddress(&p, g_Wo2);   unsigned short* wo2 = (unsigned short*)p;
    cudaGetSymbolAddress(&p, g_PEr16); unsigned short* pr16 = (unsigned short*)p;
    cudaGetSymbolAddress(&p, g_Qcat);  unsigned short* Qc  = (unsigned short*)p;
    cudaGetSymbolAddress(&p, g_KH);    char* KH = (char*)p;
    cudaGetSymbolAddress(&p, g_VH);    char* VH = (char*)p;
    cudaGetSymbolAddress(&p, g_vals);  unsigned short* Vl = (unsigned short*)p;

    // 0) packs
    pack_all_kernel<<<9728, 256>>>((const float4*)x, (const float4*)PE,
                                   (const float4*)Wqkv, (const float4*)UqUk,
                                   (const float4*)Wo,
                                   (uint2*)x2, (uint2*)pe2,
                                   (uint2*)w2, (uint2*)u2, (uint2*)wo2);
    pack_bias_kernel<<<32768, 256>>>((const float4*)PE_r, (uint2*)pr16,
                                     (int)((size_t)HH * SQ * SQ / 4));

    // 1) qkv projection (writes Q scaled fp16, K/V fp16 images)
    launch_gemm(dim3(12, 64, 1), x2, w2, EMB, EMB, EMB, 0, 0, EpiQKV{});
    // 2) positional projection
    launch_gemm(dim3(8, 64, 1), pe2, u2, EMB, EMB, EMB, 0, 0, EpiPE{});
    // 3) fused attention (2 CTAs/SM)
    cudaFuncSetAttribute(flash_attn, cudaFuncAttributeMaxDynamicSharedMemorySize, 86016);
    flash_attn<<<dim3(SQ / 128, BB * HH), 256, 86016>>>(Qc, KH, VH, (const char*)pr16, Vl);
    // 4) out projection
    launch_gemm(dim3(4, 64, 1), Vl, wo2, EMB, EMB, EMB, 0, 0, EpiOut{out});
}

// round 14
// speedup vs baseline: 4.4308x; 1.0680x over previous
#include <cuda_runtime.h>
#include <cuda_fp16.h>
#include <cstdint>

// ---------------------------------------------------------------------------
// TUPE multihead attention — plain fp16 HMMA (fp32 accumulate) everywhere.
//  Projections: 128x128x64 tile (sw128), cp.async double-buffered, qkv+PE
//  merged into one launch. Flash middle: 2 CTAs/SM (round 12, proven).
// ---------------------------------------------------------------------------

static constexpr int BB  = 4;
static constexpr int HH  = 8;
static constexpr int SQ  = 2048;
static constexpr int EMB = 512;
static constexpr int HD  = 64;
static constexpr float LOG2E = 1.4426950408889634f;
static constexpr float QK_SCALE_L2E = 0.0883883476483184f * LOG2E;

// ------------------------------ scratch ------------------------------------
__device__ __align__(16) unsigned short g_x2  [(size_t)BB * SQ * EMB];
__device__ __align__(16) unsigned short g_PE2 [(size_t)BB * SQ * EMB];
__device__ __align__(16) unsigned short g_W2  [(size_t)3 * EMB * EMB];
__device__ __align__(16) unsigned short g_U2  [(size_t)2 * EMB * EMB];
__device__ __align__(16) unsigned short g_Wo2 [(size_t)EMB * EMB];
__device__ __align__(16) unsigned short g_PEr16[(size_t)HH * SQ * SQ];      // fp16, x log2e
__device__ __align__(16) unsigned short g_Qcat[(size_t)BB * HH * SQ * 128]; // fp16 (x s*log2e)
__device__ __align__(16) unsigned short g_KH[(size_t)BB * HH * SQ * 128];   // K image sw64
__device__ __align__(16) unsigned short g_VH[(size_t)BB * HH * HD * SQ];    // V image sw64
__device__ __align__(16) unsigned short g_vals[(size_t)BB * SQ * EMB];

// ------------------------------ helpers ------------------------------------
__device__ __forceinline__ unsigned smem_u32(const void* p) {
    unsigned a;
    asm("{ .reg .u64 t; cvta.to.shared.u64 t, %1; cvt.u32.u64 %0, t; }" : "=r"(a) : "l"(p));
    return a;
}
__device__ __forceinline__ unsigned h2u(__half2 h) {
    return *reinterpret_cast<unsigned*>(&h);
}
__device__ __forceinline__ float ex2f(float x) {
    float r;
    asm("ex2.approx.f32 %0, %1;" : "=f"(r) : "f"(x));
    return r;
}

// merged pack: five f32 inputs -> fp16, segment dispatch by index
__global__ void __launch_bounds__(256)
pack_all_kernel(const float4* __restrict__ x,  const float4* __restrict__ pe,
                const float4* __restrict__ w,  const float4* __restrict__ u,
                const float4* __restrict__ wo,
                uint2* __restrict__ ox, uint2* __restrict__ ope,
                uint2* __restrict__ ow, uint2* __restrict__ ou,
                uint2* __restrict__ owo)
{
    const int N0 = 1048576, N1 = 2097152, N2 = 2293760, N3 = 2424832, N4 = 2490368;
    int i = blockIdx.x * 256 + threadIdx.x;
    if (i >= N4) return;
    const float4* src; uint2* dst; int j;
    if (i < N0)      { src = x;  dst = ox;  j = i; }
    else if (i < N1) { src = pe; dst = ope; j = i - N0; }
    else if (i < N2) { src = w;  dst = ow;  j = i - N1; }
    else if (i < N3) { src = u;  dst = ou;  j = i - N2; }
    else             { src = wo; dst = owo; j = i - N3; }
    float4 v = src[j];
    dst[j] = make_uint2(h2u(__floats2half2_rn(v.x, v.y)),
                        h2u(__floats2half2_rn(v.z, v.w)));
}

// PE_r f32 -> fp16 scaled by log2e
__global__ void __launch_bounds__(256)
pack_bias_kernel(const float4* __restrict__ in, uint2* __restrict__ out, int n4)
{
    int i = blockIdx.x * 256 + threadIdx.x;
    if (i < n4) {
        float4 v = in[i];
        out[i] = make_uint2(h2u(__floats2half2_rn(v.x * LOG2E, v.y * LOG2E)),
                            h2u(__floats2half2_rn(v.z * LOG2E, v.w * LOG2E)));
    }
}

#define LDSM4(r0, r1, r2, r3, a)                                              \
    asm volatile("ldmatrix.sync.aligned.m8n8.x4.shared.b16 {%0,%1,%2,%3}, [%4];" \
                 : "=r"(r0), "=r"(r1), "=r"(r2), "=r"(r3) : "r"(a))

#define MMA16816H(c, a, b0, b1)                                               \
    asm volatile("mma.sync.aligned.m16n8k16.row.col.f32.f16.f16.f32 "         \
                 "{%0,%1,%2,%3}, {%4,%5,%6,%7}, {%8,%9}, {%0,%1,%2,%3};"      \
                 : "+f"((c)[0]), "+f"((c)[1]), "+f"((c)[2]), "+f"((c)[3])     \
                 : "r"((a)[0]), "r"((a)[1]), "r"((a)[2]), "r"((a)[3]),        \
                   "r"(b0), "r"(b1))

#define CP_ASYNC16(dst, src) \
    asm volatile("cp.async.cg.shared.global [%0], [%1], 16;" :: "r"(dst), "l"(src))
#define CP_COMMIT() asm volatile("cp.async.commit_group;" ::: "memory")
#define CP_WAIT0()  asm volatile("cp.async.wait_group 0;" ::: "memory")
#define CP_WAIT1()  asm volatile("cp.async.wait_group 1;" ::: "memory")

__device__ __forceinline__ unsigned sw64(unsigned off)   { return off ^ ((off >> 3) & 0x30); }
__device__ __forceinline__ unsigned sw128(unsigned off)  { return off ^ ((off >> 3) & 0x70); }

// ------------------------------ GEMM core (projections / out) --------------
// C[128 x 128]; A fp16 [M,K]; B fp16 [N,K]; K mult of 64. Warp tile 32x64.
// Stage (32KB): A[128x64]@0 sw128, B[128x64]@16384 sw128; double-buffered.
// Epilogue stages C through smem [128][132] f32 (67584 B dynamic smem).
template <typename Epi>
__device__ __forceinline__ void gemm_core(
    const unsigned short* __restrict__ Ab, const unsigned short* __restrict__ Bb,
    int K, int lda, int ldb, int bx, int by, int bz, Epi epi, char* smem)
{
    constexpr int SBOF = 16384, STAGE = 32768;
    const int tid = threadIdx.x;
    const int l   = tid & 31;
    const int w   = tid >> 5;
    const int m0  = (w & 3) * 32;
    const int n0  = (w >> 2) * 64;
    const unsigned sbase = smem_u32(smem);

    float acc[2][8][4];
#pragma unroll
    for (int i = 0; i < 2; i++)
#pragma unroll
        for (int j = 0; j < 8; j++)
#pragma unroll
            for (int k = 0; k < 4; k++) acc[i][j][k] = 0.0f;

    const int arow = (l & 7) + ((l >> 3) & 1) * 8;
    const int akp  = ((l >> 4) & 1) * 16;
    const int brow = (l & 7) + ((l >> 4) & 1) * 8;
    const int bkp  = ((l >> 3) & 1) * 16;

    const int nChunks = K >> 6;

    auto prefetch = [&](int c) {
        const unsigned sb = sbase + (c & 1) * STAGE;
#pragma unroll
        for (int it = 0; it < 4; it++) {
            int idx = tid + it * 256;
            int r = idx >> 3, q = idx & 7;
            CP_ASYNC16(sb + sw128(r * 128 + q * 16), Ab + (long)r * lda + c * 64 + q * 8);
        }
#pragma unroll
        for (int it = 0; it < 4; it++) {
            int idx = tid + it * 256;
            int r = idx >> 3, q = idx & 7;
            CP_ASYNC16(sb + SBOF + sw128(r * 128 + q * 16), Bb + (long)r * ldb + c * 64 + q * 8);
        }
    };

    prefetch(0);
    CP_COMMIT();

    for (int c = 0; c < nChunks; c++) {
        if (c + 1 < nChunks) {
            prefetch(c + 1);
            CP_COMMIT();
            CP_WAIT1();
        } else {
            CP_WAIT0();
        }
        __syncthreads();

        const unsigned stage = sbase + (c & 1) * STAGE;
#pragma unroll
        for (int ks = 0; ks < 4; ks++) {
            unsigned aH[2][4], bH[4][4];
#pragma unroll
            for (int i = 0; i < 2; i++) {
                unsigned off = (m0 + i * 16 + arow) * 128 + ks * 32 + akp;
                LDSM4(aH[i][0], aH[i][1], aH[i][2], aH[i][3], stage + sw128(off));
            }
#pragma unroll
            for (int p = 0; p < 4; p++) {
                unsigned off = (n0 + p * 16 + brow) * 128 + ks * 32 + bkp;
                LDSM4(bH[p][0], bH[p][1], bH[p][2], bH[p][3], stage + SBOF + sw128(off));
            }
#pragma unroll
            for (int i = 0; i < 2; i++)
#pragma unroll
                for (int j = 0; j < 8; j++) {
                    const int p = j >> 1, h = (j & 1) * 2;
                    MMA16816H(acc[i][j], aH[i], bH[p][h], bH[p][h + 1]);
                }
        }
        __syncthreads();   // compute done before next prefetch overwrites buf
    }

    // ---- epilogue: stage through smem [128][132], coalesced functor stores ----
    float* C = reinterpret_cast<float*>(smem);
#pragma unroll
    for (int i = 0; i < 2; i++)
#pragma unroll
        for (int j = 0; j < 8; j++) {
            int r0  = m0 + i * 16 + (l >> 2);
            int col = n0 + j * 8 + (l & 3) * 2;
            *reinterpret_cast<float2*>(C + r0 * 132 + col)       = make_float2(acc[i][j][0], acc[i][j][1]);
            *reinterpret_cast<float2*>(C + (r0 + 8) * 132 + col) = make_float2(acc[i][j][2], acc[i][j][3]);
        }
    __syncthreads();

    {
        int r = tid >> 1, seg = (tid & 1) << 6;
        int m  = by * 128 + r;
        int nb = bx * 128 + seg;
        const float* Crow = C + r * 132 + seg;
#pragma unroll
        for (int i = 0; i < 16; i++) {
            float4 v = *reinterpret_cast<const float4*>(Crow + i * 4);
            epi(bz, m, nb + i * 4, v);
        }
    }
}

// ------------------------------ epilogues ----------------------------------
struct EpiQKV {   // m in [0,8192), n in [0,1536)
    __device__ void operator()(int, int m, int n, float4 v) const {
        int b = m >> 11, s = m & (SQ - 1);
        int h = n / 192, r = n - h * 192;
        int bh = b * HH + h;
        if (r < HD) {
            long row = ((long)bh * SQ + s);
            *reinterpret_cast<uint2*>(&g_Qcat[row * 128 + r]) =
                make_uint2(h2u(__floats2half2_rn(v.x * QK_SCALE_L2E, v.y * QK_SCALE_L2E)),
                           h2u(__floats2half2_rn(v.z * QK_SCALE_L2E, v.w * QK_SCALE_L2E)));
        } else if (r < 2 * HD) {
            int d0 = r - HD;
            int ck = s >> 6, rr = s & 63;
            long base = ((long)bh * 32 + ck) * 16384;
            unsigned off = (unsigned)((d0 >> 5) * 4096) + sw64(rr * 64 + (d0 & 31) * 2);
            *reinterpret_cast<uint2*>(reinterpret_cast<char*>(g_KH) + base + off) =
                make_uint2(h2u(__floats2half2_rn(v.x, v.y)),
                           h2u(__floats2half2_rn(v.z, v.w)));
        } else {
            int d = r - 2 * HD;
            int ck = s >> 6, kc = s & 63;
            long base = ((long)bh * 32 + ck) * 8192 + (kc >> 5) * 4096;
            int kb = (kc & 31) * 2;
#pragma unroll
            for (int i = 0; i < 4; i++) {
                float val = (&v.x)[i];
                unsigned off2 = sw64((d + i) * 64 + kb);
                *reinterpret_cast<__half*>(reinterpret_cast<char*>(g_VH) + base + off2) =
                    __float2half(val);
            }
        }
    }
};
struct EpiPE {    // n in [0,1024)
    __device__ void operator()(int, int m, int n, float4 v) const {
        int b = m >> 11, s = m & (SQ - 1);
        int h = n >> 7, r = n & 127;
        int bh = b * HH + h;
        if (r < HD) {
            long row = ((long)bh * SQ + s);
            *reinterpret_cast<uint2*>(&g_Qcat[row * 128 + HD + r]) =
                make_uint2(h2u(__floats2half2_rn(v.x * QK_SCALE_L2E, v.y * QK_SCALE_L2E)),
                           h2u(__floats2half2_rn(v.z * QK_SCALE_L2E, v.w * QK_SCALE_L2E)));
        } else {
            int d0 = r;
            int ck = s >> 6, rr = s & 63;
            long base = ((long)bh * 32 + ck) * 16384;
            unsigned off = (unsigned)((d0 >> 5) * 4096) + sw64(rr * 64 + (d0 & 31) * 2);
            *reinterpret_cast<uint2*>(reinterpret_cast<char*>(g_KH) + base + off) =
                make_uint2(h2u(__floats2half2_rn(v.x, v.y)),
                           h2u(__floats2half2_rn(v.z, v.w)));
        }
    }
};
struct EpiOut {
    float* out;
    __device__ void operator()(int, int m, int n, float4 v) const {
        *reinterpret_cast<float4*>(&out[(long)m * EMB + n]) = v;
    }
};

// ------------------------------ merged projection kernel -------------------
// blockIdx.x < 12: qkv tile (A=x2, B=W2);  else: PE tile (A=PE2, B=U2).
__global__ void __launch_bounds__(256, 2)
proj_kernel(const unsigned short* __restrict__ x2, const unsigned short* __restrict__ w2,
            const unsigned short* __restrict__ pe2, const unsigned short* __restrict__ u2)
{
    extern __shared__ __align__(1024) char smem[];
    const int bx = blockIdx.x, by = blockIdx.y;
    if (bx < 12) {
        gemm_core(x2 + (long)by * 128 * EMB, w2 + (long)bx * 128 * EMB,
                  EMB, EMB, EMB, bx, by, 0, EpiQKV{}, smem);
    } else {
        gemm_core(pe2 + (long)by * 128 * EMB, u2 + (long)(bx - 12) * 128 * EMB,
                  EMB, EMB, EMB, bx - 12, by, 0, EpiPE{}, smem);
    }
}

// out projection
__global__ void __launch_bounds__(256, 2)
outproj_kernel(const unsigned short* __restrict__ vals, const unsigned short* __restrict__ wo2,
               float* __restrict__ out)
{
    extern __shared__ __align__(1024) char smem[];
    gemm_core(vals + (long)blockIdx.y * 128 * EMB, wo2 + (long)blockIdx.x * 128 * EMB,
              EMB, EMB, EMB, blockIdx.x, blockIdx.y, 0, EpiOut{out}, smem);
}

// ------------------------------ flash attention ----------------------------
// One CTA = 128 q-rows of one (b,h). 8 warps x 16 q-rows. KV chunk = 64 keys.
// 2 CTAs/SM: smem 86KB (KV x2 @0, fp16 bias x2 @49152), regs capped at 128.
__global__ void __launch_bounds__(256, 2)
flash_attn(const unsigned short* __restrict__ Qc, const char* __restrict__ KH,
           const char* __restrict__ VH, const char* __restrict__ PEr,
           unsigned short* __restrict__ vals)
{
    extern __shared__ __align__(1024) char smem[];
    constexpr int KVBUF = 24576;     // KH 16K | VH 8K
    constexpr int SBIAS = 49152, BIAS_STRIDE = 144, BIAS_BUF = 18432;
    constexpr int NCHUNK = SQ / 64;  // 32

    const int tid = threadIdx.x;
    const int l = tid & 31;
    const int w = tid >> 5;
    const int g = l >> 2;
    const int t = l & 3;
    const int bh = blockIdx.y;
    const int q0 = blockIdx.x * 128;
    const int qw = q0 + w * 16;
    const unsigned sbase = smem_u32(smem);

    const unsigned short* Qb = Qc + ((long)bh * SQ + qw) * 128;
    const char* KHb = KH + (long)bh * 32 * 16384;
    const char* VHb = VH + (long)bh * 32 * 8192;
    const char* Pb = PEr + (((long)(bh & 7) * SQ + q0) * SQ) * 2;

    unsigned qH[8][4];
#pragma unroll
    for (int kc = 0; kc < 8; kc++) {
        qH[kc][0] = *reinterpret_cast<const unsigned*>(Qb + (long)g * 128 + kc * 16 + 2 * t);
        qH[kc][1] = *reinterpret_cast<const unsigned*>(Qb + (long)(g + 8) * 128 + kc * 16 + 2 * t);
        qH[kc][2] = *reinterpret_cast<const unsigned*>(Qb + (long)g * 128 + kc * 16 + 8 + 2 * t);
        qH[kc][3] = *reinterpret_cast<const unsigned*>(Qb + (long)(g + 8) * 128 + kc * 16 + 8 + 2 * t);
    }

    float oacc[8][4];
#pragma unroll
    for (int j = 0; j < 8; j++)
#pragma unroll
        for (int k = 0; k < 4; k++) oacc[j][k] = 0.0f;
    float m0r = -1e30f, m1r = -1e30f, l0r = 0.0f, l1r = 0.0f;

    const int brow = (l & 7) + ((l >> 4) & 1) * 8;
    const int bkp  = ((l >> 3) & 1) * 16;

    auto prefetch = [&](int ck) {
        const int buf = ck & 1;
        const unsigned sb = sbase + buf * KVBUF;
        const char* kh = KHb + (long)ck * 16384;
        const char* vh = VHb + (long)ck * 8192;
#pragma unroll
        for (int it = 0; it < 4; it++) {
            int o = (tid + it * 256) * 16;
            CP_ASYNC16(sb + o, kh + o);
        }
#pragma unroll
        for (int it = 0; it < 2; it++) {
            int o = (tid + it * 256) * 16;
            CP_ASYNC16(sb + 16384 + o, vh + o);
        }
        const unsigned bb = sbase + SBIAS + buf * BIAS_BUF;
#pragma unroll
        for (int it = 0; it < 4; it++) {
            int idx = tid + it * 256;
            int r = idx >> 3, c = idx & 7;
            CP_ASYNC16(bb + r * BIAS_STRIDE + c * 16,
                       Pb + ((long)r * SQ + ck * 64 + c * 8) * 2);
        }
    };

    prefetch(0);
    CP_COMMIT();

    for (int ck = 0; ck < NCHUNK; ck++) {
        if (ck + 1 < NCHUNK) {
            prefetch(ck + 1);
            CP_COMMIT();
            CP_WAIT1();
        } else {
            CP_WAIT0();
        }
        __syncthreads();

        const int buf = ck & 1;
        const unsigned kvb = sbase + buf * KVBUF;

        float sacc[8][4];
#pragma unroll
        for (int j = 0; j < 8; j++)
#pragma unroll
            for (int k = 0; k < 4; k++) sacc[j][k] = 0.0f;

#pragma unroll
        for (int kc = 0; kc < 8; kc++) {
            unsigned bH[4][4];
            const unsigned slab = kvb + (kc >> 1) * 4096;
            const unsigned koff = (kc & 1) * 32 + bkp;
#pragma unroll
            for (int p = 0; p < 4; p++) {
                unsigned sw = sw64((p * 16 + brow) * 64 + koff);
                LDSM4(bH[p][0], bH[p][1], bH[p][2], bH[p][3], slab + sw);
            }
#pragma unroll
            for (int j = 0; j < 8; j++) {
                const int p = j >> 1, h = (j & 1) * 2;
                MMA16816H(sacc[j], qH[kc], bH[p][h], bH[p][h + 1]);
            }
        }

        {
            const char* bb = smem + SBIAS + buf * BIAS_BUF;
            const int r0 = w * 16 + g, r1 = r0 + 8;
#pragma unroll
            for (int j = 0; j < 8; j++) {
                float2 b0 = __half22float2(*reinterpret_cast<const __half2*>(
                    bb + r0 * BIAS_STRIDE + (j * 8 + 2 * t) * 2));
                float2 b1 = __half22float2(*reinterpret_cast<const __half2*>(
                    bb + r1 * BIAS_STRIDE + (j * 8 + 2 * t) * 2));
                sacc[j][0] += b0.x; sacc[j][1] += b0.y;
                sacc[j][2] += b1.x; sacc[j][3] += b1.y;
            }
        }

        float mx0 = -1e30f, mx1 = -1e30f;
#pragma unroll
        for (int j = 0; j < 8; j++) {
            mx0 = fmaxf(mx0, fmaxf(sacc[j][0], sacc[j][1]));
            mx1 = fmaxf(mx1, fmaxf(sacc[j][2], sacc[j][3]));
        }
        mx0 = fmaxf(mx0, __shfl_xor_sync(0xffffffffu, mx0, 1));
        mx0 = fmaxf(mx0, __shfl_xor_sync(0xffffffffu, mx0, 2));
        mx1 = fmaxf(mx1, __shfl_xor_sync(0xffffffffu, mx1, 1));
        mx1 = fmaxf(mx1, __shfl_xor_sync(0xffffffffu, mx1, 2));

        const float mn0 = fmaxf(m0r, mx0), mn1 = fmaxf(m1r, mx1);
        const float cor0 = ex2f(m0r - mn0), cor1 = ex2f(m1r - mn1);
        m0r = mn0; m1r = mn1;

        float sum0 = 0.0f, sum1 = 0.0f;
#pragma unroll
        for (int j = 0; j < 8; j++) {
            sacc[j][0] = ex2f(sacc[j][0] - mn0);
            sacc[j][1] = ex2f(sacc[j][1] - mn0);
            sacc[j][2] = ex2f(sacc[j][2] - mn1);
            sacc[j][3] = ex2f(sacc[j][3] - mn1);
            sum0 += sacc[j][0] + sacc[j][1];
            sum1 += sacc[j][2] + sacc[j][3];
        }
        sum0 += __shfl_xor_sync(0xffffffffu, sum0, 1);
        sum0 += __shfl_xor_sync(0xffffffffu, sum0, 2);
        sum1 += __shfl_xor_sync(0xffffffffu, sum1, 1);
        sum1 += __shfl_xor_sync(0xffffffffu, sum1, 2);
        l0r = l0r * cor0 + sum0;
        l1r = l1r * cor1 + sum1;

#pragma unroll
        for (int j = 0; j < 8; j++) {
            oacc[j][0] *= cor0; oacc[j][1] *= cor0;
            oacc[j][2] *= cor1; oacc[j][3] *= cor1;
        }

#pragma unroll
        for (int kk = 0; kk < 4; kk++) {
            unsigned pH[4];
            pH[0] = h2u(__floats2half2_rn(sacc[2 * kk][0],     sacc[2 * kk][1]));
            pH[1] = h2u(__floats2half2_rn(sacc[2 * kk][2],     sacc[2 * kk][3]));
            pH[2] = h2u(__floats2half2_rn(sacc[2 * kk + 1][0], sacc[2 * kk + 1][1]));
            pH[3] = h2u(__floats2half2_rn(sacc[2 * kk + 1][2], sacc[2 * kk + 1][3]));

            unsigned vHf[4][4];
            const unsigned slab = kvb + 16384 + (kk >> 1) * 4096;
            const unsigned koff = (kk & 1) * 32 + bkp;
#pragma unroll
            for (int p = 0; p < 4; p++) {
                unsigned sw = sw64((p * 16 + brow) * 64 + koff);
                LDSM4(vHf[p][0], vHf[p][1], vHf[p][2], vHf[p][3], slab + sw);
            }
#pragma unroll
            for (int j = 0; j < 8; j++) {
                const int p = j >> 1, h = (j & 1) * 2;
                MMA16816H(oacc[j], pH, vHf[p][h], vHf[p][h + 1]);
            }
        }

        __syncthreads();
    }

    const float inv0 = 1.0f / l0r, inv1 = 1.0f / l1r;
    const int b = bh >> 3, h = bh & 7;
    const long row0 = (long)(b * SQ + qw + g) * EMB + h * HD;
    const long row1 = (long)(b * SQ + qw + g + 8) * EMB + h * HD;
#pragma unroll
    for (int j = 0; j < 8; j++) {
        int col = j * 8 + 2 * t;
        *reinterpret_cast<unsigned*>(&vals[row0 + col]) =
            h2u(__floats2half2_rn(oacc[j][0] * inv0, oacc[j][1] * inv0));
        *reinterpret_cast<unsigned*>(&vals[row1 + col]) =
            h2u(__floats2half2_rn(oacc[j][2] * inv1, oacc[j][3] * inv1));
    }
}

// ------------------------------ launch -------------------------------------
extern "C" void kernel_launch(void* const* d_in, const int* in_sizes, int n_in,
                              void* d_out, int out_size)
{
    const float* x    = (const float*)d_in[0];
    const float* PE   = (const float*)d_in[1];
    const float* PE_r = (const float*)d_in[2];
    const float* Wqkv = (const float*)d_in[3];
    const float* UqUk = (const float*)d_in[4];
    const float* Wo   = (const float*)d_in[5];
    float* out = (float*)d_out;

    void* p;
    cudaGetSymbolAddress(&p, g_x2);    unsigned short* x2  = (unsigned short*)p;
    cudaGetSymbolAddress(&p, g_PE2);   unsigned short* pe2 = (unsigned short*)p;
    cudaGetSymbolAddress(&p, g_W2);    unsigned short* w2  = (unsigned short*)p;
    cudaGetSymbolAddress(&p, g_U2);    unsigned short* u2  = (unsigned short*)p;
    cudaGetSymbolAddress(&p, g_Wo2);   unsigned short* wo2 = (unsigned short*)p;
    cudaGetSymbolAddress(&p, g_PEr16); unsigned short* pr16 = (unsigned short*)p;
    cudaGetSymbolAddress(&p, g_Qcat);  unsigned short* Qc  = (unsigned short*)p;
    cudaGetSymbolAddress(&p, g_KH);    char* KH = (char*)p;
    cudaGetSymbolAddress(&p, g_VH);    char* VH = (char*)p;
    cudaGetSymbolAddress(&p, g_vals);  unsigned short* Vl = (unsigned short*)p;

    // 0) packs
    pack_all_kernel<<<9728, 256>>>((const float4*)x, (const float4*)PE,
                                   (const float4*)Wqkv, (const float4*)UqUk,
                                   (const float4*)Wo,
                                   (uint2*)x2, (uint2*)pe2,
                                   (uint2*)w2, (uint2*)u2, (uint2*)wo2);
    pack_bias_kernel<<<32768, 256>>>((const float4*)PE_r, (uint2*)pr16,
                                     (int)((size_t)HH * SQ * SQ / 4));

    // 1) merged qkv + PE projections (writes Q scaled fp16, K/V fp16 images)
    cudaFuncSetAttribute(proj_kernel, cudaFuncAttributeMaxDynamicSharedMemorySize, 67584);
    proj_kernel<<<dim3(20, 64), 256, 67584>>>(x2, w2, pe2, u2);

    // 2) fused attention (2 CTAs/SM)
    cudaFuncSetAttribute(flash_attn, cudaFuncAttributeMaxDynamicSharedMemorySize, 86016);
    flash_attn<<<dim3(SQ / 128, BB * HH), 256, 86016>>>(Qc, KH, VH, (const char*)pr16, Vl);

    // 3) out projection
    cudaFuncSetAttribute(outproj_kernel, cudaFuncAttributeMaxDynamicSharedMemorySize, 67584);
    outproj_kernel<<<dim3(4, 64), 256, 67584>>>(Vl, wo2, out);
}